// round 13
// baseline (speedup 1.0000x reference)
#include <cuda_runtime.h>
#include <cuda_bf16.h>
#include <cstdint>
#include <math.h>

// ---------------- problem constants ----------------
#define B_      4
#define L_      2048
#define EMB     256
#define NHD     8
#define CHK     64
#define NCHUNK  (L_/CHK)          // 32
#define D_INNER 512
#define D_STATE 256
#define CONV_DIM 1024
#define D_PROJ  1544
#define NTOK    (B_*L_)           // 8192

#if defined(__CUDA_ARCH_FEAT_SM103_ALL) || defined(__CUDA_ARCH_FEAT_SM100_ALL) || \
    defined(__CUDA_ARCH_SPECIFIC__) || defined(__CUDA_ARCH_FAMILY_SPECIFIC__)
#define HAS_TCGEN05 1
#else
#define HAS_TCGEN05 0
#endif

// ---------------- scratch (device globals, no allocation) ----------------
__device__ float g_h  [NTOK*EMB];
__device__ float g_zx [NTOK*D_PROJ];
__device__ float g_xbc[NTOK*CONV_DIM];
__device__ float g_dt [NTOK*NHD];
__device__ float g_acs[B_*NHD*NCHUNK*CHK];
__device__ float g_states[(size_t)B_*NCHUNK*NHD*64*256];   // chunk states fp32
__device__ float g_y  [NTOK*D_INNER];
__device__ __nv_bfloat16 g_ah[NTOK*512];
__device__ __nv_bfloat16 g_al[NTOK*512];
__device__ __nv_bfloat16 g_wth[1544*256];
__device__ __nv_bfloat16 g_wtl[1544*256];
__device__ float g_xbt[(size_t)B_*768*L_];
__device__ __nv_bfloat16 g_sph[(size_t)B_*NCHUNK*512*256];
__device__ __nv_bfloat16 g_spl[(size_t)B_*NCHUNK*512*256];

__device__ __forceinline__ void bf16_split(float x, __nv_bfloat16& hi, __nv_bfloat16& lo){
    hi = __float2bfloat16_rn(x);
    lo = __float2bfloat16_rn(x - __bfloat162float(hi));
}

// GEMM v2 (in_proj) smem
#define GM_STAGE0  1024
#define GM_STAGE   98304
#define GM_AH      0
#define GM_AL      16384
#define GM_BH      32768
#define GM_BL      65536
#define SM2_BYTES  197632
// GEMM v1 (out_proj/head) smem: double-buffered, K-chunk 64
#define S1_STAGE0  1024
#define S1_STAGE   65536
#define S1_AH      0
#define S1_AL      16384
#define S1_BH      32768
#define S1_BL      49152
#define SM1_BYTES  132096
// states kernel smem
#define ST_BH      1024
#define ST_BL      33792
#define ST_AH      66560
#define ST_AL      82944
#define ST_BYTES   100352
// yoff kernel smem
#define YO_CH      1024
#define YO_CL      33792
#define YO_AH      66560
#define YO_AL      132096
#define YO_BYTES   197632
// conv smem: max(input (64+3)x256, out-transpose 256x65) fp32
#define CV_BYTES   (67*256*4)

#if HAS_TCGEN05
// ================= tcgen05 helpers =================
__device__ __forceinline__ uint32_t smem_u32(const void* p){
    uint32_t a;
    asm("{ .reg .u64 t; cvta.to.shared.u64 t, %1; cvt.u32.u64 %0, t; }" : "=r"(a) : "l"(p));
    return a;
}
__device__ __forceinline__ uint32_t elect_one(){
    uint32_t p;
    asm volatile("{ .reg .pred p; elect.sync _|p, 0xFFFFFFFF; selp.b32 %0, 1, 0, p; }" : "=r"(p));
    return p;
}
#define TC_ALLOC(sm, n)  asm volatile("tcgen05.alloc.cta_group::1.sync.aligned.shared::cta.b32 [%0], %1;" :: "r"(sm), "r"(n) : "memory")
#define TC_DEALLOC(t, n) asm volatile("tcgen05.dealloc.cta_group::1.sync.aligned.b32 %0, %1;" :: "r"(t), "r"(n))
#define TC_RELINQ()      asm volatile("tcgen05.relinquish_alloc_permit.cta_group::1.sync.aligned;")
#define TC_COMMIT(mb)    asm volatile("tcgen05.commit.cta_group::1.mbarrier::arrive::one.shared::cluster.b64 [%0];" :: "r"(mb) : "memory")
#define TC_FENCE_AFTER() asm volatile("tcgen05.fence::after_thread_sync;" ::: "memory")
#define TC_FENCE_BEFORE() asm volatile("tcgen05.fence::before_thread_sync;" ::: "memory")
#define TC_WAIT_LD()     asm volatile("tcgen05.wait::ld.sync.aligned;" ::: "memory")
#define MBAR_INIT(mb, c) asm volatile("mbarrier.init.shared.b64 [%0], %1;" :: "r"(mb), "r"(c) : "memory")
#define MBAR_WAIT(mb, ph) do { \
    uint32_t _m = (mb), _p = (ph), _d; \
    asm volatile("{ .reg .pred p; mbarrier.try_wait.parity.acquire.cta.shared::cta.b64 p, [%1], %2; selp.b32 %0, 1, 0, p; }" \
        : "=r"(_d) : "r"(_m), "r"(_p) : "memory"); \
    if (!_d) { \
        asm volatile("{ .reg .pred P1; WL_%=: mbarrier.try_wait.parity.acquire.cta.shared::cta.b64 P1, [%0], %1, 0x989680; @P1 bra.uni WD_%=; bra.uni WL_%=; WD_%=: }" \
            :: "r"(_m), "r"(_p) : "memory"); \
    } } while(0)
#define TC_LD_X32(r, ta) \
    asm volatile("tcgen05.ld.sync.aligned.32x32b.x32.b32 " \
        "{%0,%1,%2,%3,%4,%5,%6,%7,%8,%9,%10,%11,%12,%13,%14,%15," \
        "%16,%17,%18,%19,%20,%21,%22,%23,%24,%25,%26,%27,%28,%29,%30,%31}, [%32];" \
        : "=r"((r)[0]),"=r"((r)[1]),"=r"((r)[2]),"=r"((r)[3]),"=r"((r)[4]),"=r"((r)[5]),"=r"((r)[6]),"=r"((r)[7]), \
          "=r"((r)[8]),"=r"((r)[9]),"=r"((r)[10]),"=r"((r)[11]),"=r"((r)[12]),"=r"((r)[13]),"=r"((r)[14]),"=r"((r)[15]), \
          "=r"((r)[16]),"=r"((r)[17]),"=r"((r)[18]),"=r"((r)[19]),"=r"((r)[20]),"=r"((r)[21]),"=r"((r)[22]),"=r"((r)[23]), \
          "=r"((r)[24]),"=r"((r)[25]),"=r"((r)[26]),"=r"((r)[27]),"=r"((r)[28]),"=r"((r)[29]),"=r"((r)[30]),"=r"((r)[31]) \
        : "r"(ta))

static __device__ __forceinline__ uint64_t make_desc_sw128(uint32_t addr){
    const uint64_t base =
        (uint64_t(2)  << 61) | (uint64_t(1) << 46) | (uint64_t(64) << 32) | (uint64_t(1) << 16);
    return base | ((uint64_t)(addr >> 4) & 0x3FFF);
}
__device__ __forceinline__ void mma_bf16_ss(uint32_t d, uint64_t ad, uint64_t bd,
                                            uint32_t idesc, bool acc){
    uint32_t en = acc ? 1u : 0u;
    asm volatile(
        "{\n\t"
        ".reg .pred p;\n\t"
        "setp.ne.u32 p, %5, 0;\n\t"
        "tcgen05.mma.cta_group::1.kind::f16 [%0], %1, %2, %3, {%4, %4, %4, %4}, p;\n\t"
        "}"
        :: "r"(d), "l"(ad), "l"(bd), "r"(idesc), "r"(0u), "r"(en)
        : "memory");
}
#define SWZ(o) ((o) ^ (((o) >> 3) & 0x70))
#define IDESC_N128 ((1u<<4) | (1u<<7) | (1u<<10) | ((128u/8u)<<17) | ((128u/16u)<<24))
#define IDESC_N64  ((1u<<4) | (1u<<7) | (1u<<10) | (( 64u/8u)<<17) | ((128u/16u)<<24))
#endif // HAS_TCGEN05

// ---------------- GEMM v2 (in_proj): 128x256 tile, K chunks of 64, double-buffered ----------------
__global__ void __launch_bounds__(256)
k_mma_gemm2(const __nv_bfloat16* __restrict__ Ah, const __nv_bfloat16* __restrict__ Al,
            const __nv_bfloat16* __restrict__ Bh, const __nv_bfloat16* __restrict__ Bl,
            float* __restrict__ C, int M, int N, int K,
            const float* __restrict__ resid){
    extern __shared__ char smem[];
    int tid = threadIdx.x;
    int bm = blockIdx.y * 128, bn = blockIdx.x * 256;

#if HAS_TCGEN05
    uint32_t sbase = smem_u32(smem);
    int wid = tid >> 5, lid = tid & 31;
    if (wid == 0) TC_ALLOC(sbase, 256);
    if (tid == 0){ MBAR_INIT(sbase + 8, 1); MBAR_INIT(sbase + 16, 1); }
    __syncthreads();
    uint32_t tmem;
    asm volatile("ld.shared.b32 %0, [%1];" : "=r"(tmem) : "r"(sbase));

    int nc = K >> 6;
    int ph0 = 0, ph1 = 0;
    for (int c = 0; c < nc; c++){
        int buf = c & 1;
        uint32_t sb = sbase + GM_STAGE0 + buf*GM_STAGE;
        char* smb = smem + GM_STAGE0 + buf*GM_STAGE;
        int kc = c << 6;
        if (c >= 2){
            if (buf == 0){ MBAR_WAIT(sbase + 8,  ph0); ph0 ^= 1; }
            else         { MBAR_WAIT(sbase + 16, ph1); ph1 ^= 1; }
        }
        #pragma unroll
        for (int it = 0; it < 4; it++){
            int v = tid + it*256;
            int m = v >> 3, u = v & 7;
            uint32_t so = SWZ((uint32_t)(m*128 + u*16));
            size_t gi = (size_t)(bm+m)*K + kc + u*8;
            *(uint4*)(smb + GM_AH + so) = *(const uint4*)&Ah[gi];
            *(uint4*)(smb + GM_AL + so) = *(const uint4*)&Al[gi];
        }
        #pragma unroll
        for (int it = 0; it < 8; it++){
            int v = tid + it*256;
            int n = v >> 3, u = v & 7;
            uint32_t so = SWZ((uint32_t)(n*128 + u*16));
            uint4 vh = make_uint4(0,0,0,0), vl = make_uint4(0,0,0,0);
            if (bn + n < N){
                size_t gi = (size_t)(bn+n)*K + kc + u*8;
                vh = *(const uint4*)&Bh[gi];
                vl = *(const uint4*)&Bl[gi];
            }
            *(uint4*)(smb + GM_BH + so) = vh;
            *(uint4*)(smb + GM_BL + so) = vl;
        }
        __syncthreads();
        asm volatile("fence.proxy.async.shared::cta;" ::: "memory");

        if (wid == 0 && elect_one()){
            uint64_t ah = make_desc_sw128(sb + GM_AH);
            uint64_t al = make_desc_sw128(sb + GM_AL);
            #pragma unroll
            for (int half = 0; half < 2; half++){
                uint64_t bh = make_desc_sw128(sb + GM_BH + half*16384);
                uint64_t bl = make_desc_sw128(sb + GM_BL + half*16384);
                uint32_t dt_ = tmem + half*128;
                #pragma unroll
                for (int s = 0; s < 4; s++){
                    bool acc = !(c == 0 && s == 0);
                    mma_bf16_ss(dt_, ah + s*2, bh + s*2, IDESC_N128, acc);
                    mma_bf16_ss(dt_, ah + s*2, bl + s*2, IDESC_N128, true);
                    mma_bf16_ss(dt_, al + s*2, bh + s*2, IDESC_N128, true);
                }
            }
            TC_COMMIT(sbase + 8 + buf*8);
        }
        __syncthreads();
    }
    {
        int lb = (nc-1) & 1;
        if (lb == 0) MBAR_WAIT(sbase + 8,  ph0);
        else         MBAR_WAIT(sbase + 16, ph1);
    }

    TC_FENCE_AFTER();
    float* eb = (float*)(smem + GM_STAGE0);
    for (int g = 0; g < 8; g++){
        if (wid < 4){
            uint32_t r[32];
            TC_LD_X32(r, tmem + g*32);
            TC_WAIT_LD();
            int m = wid*32 + lid;
            #pragma unroll
            for (int j = 0; j < 32; j++)
                eb[m*33 + j] = __uint_as_float(r[j]);
        }
        __syncthreads();
        #pragma unroll
        for (int it = 0; it < 16; it++){
            int v = tid + it*256;
            int m = v >> 5, j = v & 31;
            int n = bn + g*32 + j;
            if (n < N){
                size_t idx = (size_t)(bm+m)*N + n;
                float val = eb[m*33 + j];
                if (resid) val += resid[idx];
                C[idx] = val;
            }
        }
        __syncthreads();
    }
    if (wid == 0){
        TC_RELINQ();
        TC_DEALLOC(tmem, 256);
    }
#else
    float (*As)[132] = (float(*)[132])(smem);
    float (*Ws)[132] = (float(*)[132])(smem + 16*132*4);
    int tx = tid & 15, ty = tid >> 4;
    for (int half = 0; half < 2; half++){
        int bn2 = bn + half*128;
        float acc[8][8] = {};
        for (int k0 = 0; k0 < K; k0 += 16){
            #pragma unroll
            for (int r = 0; r < 8; r++){
                int i = tid + r*256;
                int m = i >> 4, k = i & 15;
                size_t gi = (size_t)(bm+m)*K + k0 + k;
                As[k][m] = __bfloat162float(Ah[gi]) + __bfloat162float(Al[gi]);
            }
            #pragma unroll
            for (int r = 0; r < 8; r++){
                int i = tid + r*256;
                int k = i >> 7, n = i & 127;
                float w = 0.f;
                if (bn2+n < N){
                    size_t gi = (size_t)(bn2+n)*K + k0 + k;
                    w = __bfloat162float(Bh[gi]) + __bfloat162float(Bl[gi]);
                }
                Ws[k][n] = w;
            }
            __syncthreads();
            #pragma unroll
            for (int kk = 0; kk < 16; kk++){
                float a[8], b[8];
                #pragma unroll
                for (int i = 0; i < 8; i++) a[i] = As[kk][ty*8+i];
                #pragma unroll
                for (int j = 0; j < 8; j++) b[j] = Ws[kk][tx*8+j];
                #pragma unroll
                for (int i = 0; i < 8; i++)
                    #pragma unroll
                    for (int j = 0; j < 8; j++)
                        acc[i][j] = fmaf(a[i], b[j], acc[i][j]);
            }
            __syncthreads();
        }
        #pragma unroll
        for (int i = 0; i < 8; i++){
            int m = bm + ty*8 + i;
            #pragma unroll
            for (int j = 0; j < 8; j++){
                int n = bn2 + tx*8 + j;
                if (n < N){
                    size_t idx = (size_t)m*N + n;
                    float v = acc[i][j];
                    if (resid) v += resid[idx];
                    C[idx] = v;
                }
            }
        }
        __syncthreads();
    }
#endif
}

// ---------------- GEMM v1 (out_proj/head): 128x128 tile, K chunks of 64, double-buffered ----------------
__global__ void __launch_bounds__(256)
k_mma_gemm(const __nv_bfloat16* __restrict__ Ah, const __nv_bfloat16* __restrict__ Al,
           const __nv_bfloat16* __restrict__ Bh, const __nv_bfloat16* __restrict__ Bl,
           float* __restrict__ C, int M, int N, int K,
           const float* __restrict__ resid){
    extern __shared__ char smem[];
    int tid = threadIdx.x;
    int bm = blockIdx.y * 128, bn = blockIdx.x * 128;

#if HAS_TCGEN05
    uint32_t sbase = smem_u32(smem);
    int wid = tid >> 5, lid = tid & 31;
    if (wid == 0) TC_ALLOC(sbase, 128);
    if (tid == 0){ MBAR_INIT(sbase + 8, 1); MBAR_INIT(sbase + 16, 1); }
    __syncthreads();
    uint32_t tmem;
    asm volatile("ld.shared.b32 %0, [%1];" : "=r"(tmem) : "r"(sbase));

    int nc = K >> 6;
    int ph0 = 0, ph1 = 0;
    for (int c = 0; c < nc; c++){
        int buf = c & 1;
        uint32_t sb = sbase + S1_STAGE0 + buf*S1_STAGE;
        char* smb = smem + S1_STAGE0 + buf*S1_STAGE;
        int kc = c << 6;
        if (c >= 2){
            if (buf == 0){ MBAR_WAIT(sbase + 8,  ph0); ph0 ^= 1; }
            else         { MBAR_WAIT(sbase + 16, ph1); ph1 ^= 1; }
        }
        #pragma unroll
        for (int it = 0; it < 4; it++){
            int v = tid + it*256;
            int m = v >> 3, u = v & 7;
            uint32_t so = SWZ((uint32_t)(m*128 + u*16));
            size_t gi = (size_t)(bm+m)*K + kc + u*8;
            *(uint4*)(smb + S1_AH + so) = *(const uint4*)&Ah[gi];
            *(uint4*)(smb + S1_AL + so) = *(const uint4*)&Al[gi];
        }
        #pragma unroll
        for (int it = 0; it < 4; it++){
            int v = tid + it*256;
            int n = v >> 3, u = v & 7;
            uint32_t so = SWZ((uint32_t)(n*128 + u*16));
            uint4 vh = make_uint4(0,0,0,0), vl = make_uint4(0,0,0,0);
            if (bn + n < N){
                size_t gi = (size_t)(bn+n)*K + kc + u*8;
                vh = *(const uint4*)&Bh[gi];
                vl = *(const uint4*)&Bl[gi];
            }
            *(uint4*)(smb + S1_BH + so) = vh;
            *(uint4*)(smb + S1_BL + so) = vl;
        }
        __syncthreads();
        asm volatile("fence.proxy.async.shared::cta;" ::: "memory");

        if (wid == 0 && elect_one()){
            uint64_t ah = make_desc_sw128(sb + S1_AH);
            uint64_t al = make_desc_sw128(sb + S1_AL);
            uint64_t bh = make_desc_sw128(sb + S1_BH);
            uint64_t bl = make_desc_sw128(sb + S1_BL);
            #pragma unroll
            for (int s = 0; s < 4; s++){
                bool acc = !(c == 0 && s == 0);
                mma_bf16_ss(tmem, ah + s*2, bh + s*2, IDESC_N128, acc);
                mma_bf16_ss(tmem, ah + s*2, bl + s*2, IDESC_N128, true);
                mma_bf16_ss(tmem, al + s*2, bh + s*2, IDESC_N128, true);
            }
            TC_COMMIT(sbase + 8 + buf*8);
        }
        __syncthreads();
    }
    {
        int lb = (nc-1) & 1;
        if (lb == 0) MBAR_WAIT(sbase + 8,  ph0);
        else         MBAR_WAIT(sbase + 16, ph1);
    }

    TC_FENCE_AFTER();
    float* eb = (float*)(smem + S1_STAGE0);
    for (int g = 0; g < 4; g++){
        if (wid < 4){
            uint32_t r[32];
            TC_LD_X32(r, tmem + g*32);
            TC_WAIT_LD();
            int m = wid*32 + lid;
            #pragma unroll
            for (int j = 0; j < 32; j++)
                eb[m*33 + j] = __uint_as_float(r[j]);
        }
        __syncthreads();
        #pragma unroll
        for (int it = 0; it < 16; it++){
            int v = tid + it*256;
            int m = v >> 5, j = v & 31;
            int n = bn + g*32 + j;
            if (n < N){
                size_t idx = (size_t)(bm+m)*N + n;
                float val = eb[m*33 + j];
                if (resid) val += resid[idx];
                C[idx] = val;
            }
        }
        __syncthreads();
    }
    if (wid == 0){
        TC_RELINQ();
        TC_DEALLOC(tmem, 128);
    }
#else
    float (*As)[132] = (float(*)[132])(smem);
    float (*Ws)[132] = (float(*)[132])(smem + 16*132*4);
    int tx = tid & 15, ty = tid >> 4;
    float acc[8][8] = {};
    for (int k0 = 0; k0 < K; k0 += 16){
        #pragma unroll
        for (int r = 0; r < 8; r++){
            int i = tid + r*256;
            int m = i >> 4, k = i & 15;
            size_t gi = (size_t)(bm+m)*K + k0 + k;
            As[k][m] = __bfloat162float(Ah[gi]) + __bfloat162float(Al[gi]);
        }
        #pragma unroll
        for (int r = 0; r < 8; r++){
            int i = tid + r*256;
            int k = i >> 7, n = i & 127;
            float w = 0.f;
            if (bn+n < N){
                size_t gi = (size_t)(bn+n)*K + k0 + k;
                w = __bfloat162float(Bh[gi]) + __bfloat162float(Bl[gi]);
            }
            Ws[k][n] = w;
        }
        __syncthreads();
        #pragma unroll
        for (int kk = 0; kk < 16; kk++){
            float a[8], b[8];
            #pragma unroll
            for (int i = 0; i < 8; i++) a[i] = As[kk][ty*8+i];
            #pragma unroll
            for (int j = 0; j < 8; j++) b[j] = Ws[kk][tx*8+j];
            #pragma unroll
            for (int i = 0; i < 8; i++)
                #pragma unroll
                for (int j = 0; j < 8; j++)
                    acc[i][j] = fmaf(a[i], b[j], acc[i][j]);
        }
        __syncthreads();
    }
    #pragma unroll
    for (int i = 0; i < 8; i++){
        int m = bm + ty*8 + i;
        #pragma unroll
        for (int j = 0; j < 8; j++){
            int n = bn + tx*8 + j;
            if (n < N){
                size_t idx = (size_t)m*N + n;
                float v = acc[i][j];
                if (resid) v += resid[idx];
                C[idx] = v;
            }
        }
    }
#endif
}

// ---------------- states: S[hp,n] = sum_l xdts[l,hp]*B[l,n]  (tcgen05, fp32 out) ----------------
__global__ void __launch_bounds__(256)
k_states_mma(){
    extern __shared__ char smem[];
    int tid = threadIdx.x;
    int bc = blockIdx.x;
    int c = bc & 31, b = bc >> 5;
    int t0 = b*L_ + c*64;
#if HAS_TCGEN05
    uint32_t sbase = smem_u32(smem);
    int wid = tid >> 5, lid = tid & 31;
    float* sc = (float*)(smem + 128);
    if (wid == 0) TC_ALLOC(sbase, 128);
    if (tid == 0) MBAR_INIT(sbase + 8, 1);
    __syncthreads();
    uint32_t tmem;
    asm volatile("ld.shared.b32 %0, [%1];" : "=r"(tmem) : "r"(sbase));

    #pragma unroll
    for (int it = 0; it < 16; it++){
        int v = tid + it*256;
        int n = v >> 4, u = v & 15;
        const float* src = g_xbt + ((size_t)b*768 + 512 + n)*L_ + c*64 + u*4;
        float4 a = *(const float4*)src;
        __nv_bfloat16 h0,l0,h1,l1,h2,l2,h3,l3;
        bf16_split(a.x,h0,l0); bf16_split(a.y,h1,l1);
        bf16_split(a.z,h2,l2); bf16_split(a.w,h3,l3);
        __nv_bfloat162 hp2 = __halves2bfloat162(h0,h1), hq2 = __halves2bfloat162(h2,h3);
        __nv_bfloat162 lp2 = __halves2bfloat162(l0,l1), lq2 = __halves2bfloat162(l2,l3);
        int nt = n >> 7, r = n & 127;
        uint32_t so = nt*16384 + SWZ((uint32_t)(r*128 + u*8));
        *(uint2*)(smem + ST_BH + so) = make_uint2(*(uint32_t*)&hp2, *(uint32_t*)&hq2);
        *(uint2*)(smem + ST_BL + so) = make_uint2(*(uint32_t*)&lp2, *(uint32_t*)&lq2);
    }

    int phase = 0;
    for (int ht = 0; ht < 4; ht++){
        __syncthreads();
        if (tid < 128){
            int hl = tid >> 6, l = tid & 63;
            int h = ht*2 + hl;
            const float* ap = g_acs + ((size_t)(b*8+h)*32 + c)*64;
            sc[hl*64 + l] = g_dt[(size_t)(t0+l)*NHD + h] * __expf(ap[63] - ap[l]);
        }
        __syncthreads();
        #pragma unroll
        for (int it = 0; it < 8; it++){
            int v = tid + it*256;
            int r = v >> 4, u = v & 15;
            const float* src = g_xbt + ((size_t)b*768 + ht*128 + r)*L_ + c*64 + u*4;
            float4 a = *(const float4*)src;
            const float* s4 = sc + (r >> 6)*64 + u*4;
            a.x *= s4[0]; a.y *= s4[1]; a.z *= s4[2]; a.w *= s4[3];
            __nv_bfloat16 h0,l0,h1,l1,h2,l2,h3,l3;
            bf16_split(a.x,h0,l0); bf16_split(a.y,h1,l1);
            bf16_split(a.z,h2,l2); bf16_split(a.w,h3,l3);
            __nv_bfloat162 hp2 = __halves2bfloat162(h0,h1), hq2 = __halves2bfloat162(h2,h3);
            __nv_bfloat162 lp2 = __halves2bfloat162(l0,l1), lq2 = __halves2bfloat162(l2,l3);
            uint32_t so = SWZ((uint32_t)(r*128 + u*8));
            *(uint2*)(smem + ST_AH + so) = make_uint2(*(uint32_t*)&hp2, *(uint32_t*)&hq2);
            *(uint2*)(smem + ST_AL + so) = make_uint2(*(uint32_t*)&lp2, *(uint32_t*)&lq2);
        }
        __syncthreads();
        asm volatile("fence.proxy.async.shared::cta;" ::: "memory");

        for (int nt = 0; nt < 2; nt++){
            if (wid == 0 && elect_one()){
                uint64_t ah = make_desc_sw128(sbase + ST_AH);
                uint64_t al = make_desc_sw128(sbase + ST_AL);
                uint64_t bh = make_desc_sw128(sbase + ST_BH + nt*16384);
                uint64_t bl = make_desc_sw128(sbase + ST_BL + nt*16384);
                bool first = true;
                #pragma unroll
                for (int s = 0; s < 4; s++){
                    mma_bf16_ss(tmem, ah + s*2, bh + s*2, IDESC_N128, !first);
                    first = false;
                    mma_bf16_ss(tmem, ah + s*2, bl + s*2, IDESC_N128, true);
                    mma_bf16_ss(tmem, al + s*2, bh + s*2, IDESC_N128, true);
                }
                TC_COMMIT(sbase + 8);
            }
            MBAR_WAIT(sbase + 8, phase);
            phase ^= 1;
            TC_FENCE_AFTER();
            if (wid < 4){
                int hp = ht*128 + wid*32 + lid;
                float* out = g_states + ((size_t)bc*512 + hp)*256 + nt*128;
                #pragma unroll
                for (int g = 0; g < 4; g++){
                    uint32_t r[32];
                    TC_LD_X32(r, tmem + g*32);
                    TC_WAIT_LD();
                    #pragma unroll
                    for (int j = 0; j < 32; j += 4){
                        float4 v4 = make_float4(__uint_as_float(r[j]),   __uint_as_float(r[j+1]),
                                                __uint_as_float(r[j+2]), __uint_as_float(r[j+3]));
                        *(float4*)(out + g*32 + j) = v4;
                    }
                }
                TC_FENCE_BEFORE();
            }
            __syncthreads();
        }
    }
    if (wid == 0){
        TC_RELINQ();
        TC_DEALLOC(tmem, 128);
    }
#else
    __shared__ float sc8[8][64];
    for (int v = tid; v < 512; v += 256){
        int h = v >> 6, l = v & 63;
        const float* ap = g_acs + ((size_t)(b*8+h)*32 + c)*64;
        sc8[h][l] = g_dt[(size_t)(t0+l)*NHD + h] * __expf(ap[63] - ap[l]);
    }
    __syncthreads();
    for (int h = 0; h < 8; h++)
        for (int idx = tid; idx < 16384; idx += 256){
            int p = idx >> 8, n = idx & 255;
            float s = 0.f;
            for (int l = 0; l < 64; l++)
                s += g_xbc[(size_t)(t0+l)*CONV_DIM + h*64 + p] * sc8[h][l]
                   * g_xbc[(size_t)(t0+l)*CONV_DIM + 512 + n];
            g_states[((size_t)bc*512 + h*64 + p)*256 + n] = s;
        }
#endif
}

// ---------------- yoff ----------------
__global__ void __launch_bounds__(256)
k_yoff_mma(const float* __restrict__ Dvec){
    extern __shared__ char smem[];
    int tid = threadIdx.x;
    int bc = blockIdx.x;
    int c = bc & 31, b = bc >> 5;
    int t0 = b*L_ + c*64;
#if HAS_TCGEN05
    uint32_t sbase = smem_u32(smem);
    int wid = tid >> 5, lid = tid & 31;
    float* ex = (float*)(smem + 128);
    if (wid == 0) TC_ALLOC(sbase, 64);
    if (tid == 0) MBAR_INIT(sbase + 8, 1);
    __syncthreads();
    uint32_t tmem;
    asm volatile("ld.shared.b32 %0, [%1];" : "=r"(tmem) : "r"(sbase));

    #pragma unroll
    for (int it = 0; it < 8; it++){
        int v = tid + it*256;
        int l = v >> 5, q = v & 31;
        const float* src = &g_xbc[(size_t)(t0+l)*CONV_DIM + 768 + q*8];
        float4 a = *(const float4*)src;
        float4 bq = *(const float4*)(src + 4);
        __nv_bfloat16 h0,l0,h1,l1,h2,l2,h3,l3,h4,l4,h5,l5,h6,l6,h7,l7;
        bf16_split(a.x,h0,l0);  bf16_split(a.y,h1,l1);
        bf16_split(a.z,h2,l2);  bf16_split(a.w,h3,l3);
        bf16_split(bq.x,h4,l4); bf16_split(bq.y,h5,l5);
        bf16_split(bq.z,h6,l6); bf16_split(bq.w,h7,l7);
        __nv_bfloat162 H0 = __halves2bfloat162(h0,h1), H1 = __halves2bfloat162(h2,h3);
        __nv_bfloat162 H2 = __halves2bfloat162(h4,h5), H3 = __halves2bfloat162(h6,h7);
        __nv_bfloat162 L0 = __halves2bfloat162(l0,l1), L1 = __halves2bfloat162(l2,l3);
        __nv_bfloat162 L2 = __halves2bfloat162(l4,l5), L3 = __halves2bfloat162(l6,l7);
        int kt = q >> 3;
        uint32_t so = kt*8192 + SWZ((uint32_t)(l*128 + (q & 7)*16));
        *(uint4*)(smem + YO_CH + so) = make_uint4(*(uint32_t*)&H0, *(uint32_t*)&H1,
                                                  *(uint32_t*)&H2, *(uint32_t*)&H3);
        *(uint4*)(smem + YO_CL + so) = make_uint4(*(uint32_t*)&L0, *(uint32_t*)&L1,
                                                  *(uint32_t*)&L2, *(uint32_t*)&L3);
    }

    int phase = 0;
    for (int ht = 0; ht < 4; ht++){
        __syncthreads();
        if (tid < 128){
            int hl = tid >> 6, l = tid & 63;
            int h = ht*2 + hl;
            ex[hl*64 + l] = __expf(g_acs[((size_t)(b*8+h)*32 + c)*64 + l]);
        }
        #pragma unroll
        for (int it = 0; it < 16; it++){
            int v = tid + it*256;
            int r = v >> 5, u = v & 31;
            size_t gi = ((size_t)bc*512 + ht*128 + r)*256 + u*8;
            int kt = u >> 3;
            uint32_t so = kt*16384 + SWZ((uint32_t)(r*128 + (u & 7)*16));
            *(uint4*)(smem + YO_AH + so) = *(const uint4*)&g_sph[gi];
            *(uint4*)(smem + YO_AL + so) = *(const uint4*)&g_spl[gi];
        }
        __syncthreads();
        asm volatile("fence.proxy.async.shared::cta;" ::: "memory");

        if (wid == 0 && elect_one()){
            bool first = true;
            #pragma unroll
            for (int kt = 0; kt < 4; kt++){
                uint64_t ah = make_desc_sw128(sbase + YO_AH + kt*16384);
                uint64_t al = make_desc_sw128(sbase + YO_AL + kt*16384);
                uint64_t bh = make_desc_sw128(sbase + YO_CH + kt*8192);
                uint64_t bl = make_desc_sw128(sbase + YO_CL + kt*8192);
                #pragma unroll
                for (int s = 0; s < 4; s++){
                    mma_bf16_ss(tmem, ah + s*2, bh + s*2, IDESC_N64, !first);
                    first = false;
                    mma_bf16_ss(tmem, ah + s*2, bl + s*2, IDESC_N64, true);
                    mma_bf16_ss(tmem, al + s*2, bh + s*2, IDESC_N64, true);
                }
            }
            TC_COMMIT(sbase + 8);
        }
        MBAR_WAIT(sbase + 8, phase);
        phase ^= 1;
        TC_FENCE_AFTER();
        float* eb = (float*)(smem + YO_AH);
        if (wid < 4){
            int hp = wid*32 + lid;
            #pragma unroll
            for (int g = 0; g < 2; g++){
                uint32_t r[32];
                TC_LD_X32(r, tmem + g*32);
                TC_WAIT_LD();
                #pragma unroll
                for (int j = 0; j < 32; j++)
                    eb[hp*65 + g*32 + j] = __uint_as_float(r[j]);
            }
            TC_FENCE_BEFORE();
        }
        __syncthreads();
        #pragma unroll
        for (int it = 0; it < 32; it++){
            int v = tid + it*256;
            int l = v >> 7, hp = v & 127;
            int h = ht*2 + (hp >> 6);
            float val = ex[(hp >> 6)*64 + l] * eb[hp*65 + l];
            float xh = g_xbc[(size_t)(t0+l)*CONV_DIM + ht*128 + hp];
            size_t oi = (size_t)(t0+l)*D_INNER + ht*128 + hp;
            g_y[oi] += val + xh*Dvec[h];
        }
    }
    __syncthreads();
    if (wid == 0){
        TC_RELINQ();
        TC_DEALLOC(tmem, 64);
    }
#else
    for (int idx = tid; idx < 64*512; idx += 256){
        int l = idx >> 9, hp = idx & 511;
        int h = hp >> 6;
        const __nv_bfloat16* sh = g_sph + ((size_t)bc*512 + hp)*256;
        const __nv_bfloat16* sl = g_spl + ((size_t)bc*512 + hp)*256;
        float acc = 0.f;
        for (int n = 0; n < 256; n++)
            acc += g_xbc[(size_t)(t0+l)*CONV_DIM + 768 + n]
                 * (__bfloat162float(sh[n]) + __bfloat162float(sl[n]));
        float e = __expf(g_acs[((size_t)(b*8+h)*32 + c)*64 + l]);
        float xh = g_xbc[(size_t)(t0+l)*CONV_DIM + hp];
        g_y[(size_t)(t0+l)*D_INNER + hp] += e*acc + xh*Dvec[h];
    }
#endif
}

// ---------------- W split + transpose ----------------
__global__ void k_wsplit_t(const float* __restrict__ W,
                           __nv_bfloat16* __restrict__ Wh, __nv_bfloat16* __restrict__ Wl,
                           int K, int N){
    __shared__ float tile[32][33];
    int n0 = blockIdx.x*32, k0 = blockIdx.y*32;
    int tx = threadIdx.x, ty = threadIdx.y;
    #pragma unroll
    for (int r = ty; r < 32; r += 8){
        int k = k0 + r, n = n0 + tx;
        tile[r][tx] = (k < K && n < N) ? W[(size_t)k*N + n] : 0.f;
    }
    __syncthreads();
    #pragma unroll
    for (int r = ty; r < 32; r += 8){
        int n = n0 + r, k = k0 + tx;
        if (n < N && k < K){
            __nv_bfloat16 hi, lo;
            bf16_split(tile[tx][r], hi, lo);
            Wh[(size_t)n*K + k] = hi;
            Wl[(size_t)n*K + k] = lo;
        }
    }
}

// ---------------- embed ----------------
__global__ void k_embed(const float* __restrict__ x, const float* __restrict__ emb){
    int t = blockIdx.x;
    int e = threadIdx.x;
    int v = (int)(255.0f * x[t]);
    v = min(max(v, 0), 255);
    g_h[(size_t)t*EMB + e] = emb[(size_t)v*EMB + e];
}

// ---------------- rmsnorm + bf16 split ----------------
template<int DIM>
__global__ void k_rmsnorm_split(const float* __restrict__ in, const float* __restrict__ w,
                                __nv_bfloat16* __restrict__ oh, __nv_bfloat16* __restrict__ ol){
    int t = blockIdx.x;
    const float* row = in + (size_t)t*DIM;
    __shared__ float red[8];
    float v[DIM/256];
    float ss = 0.f;
    #pragma unroll
    for (int i = 0; i < DIM/256; i++){
        v[i] = row[threadIdx.x + i*256];
        ss += v[i]*v[i];
    }
    #pragma unroll
    for (int o = 16; o; o >>= 1) ss += __shfl_xor_sync(0xffffffffu, ss, o);
    if ((threadIdx.x & 31) == 0) red[threadIdx.x >> 5] = ss;
    __syncthreads();
    if (threadIdx.x < 32){
        float s2 = (threadIdx.x < 8) ? red[threadIdx.x] : 0.f;
        #pragma unroll
        for (int o = 4; o; o >>= 1) s2 += __shfl_xor_sync(0xffffffffu, s2, o);
        if (threadIdx.x == 0) red[0] = s2;
    }
    __syncthreads();
    float scale = rsqrtf(red[0]/(float)DIM + 1e-5f);
    #pragma unroll
    for (int i = 0; i < DIM/256; i++){
        int d = threadIdx.x + i*256;
        float val = v[i]*scale*w[d];
        __nv_bfloat16 hi, lo;
        bf16_split(val, hi, lo);
        oh[(size_t)t*DIM + d] = hi;
        ol[(size_t)t*DIM + d] = lo;
    }
}

// ---------------- smem-tiled causal depthwise conv + silu + fused transpose ----------------
// block: 64 tokens x 256 channels. Writes g_xbc; blocks with ch0<768 also write
// the transposed layout g_xbt directly (eliminates the separate transpose kernel).
__global__ void __launch_bounds__(256)
k_conv2(const float* __restrict__ cw, const float* __restrict__ cb){
    extern __shared__ float s[];                 // input [67][256]; reused as out [256][65]
    int t0  = blockIdx.x * 64;
    int ch0 = blockIdx.y * 256;
    int tid = threadIdx.x;
    int l0  = t0 & (L_-1);
    int b   = t0 >> 11;                          // L_ = 2048
    #pragma unroll
    for (int r = 0; r < 67; r++){
        float val = 0.f;
        if (l0 - 3 + r >= 0)
            val = g_zx[(size_t)(t0 - 3 + r)*D_PROJ + 512 + ch0 + tid];
        s[r*256 + tid] = val;
    }
    __syncthreads();
    int ch = ch0 + tid;
    float w0 = cw[ch*4+0], w1 = cw[ch*4+1], w2 = cw[ch*4+2], w3 = cw[ch*4+3];
    float bias = cb[ch];
    float out[64];
    #pragma unroll 4
    for (int r = 0; r < 64; r++){
        float acc = bias;
        acc = fmaf(w0, s[(r+0)*256 + tid], acc);
        acc = fmaf(w1, s[(r+1)*256 + tid], acc);
        acc = fmaf(w2, s[(r+2)*256 + tid], acc);
        acc = fmaf(w3, s[(r+3)*256 + tid], acc);
        acc = acc / (1.f + __expf(-acc));
        out[r] = acc;
        g_xbc[(size_t)(t0+r)*CONV_DIM + ch] = acc;
    }
    if (ch0 < 768){
        __syncthreads();                         // all threads done reading input tile
        #pragma unroll 4
        for (int r = 0; r < 64; r++)
            s[tid*65 + r] = out[r];              // [ch_local][l], stride 65 (conflict-free)
        __syncthreads();
        #pragma unroll
        for (int it = 0; it < 64; it++){
            int v = tid + it*256;
            int cl = v >> 6, l = v & 63;
            g_xbt[((size_t)b*768 + ch0 + cl)*L_ + l0 + l] = s[cl*65 + l];
        }
    }
}

// ---------------- fused dt(softplus) + per-chunk cumsum ----------------
__global__ void k_cumsum(const float* __restrict__ A_log, const float* __restrict__ dt_bias){
    int bhc = blockIdx.x;
    int c = bhc & 31;
    int h = (bhc >> 5) & 7;
    int b = bhc >> 8;
    int l = threadIdx.x;
    int t = b*L_ + c*64 + l;
    float v = g_zx[(size_t)t*D_PROJ + 1536 + h] + dt_bias[h];
    float dt = (v > 20.f) ? v : log1pf(__expf(v));
    g_dt[t*NHD + h] = dt;
    float a = -__expf(A_log[h]) * dt;
    __shared__ float s[64];
    s[l] = a; __syncthreads();
    #pragma unroll
    for (int off = 1; off < 64; off <<= 1){
        float vv = s[l] + ((l >= off) ? s[l-off] : 0.f);
        __syncthreads();
        s[l] = vv;
        __syncthreads();
    }
    g_acs[bhc*64 + l] = s[l];
}

// ---------------- Y_diag per (b,c) (fp32 FMA) ----------------
__global__ void k_ydiag(){
    __shared__ float bufA[64][65];
    __shared__ float bufB[64][65];
    __shared__ float acsS[64];
    int bc = blockIdx.x;
    int c = bc & 31, b = bc >> 5;
    int t0 = b*L_ + c*64;
    int tid = threadIdx.x, tx = tid & 15, ty = tid >> 4;
    float G[4][4] = {};
    for (int nt = 0; nt < 4; nt++){
        for (int i = tid; i < 4096; i += 256){
            int r = i >> 6, nn = i & 63;
            bufA[r][nn] = g_xbc[(size_t)(t0+r)*CONV_DIM + 768 + nt*64 + nn];
            bufB[r][nn] = g_xbc[(size_t)(t0+r)*CONV_DIM + 512 + nt*64 + nn];
        }
        __syncthreads();
        #pragma unroll 8
        for (int nn = 0; nn < 64; nn++){
            float cv[4], bv[4];
            #pragma unroll
            for (int i = 0; i < 4; i++) cv[i] = bufA[ty*4+i][nn];
            #pragma unroll
            for (int j = 0; j < 4; j++) bv[j] = bufB[tx*4+j][nn];
            #pragma unroll
            for (int i = 0; i < 4; i++)
                #pragma unroll
                for (int j = 0; j < 4; j++)
                    G[i][j] = fmaf(cv[i], bv[j], G[i][j]);
        }
        __syncthreads();
    }

    for (int hh = 0; hh < NHD; hh++){
        __syncthreads();
        if (tid < 64) acsS[tid] = g_acs[((b*8+hh)*32 + c)*64 + tid];
        for (int i = tid; i < 4096; i += 256){
            int s = i >> 6, p = i & 63;
            int t = t0 + s;
            bufB[s][p] = g_xbc[(size_t)t*CONV_DIM + hh*64 + p] * g_dt[t*NHD + hh];
        }
        __syncthreads();
        #pragma unroll
        for (int i = 0; i < 4; i++){
            int l = ty*4 + i;
            #pragma unroll
            for (int j = 0; j < 4; j++){
                int s = tx*4 + j;
                bufA[l][s] = (s <= l) ? G[i][j]*__expf(acsS[l]-acsS[s]) : 0.f;
            }
        }
        __syncthreads();
        float y[4][4] = {};
        #pragma unroll 4
        for (int s = 0; s < 64; s++){
            float xv[4], wv[4];
            #pragma unroll
            for (int j = 0; j < 4; j++) xv[j] = bufB[s][tx*4+j];
            #pragma unroll
            for (int i = 0; i < 4; i++) wv[i] = bufA[ty*4+i][s];
            #pragma unroll
            for (int i = 0; i < 4; i++)
                #pragma unroll
                for (int j = 0; j < 4; j++)
                    y[i][j] = fmaf(wv[i], xv[j], y[i][j]);
        }
        #pragma unroll
        for (int i = 0; i < 4; i++)
            #pragma unroll
            for (int j = 0; j < 4; j++)
                g_y[(size_t)(t0 + ty*4 + i)*D_INNER + hh*64 + tx*4 + j] = y[i][j];
    }
}

// ---------------- inter-chunk scan: fp32 states -> bf16 hi/lo prev-states ----------------
__global__ void k_scan(){
    int bh = blockIdx.x;
    int h = bh & 7, b = bh >> 3;
    int base = blockIdx.y*2048 + threadIdx.x;
    float S[8] = {};
    for (int c = 0; c < 32; c++){
        float dec = __expf(g_acs[((b*8+h)*32 + c)*64 + 63]);
        size_t off = ((size_t)(b*32 + c)*8 + h)*16384 + base;
        const float* ptr = g_states + off;
        __nv_bfloat16* ph = g_sph + off;
        __nv_bfloat16* pl = g_spl + off;
        #pragma unroll
        for (int e = 0; e < 8; e++){
            float tmp = ptr[e*256];
            __nv_bfloat16 hi, lo;
            bf16_split(S[e], hi, lo);
            ph[e*256] = hi;
            pl[e*256] = lo;
            S[e] = fmaf(S[e], dec, tmp);
        }
    }
}

// ---------------- gated rmsnorm + bf16 split ----------------
__global__ void k_gatenorm_split(const float* __restrict__ gw,
                                 __nv_bfloat16* __restrict__ oh, __nv_bfloat16* __restrict__ ol){
    int t = blockIdx.x;
    __shared__ float red[8];
    float v[2];
    float ss = 0.f;
    #pragma unroll
    for (int i = 0; i < 2; i++){
        int d = threadIdx.x + i*256;
        float z = g_zx[(size_t)t*D_PROJ + d];
        float val = g_y[(size_t)t*D_INNER + d] * (z / (1.f + __expf(-z)));
        v[i] = val;
        ss += val*val;
    }
    #pragma unroll
    for (int o = 16; o; o >>= 1) ss += __shfl_xor_sync(0xffffffffu, ss, o);
    if ((threadIdx.x & 31) == 0) red[threadIdx.x >> 5] = ss;
    __syncthreads();
    if (threadIdx.x < 32){
        float s2 = (threadIdx.x < 8) ? red[threadIdx.x] : 0.f;
        #pragma unroll
        for (int o = 4; o; o >>= 1) s2 += __shfl_xor_sync(0xffffffffu, s2, o);
        if (threadIdx.x == 0) red[0] = s2;
    }
    __syncthreads();
    float scale = rsqrtf(red[0]/512.f + 1e-5f);
    #pragma unroll
    for (int i = 0; i < 2; i++){
        int d = threadIdx.x + i*256;
        float val = v[i]*scale*gw[d];
        __nv_bfloat16 hi, lo;
        bf16_split(val, hi, lo);
        oh[(size_t)t*D_INNER + d] = hi;
        ol[(size_t)t*D_INNER + d] = lo;
    }
}

// ---------------- launch ----------------
extern "C" void kernel_launch(void* const* d_in, const int* in_sizes, int n_in,
                              void* d_out, int out_size){
    const float* x       = (const float*)d_in[0];
    const float* emb     = (const float*)d_in[1];
    const float* in_proj = (const float*)d_in[2];
    const float* conv_w  = (const float*)d_in[3];
    const float* conv_b  = (const float*)d_in[4];
    const float* dt_bias = (const float*)d_in[5];
    const float* A_log   = (const float*)d_in[6];
    const float* Dv      = (const float*)d_in[7];
    const float* gnorm   = (const float*)d_in[8];
    const float* outp_w  = (const float*)d_in[9];
    const float* norm_w  = (const float*)d_in[10];
    const float* normf   = (const float*)d_in[11];
    const float* head_w  = (const float*)d_in[12];

    void *p_h, *p_ah, *p_al, *p_wh, *p_wl, *p_zx;
    cudaGetSymbolAddress(&p_h,  g_h);
    cudaGetSymbolAddress(&p_ah, g_ah);
    cudaGetSymbolAddress(&p_al, g_al);
    cudaGetSymbolAddress(&p_wh, g_wth);
    cudaGetSymbolAddress(&p_wl, g_wtl);
    cudaGetSymbolAddress(&p_zx, g_zx);
    float* gh  = (float*)p_h;
    float* gzx = (float*)p_zx;
    __nv_bfloat16* ah = (__nv_bfloat16*)p_ah;
    __nv_bfloat16* al = (__nv_bfloat16*)p_al;
    __nv_bfloat16* wh = (__nv_bfloat16*)p_wh;
    __nv_bfloat16* wl = (__nv_bfloat16*)p_wl;

    cudaFuncSetAttribute(k_mma_gemm2,  cudaFuncAttributeMaxDynamicSharedMemorySize, SM2_BYTES);
    cudaFuncSetAttribute(k_mma_gemm,   cudaFuncAttributeMaxDynamicSharedMemorySize, SM1_BYTES);
    cudaFuncSetAttribute(k_states_mma, cudaFuncAttributeMaxDynamicSharedMemorySize, ST_BYTES);
    cudaFuncSetAttribute(k_yoff_mma,   cudaFuncAttributeMaxDynamicSharedMemorySize, YO_BYTES);
    cudaFuncSetAttribute(k_conv2,      cudaFuncAttributeMaxDynamicSharedMemorySize, CV_BYTES);

    k_embed<<<NTOK, 256>>>(x, emb);

    for (int i = 0; i < 2; i++){
        k_rmsnorm_split<256><<<NTOK, 256>>>(gh, norm_w + i*EMB, ah, al);
        k_wsplit_t<<<dim3((D_PROJ+31)/32, EMB/32), dim3(32,8)>>>(
            in_proj + (size_t)i*EMB*D_PROJ, wh, wl, EMB, D_PROJ);
        k_mma_gemm2<<<dim3((D_PROJ+255)/256, NTOK/128), 256, SM2_BYTES>>>(
            ah, al, wh, wl, gzx, NTOK, D_PROJ, EMB, nullptr);
        k_conv2<<<dim3(NTOK/64, CONV_DIM/256), 256, CV_BYTES>>>(
            conv_w + i*CONV_DIM*4, conv_b + i*CONV_DIM);
        k_cumsum<<<B_*NHD*NCHUNK, 64>>>(A_log + i*NHD, dt_bias + i*NHD);
        k_ydiag<<<B_*NCHUNK, 256>>>();
        k_states_mma<<<B_*NCHUNK, 256, ST_BYTES>>>();
        k_scan<<<dim3(B_*NHD, 8), 256>>>();
        k_yoff_mma<<<B_*NCHUNK, 256, YO_BYTES>>>(Dv + i*NHD);
        k_gatenorm_split<<<NTOK, 256>>>(gnorm + i*D_INNER, ah, al);
        k_wsplit_t<<<dim3(EMB/32, D_INNER/32), dim3(32,8)>>>(
            outp_w + (size_t)i*D_INNER*EMB, wh, wl, D_INNER, EMB);
        k_mma_gemm<<<dim3(EMB/128, NTOK/128), 256, SM1_BYTES>>>(
            ah, al, wh, wl, gh, NTOK, EMB, D_INNER, gh);
    }

    k_rmsnorm_split<256><<<NTOK, 256>>>(gh, normf, ah, al);
    k_wsplit_t<<<dim3(EMB/32, EMB/32), dim3(32,8)>>>(head_w, wh, wl, EMB, EMB);
    k_mma_gemm<<<dim3(EMB/128, NTOK/128), 256, SM1_BYTES>>>(
        ah, al, wh, wl, (float*)d_out, NTOK, EMB, EMB, nullptr);
}

// round 14
// speedup vs baseline: 1.0202x; 1.0202x over previous
#include <cuda_runtime.h>
#include <cuda_bf16.h>
#include <cstdint>
#include <math.h>

// ---------------- problem constants ----------------
#define B_      4
#define L_      2048
#define EMB     256
#define NHD     8
#define CHK     64
#define NCHUNK  (L_/CHK)          // 32
#define D_INNER 512
#define D_STATE 256
#define CONV_DIM 1024
#define D_PROJ  1544
#define NTOK    (B_*L_)           // 8192

#if defined(__CUDA_ARCH_FEAT_SM103_ALL) || defined(__CUDA_ARCH_FEAT_SM100_ALL) || \
    defined(__CUDA_ARCH_SPECIFIC__) || defined(__CUDA_ARCH_FAMILY_SPECIFIC__)
#define HAS_TCGEN05 1
#else
#define HAS_TCGEN05 0
#endif

// ---------------- scratch (device globals, no allocation) ----------------
__device__ float g_h  [NTOK*EMB];
__device__ float g_zx [NTOK*D_PROJ];
__device__ float g_xbc[NTOK*CONV_DIM];
__device__ float g_dt [NTOK*NHD];
__device__ float g_acs[B_*NHD*NCHUNK*CHK];
__device__ float g_states[(size_t)B_*NCHUNK*NHD*64*256];   // chunk states fp32
__device__ float g_y  [NTOK*D_INNER];
__device__ __nv_bfloat16 g_ah[NTOK*512];
__device__ __nv_bfloat16 g_al[NTOK*512];
__device__ __nv_bfloat16 g_wth[1544*256];
__device__ __nv_bfloat16 g_wtl[1544*256];
__device__ float g_xbt[(size_t)B_*768*L_];
__device__ __nv_bfloat16 g_sph[(size_t)B_*NCHUNK*512*256];
__device__ __nv_bfloat16 g_spl[(size_t)B_*NCHUNK*512*256];

__device__ __forceinline__ void bf16_split(float x, __nv_bfloat16& hi, __nv_bfloat16& lo){
    hi = __float2bfloat16_rn(x);
    lo = __float2bfloat16_rn(x - __bfloat162float(hi));
}

// GEMM v2 (in_proj) smem
#define GM_STAGE0  1024
#define GM_STAGE   98304
#define GM_AH      0
#define GM_AL      16384
#define GM_BH      32768
#define GM_BL      65536
#define SM2_BYTES  197632
// GEMM v1 (out_proj/head) smem: double-buffered, K-chunk 64
#define S1_STAGE0  1024
#define S1_STAGE   65536
#define S1_AH      0
#define S1_AL      16384
#define S1_BH      32768
#define S1_BL      49152
#define SM1_BYTES  132096
// states kernel smem
#define ST_BH      1024
#define ST_BL      33792
#define ST_AH      66560
#define ST_AL      82944
#define ST_BYTES   100352
// yoff kernel smem
#define YO_CH      1024
#define YO_CL      33792
#define YO_AH      66560
#define YO_AL      132096
#define YO_BYTES   197632
// conv smem: (64+3) x 256 fp32
#define CV_BYTES   (67*256*4)

#if HAS_TCGEN05
// ================= tcgen05 helpers =================
__device__ __forceinline__ uint32_t smem_u32(const void* p){
    uint32_t a;
    asm("{ .reg .u64 t; cvta.to.shared.u64 t, %1; cvt.u32.u64 %0, t; }" : "=r"(a) : "l"(p));
    return a;
}
__device__ __forceinline__ uint32_t elect_one(){
    uint32_t p;
    asm volatile("{ .reg .pred p; elect.sync _|p, 0xFFFFFFFF; selp.b32 %0, 1, 0, p; }" : "=r"(p));
    return p;
}
#define TC_ALLOC(sm, n)  asm volatile("tcgen05.alloc.cta_group::1.sync.aligned.shared::cta.b32 [%0], %1;" :: "r"(sm), "r"(n) : "memory")
#define TC_DEALLOC(t, n) asm volatile("tcgen05.dealloc.cta_group::1.sync.aligned.b32 %0, %1;" :: "r"(t), "r"(n))
#define TC_RELINQ()      asm volatile("tcgen05.relinquish_alloc_permit.cta_group::1.sync.aligned;")
#define TC_COMMIT(mb)    asm volatile("tcgen05.commit.cta_group::1.mbarrier::arrive::one.shared::cluster.b64 [%0];" :: "r"(mb) : "memory")
#define TC_FENCE_AFTER() asm volatile("tcgen05.fence::after_thread_sync;" ::: "memory")
#define TC_FENCE_BEFORE() asm volatile("tcgen05.fence::before_thread_sync;" ::: "memory")
#define TC_WAIT_LD()     asm volatile("tcgen05.wait::ld.sync.aligned;" ::: "memory")
#define MBAR_INIT(mb, c) asm volatile("mbarrier.init.shared.b64 [%0], %1;" :: "r"(mb), "r"(c) : "memory")
#define MBAR_WAIT(mb, ph) do { \
    uint32_t _m = (mb), _p = (ph), _d; \
    asm volatile("{ .reg .pred p; mbarrier.try_wait.parity.acquire.cta.shared::cta.b64 p, [%1], %2; selp.b32 %0, 1, 0, p; }" \
        : "=r"(_d) : "r"(_m), "r"(_p) : "memory"); \
    if (!_d) { \
        asm volatile("{ .reg .pred P1; WL_%=: mbarrier.try_wait.parity.acquire.cta.shared::cta.b64 P1, [%0], %1, 0x989680; @P1 bra.uni WD_%=; bra.uni WL_%=; WD_%=: }" \
            :: "r"(_m), "r"(_p) : "memory"); \
    } } while(0)
#define TC_LD_X32(r, ta) \
    asm volatile("tcgen05.ld.sync.aligned.32x32b.x32.b32 " \
        "{%0,%1,%2,%3,%4,%5,%6,%7,%8,%9,%10,%11,%12,%13,%14,%15," \
        "%16,%17,%18,%19,%20,%21,%22,%23,%24,%25,%26,%27,%28,%29,%30,%31}, [%32];" \
        : "=r"((r)[0]),"=r"((r)[1]),"=r"((r)[2]),"=r"((r)[3]),"=r"((r)[4]),"=r"((r)[5]),"=r"((r)[6]),"=r"((r)[7]), \
          "=r"((r)[8]),"=r"((r)[9]),"=r"((r)[10]),"=r"((r)[11]),"=r"((r)[12]),"=r"((r)[13]),"=r"((r)[14]),"=r"((r)[15]), \
          "=r"((r)[16]),"=r"((r)[17]),"=r"((r)[18]),"=r"((r)[19]),"=r"((r)[20]),"=r"((r)[21]),"=r"((r)[22]),"=r"((r)[23]), \
          "=r"((r)[24]),"=r"((r)[25]),"=r"((r)[26]),"=r"((r)[27]),"=r"((r)[28]),"=r"((r)[29]),"=r"((r)[30]),"=r"((r)[31]) \
        : "r"(ta))

static __device__ __forceinline__ uint64_t make_desc_sw128(uint32_t addr){
    const uint64_t base =
        (uint64_t(2)  << 61) | (uint64_t(1) << 46) | (uint64_t(64) << 32) | (uint64_t(1) << 16);
    return base | ((uint64_t)(addr >> 4) & 0x3FFF);
}
__device__ __forceinline__ void mma_bf16_ss(uint32_t d, uint64_t ad, uint64_t bd,
                                            uint32_t idesc, bool acc){
    uint32_t en = acc ? 1u : 0u;
    asm volatile(
        "{\n\t"
        ".reg .pred p;\n\t"
        "setp.ne.u32 p, %5, 0;\n\t"
        "tcgen05.mma.cta_group::1.kind::f16 [%0], %1, %2, %3, {%4, %4, %4, %4}, p;\n\t"
        "}"
        :: "r"(d), "l"(ad), "l"(bd), "r"(idesc), "r"(0u), "r"(en)
        : "memory");
}
#define SWZ(o) ((o) ^ (((o) >> 3) & 0x70))
#define IDESC_N128 ((1u<<4) | (1u<<7) | (1u<<10) | ((128u/8u)<<17) | ((128u/16u)<<24))
#define IDESC_N64  ((1u<<4) | (1u<<7) | (1u<<10) | (( 64u/8u)<<17) | ((128u/16u)<<24))
#endif // HAS_TCGEN05

// ---------------- GEMM v2 (in_proj): 128x256 tile, K chunks of 64, double-buffered ----------------
__global__ void __launch_bounds__(256)
k_mma_gemm2(const __nv_bfloat16* __restrict__ Ah, const __nv_bfloat16* __restrict__ Al,
            const __nv_bfloat16* __restrict__ Bh, const __nv_bfloat16* __restrict__ Bl,
            float* __restrict__ C, int M, int N, int K,
            const float* __restrict__ resid){
    extern __shared__ char smem[];
    int tid = threadIdx.x;
    int bm = blockIdx.y * 128, bn = blockIdx.x * 256;

#if HAS_TCGEN05
    uint32_t sbase = smem_u32(smem);
    int wid = tid >> 5, lid = tid & 31;
    if (wid == 0) TC_ALLOC(sbase, 256);
    if (tid == 0){ MBAR_INIT(sbase + 8, 1); MBAR_INIT(sbase + 16, 1); }
    __syncthreads();
    uint32_t tmem;
    asm volatile("ld.shared.b32 %0, [%1];" : "=r"(tmem) : "r"(sbase));

    int nc = K >> 6;
    int ph0 = 0, ph1 = 0;
    for (int c = 0; c < nc; c++){
        int buf = c & 1;
        uint32_t sb = sbase + GM_STAGE0 + buf*GM_STAGE;
        char* smb = smem + GM_STAGE0 + buf*GM_STAGE;
        int kc = c << 6;
        if (c >= 2){
            if (buf == 0){ MBAR_WAIT(sbase + 8,  ph0); ph0 ^= 1; }
            else         { MBAR_WAIT(sbase + 16, ph1); ph1 ^= 1; }
        }
        #pragma unroll
        for (int it = 0; it < 4; it++){
            int v = tid + it*256;
            int m = v >> 3, u = v & 7;
            uint32_t so = SWZ((uint32_t)(m*128 + u*16));
            size_t gi = (size_t)(bm+m)*K + kc + u*8;
            *(uint4*)(smb + GM_AH + so) = *(const uint4*)&Ah[gi];
            *(uint4*)(smb + GM_AL + so) = *(const uint4*)&Al[gi];
        }
        #pragma unroll
        for (int it = 0; it < 8; it++){
            int v = tid + it*256;
            int n = v >> 3, u = v & 7;
            uint32_t so = SWZ((uint32_t)(n*128 + u*16));
            uint4 vh = make_uint4(0,0,0,0), vl = make_uint4(0,0,0,0);
            if (bn + n < N){
                size_t gi = (size_t)(bn+n)*K + kc + u*8;
                vh = *(const uint4*)&Bh[gi];
                vl = *(const uint4*)&Bl[gi];
            }
            *(uint4*)(smb + GM_BH + so) = vh;
            *(uint4*)(smb + GM_BL + so) = vl;
        }
        __syncthreads();
        asm volatile("fence.proxy.async.shared::cta;" ::: "memory");

        if (wid == 0 && elect_one()){
            uint64_t ah = make_desc_sw128(sb + GM_AH);
            uint64_t al = make_desc_sw128(sb + GM_AL);
            #pragma unroll
            for (int half = 0; half < 2; half++){
                uint64_t bh = make_desc_sw128(sb + GM_BH + half*16384);
                uint64_t bl = make_desc_sw128(sb + GM_BL + half*16384);
                uint32_t dt_ = tmem + half*128;
                #pragma unroll
                for (int s = 0; s < 4; s++){
                    bool acc = !(c == 0 && s == 0);
                    mma_bf16_ss(dt_, ah + s*2, bh + s*2, IDESC_N128, acc);
                    mma_bf16_ss(dt_, ah + s*2, bl + s*2, IDESC_N128, true);
                    mma_bf16_ss(dt_, al + s*2, bh + s*2, IDESC_N128, true);
                }
            }
            TC_COMMIT(sbase + 8 + buf*8);
        }
        __syncthreads();
    }
    {
        int lb = (nc-1) & 1;
        if (lb == 0) MBAR_WAIT(sbase + 8,  ph0);
        else         MBAR_WAIT(sbase + 16, ph1);
    }

    TC_FENCE_AFTER();
    float* eb = (float*)(smem + GM_STAGE0);
    for (int g = 0; g < 8; g++){
        if (wid < 4){
            uint32_t r[32];
            TC_LD_X32(r, tmem + g*32);
            TC_WAIT_LD();
            int m = wid*32 + lid;
            #pragma unroll
            for (int j = 0; j < 32; j++)
                eb[m*33 + j] = __uint_as_float(r[j]);
        }
        __syncthreads();
        #pragma unroll
        for (int it = 0; it < 16; it++){
            int v = tid + it*256;
            int m = v >> 5, j = v & 31;
            int n = bn + g*32 + j;
            if (n < N){
                size_t idx = (size_t)(bm+m)*N + n;
                float val = eb[m*33 + j];
                if (resid) val += resid[idx];
                C[idx] = val;
            }
        }
        __syncthreads();
    }
    if (wid == 0){
        TC_RELINQ();
        TC_DEALLOC(tmem, 256);
    }
#else
    float (*As)[132] = (float(*)[132])(smem);
    float (*Ws)[132] = (float(*)[132])(smem + 16*132*4);
    int tx = tid & 15, ty = tid >> 4;
    for (int half = 0; half < 2; half++){
        int bn2 = bn + half*128;
        float acc[8][8] = {};
        for (int k0 = 0; k0 < K; k0 += 16){
            #pragma unroll
            for (int r = 0; r < 8; r++){
                int i = tid + r*256;
                int m = i >> 4, k = i & 15;
                size_t gi = (size_t)(bm+m)*K + k0 + k;
                As[k][m] = __bfloat162float(Ah[gi]) + __bfloat162float(Al[gi]);
            }
            #pragma unroll
            for (int r = 0; r < 8; r++){
                int i = tid + r*256;
                int k = i >> 7, n = i & 127;
                float w = 0.f;
                if (bn2+n < N){
                    size_t gi = (size_t)(bn2+n)*K + k0 + k;
                    w = __bfloat162float(Bh[gi]) + __bfloat162float(Bl[gi]);
                }
                Ws[k][n] = w;
            }
            __syncthreads();
            #pragma unroll
            for (int kk = 0; kk < 16; kk++){
                float a[8], b[8];
                #pragma unroll
                for (int i = 0; i < 8; i++) a[i] = As[kk][ty*8+i];
                #pragma unroll
                for (int j = 0; j < 8; j++) b[j] = Ws[kk][tx*8+j];
                #pragma unroll
                for (int i = 0; i < 8; i++)
                    #pragma unroll
                    for (int j = 0; j < 8; j++)
                        acc[i][j] = fmaf(a[i], b[j], acc[i][j]);
            }
            __syncthreads();
        }
        #pragma unroll
        for (int i = 0; i < 8; i++){
            int m = bm + ty*8 + i;
            #pragma unroll
            for (int j = 0; j < 8; j++){
                int n = bn2 + tx*8 + j;
                if (n < N){
                    size_t idx = (size_t)m*N + n;
                    float v = acc[i][j];
                    if (resid) v += resid[idx];
                    C[idx] = v;
                }
            }
        }
        __syncthreads();
    }
#endif
}

// ---------------- GEMM v1 (out_proj/head): 128x128 tile, K chunks of 64, double-buffered ----------------
__global__ void __launch_bounds__(256)
k_mma_gemm(const __nv_bfloat16* __restrict__ Ah, const __nv_bfloat16* __restrict__ Al,
           const __nv_bfloat16* __restrict__ Bh, const __nv_bfloat16* __restrict__ Bl,
           float* __restrict__ C, int M, int N, int K,
           const float* __restrict__ resid){
    extern __shared__ char smem[];
    int tid = threadIdx.x;
    int bm = blockIdx.y * 128, bn = blockIdx.x * 128;

#if HAS_TCGEN05
    uint32_t sbase = smem_u32(smem);
    int wid = tid >> 5, lid = tid & 31;
    if (wid == 0) TC_ALLOC(sbase, 128);
    if (tid == 0){ MBAR_INIT(sbase + 8, 1); MBAR_INIT(sbase + 16, 1); }
    __syncthreads();
    uint32_t tmem;
    asm volatile("ld.shared.b32 %0, [%1];" : "=r"(tmem) : "r"(sbase));

    int nc = K >> 6;
    int ph0 = 0, ph1 = 0;
    for (int c = 0; c < nc; c++){
        int buf = c & 1;
        uint32_t sb = sbase + S1_STAGE0 + buf*S1_STAGE;
        char* smb = smem + S1_STAGE0 + buf*S1_STAGE;
        int kc = c << 6;
        if (c >= 2){
            if (buf == 0){ MBAR_WAIT(sbase + 8,  ph0); ph0 ^= 1; }
            else         { MBAR_WAIT(sbase + 16, ph1); ph1 ^= 1; }
        }
        #pragma unroll
        for (int it = 0; it < 4; it++){
            int v = tid + it*256;
            int m = v >> 3, u = v & 7;
            uint32_t so = SWZ((uint32_t)(m*128 + u*16));
            size_t gi = (size_t)(bm+m)*K + kc + u*8;
            *(uint4*)(smb + S1_AH + so) = *(const uint4*)&Ah[gi];
            *(uint4*)(smb + S1_AL + so) = *(const uint4*)&Al[gi];
        }
        #pragma unroll
        for (int it = 0; it < 4; it++){
            int v = tid + it*256;
            int n = v >> 3, u = v & 7;
            uint32_t so = SWZ((uint32_t)(n*128 + u*16));
            uint4 vh = make_uint4(0,0,0,0), vl = make_uint4(0,0,0,0);
            if (bn + n < N){
                size_t gi = (size_t)(bn+n)*K + kc + u*8;
                vh = *(const uint4*)&Bh[gi];
                vl = *(const uint4*)&Bl[gi];
            }
            *(uint4*)(smb + S1_BH + so) = vh;
            *(uint4*)(smb + S1_BL + so) = vl;
        }
        __syncthreads();
        asm volatile("fence.proxy.async.shared::cta;" ::: "memory");

        if (wid == 0 && elect_one()){
            uint64_t ah = make_desc_sw128(sb + S1_AH);
            uint64_t al = make_desc_sw128(sb + S1_AL);
            uint64_t bh = make_desc_sw128(sb + S1_BH);
            uint64_t bl = make_desc_sw128(sb + S1_BL);
            #pragma unroll
            for (int s = 0; s < 4; s++){
                bool acc = !(c == 0 && s == 0);
                mma_bf16_ss(tmem, ah + s*2, bh + s*2, IDESC_N128, acc);
                mma_bf16_ss(tmem, ah + s*2, bl + s*2, IDESC_N128, true);
                mma_bf16_ss(tmem, al + s*2, bh + s*2, IDESC_N128, true);
            }
            TC_COMMIT(sbase + 8 + buf*8);
        }
        __syncthreads();
    }
    {
        int lb = (nc-1) & 1;
        if (lb == 0) MBAR_WAIT(sbase + 8,  ph0);
        else         MBAR_WAIT(sbase + 16, ph1);
    }

    TC_FENCE_AFTER();
    float* eb = (float*)(smem + S1_STAGE0);
    for (int g = 0; g < 4; g++){
        if (wid < 4){
            uint32_t r[32];
            TC_LD_X32(r, tmem + g*32);
            TC_WAIT_LD();
            int m = wid*32 + lid;
            #pragma unroll
            for (int j = 0; j < 32; j++)
                eb[m*33 + j] = __uint_as_float(r[j]);
        }
        __syncthreads();
        #pragma unroll
        for (int it = 0; it < 16; it++){
            int v = tid + it*256;
            int m = v >> 5, j = v & 31;
            int n = bn + g*32 + j;
            if (n < N){
                size_t idx = (size_t)(bm+m)*N + n;
                float val = eb[m*33 + j];
                if (resid) val += resid[idx];
                C[idx] = val;
            }
        }
        __syncthreads();
    }
    if (wid == 0){
        TC_RELINQ();
        TC_DEALLOC(tmem, 128);
    }
#else
    float (*As)[132] = (float(*)[132])(smem);
    float (*Ws)[132] = (float(*)[132])(smem + 16*132*4);
    int tx = tid & 15, ty = tid >> 4;
    float acc[8][8] = {};
    for (int k0 = 0; k0 < K; k0 += 16){
        #pragma unroll
        for (int r = 0; r < 8; r++){
            int i = tid + r*256;
            int m = i >> 4, k = i & 15;
            size_t gi = (size_t)(bm+m)*K + k0 + k;
            As[k][m] = __bfloat162float(Ah[gi]) + __bfloat162float(Al[gi]);
        }
        #pragma unroll
        for (int r = 0; r < 8; r++){
            int i = tid + r*256;
            int k = i >> 7, n = i & 127;
            float w = 0.f;
            if (bn+n < N){
                size_t gi = (size_t)(bn+n)*K + k0 + k;
                w = __bfloat162float(Bh[gi]) + __bfloat162float(Bl[gi]);
            }
            Ws[k][n] = w;
        }
        __syncthreads();
        #pragma unroll
        for (int kk = 0; kk < 16; kk++){
            float a[8], b[8];
            #pragma unroll
            for (int i = 0; i < 8; i++) a[i] = As[kk][ty*8+i];
            #pragma unroll
            for (int j = 0; j < 8; j++) b[j] = Ws[kk][tx*8+j];
            #pragma unroll
            for (int i = 0; i < 8; i++)
                #pragma unroll
                for (int j = 0; j < 8; j++)
                    acc[i][j] = fmaf(a[i], b[j], acc[i][j]);
        }
        __syncthreads();
    }
    #pragma unroll
    for (int i = 0; i < 8; i++){
        int m = bm + ty*8 + i;
        #pragma unroll
        for (int j = 0; j < 8; j++){
            int n = bn + tx*8 + j;
            if (n < N){
                size_t idx = (size_t)m*N + n;
                float v = acc[i][j];
                if (resid) v += resid[idx];
                C[idx] = v;
            }
        }
    }
#endif
}

// ---------------- states: S[hp,n] = sum_l xdts[l,hp]*B[l,n]  (tcgen05, fp32 out) ----------------
__global__ void __launch_bounds__(256)
k_states_mma(){
    extern __shared__ char smem[];
    int tid = threadIdx.x;
    int bc = blockIdx.x;
    int c = bc & 31, b = bc >> 5;
    int t0 = b*L_ + c*64;
#if HAS_TCGEN05
    uint32_t sbase = smem_u32(smem);
    int wid = tid >> 5, lid = tid & 31;
    float* sc = (float*)(smem + 128);
    if (wid == 0) TC_ALLOC(sbase, 128);
    if (tid == 0) MBAR_INIT(sbase + 8, 1);
    __syncthreads();
    uint32_t tmem;
    asm volatile("ld.shared.b32 %0, [%1];" : "=r"(tmem) : "r"(sbase));

    #pragma unroll
    for (int it = 0; it < 16; it++){
        int v = tid + it*256;
        int n = v >> 4, u = v & 15;
        const float* src = g_xbt + ((size_t)b*768 + 512 + n)*L_ + c*64 + u*4;
        float4 a = *(const float4*)src;
        __nv_bfloat16 h0,l0,h1,l1,h2,l2,h3,l3;
        bf16_split(a.x,h0,l0); bf16_split(a.y,h1,l1);
        bf16_split(a.z,h2,l2); bf16_split(a.w,h3,l3);
        __nv_bfloat162 hp2 = __halves2bfloat162(h0,h1), hq2 = __halves2bfloat162(h2,h3);
        __nv_bfloat162 lp2 = __halves2bfloat162(l0,l1), lq2 = __halves2bfloat162(l2,l3);
        int nt = n >> 7, r = n & 127;
        uint32_t so = nt*16384 + SWZ((uint32_t)(r*128 + u*8));
        *(uint2*)(smem + ST_BH + so) = make_uint2(*(uint32_t*)&hp2, *(uint32_t*)&hq2);
        *(uint2*)(smem + ST_BL + so) = make_uint2(*(uint32_t*)&lp2, *(uint32_t*)&lq2);
    }

    int phase = 0;
    for (int ht = 0; ht < 4; ht++){
        __syncthreads();
        if (tid < 128){
            int hl = tid >> 6, l = tid & 63;
            int h = ht*2 + hl;
            const float* ap = g_acs + ((size_t)(b*8+h)*32 + c)*64;
            sc[hl*64 + l] = g_dt[(size_t)(t0+l)*NHD + h] * __expf(ap[63] - ap[l]);
        }
        __syncthreads();
        #pragma unroll
        for (int it = 0; it < 8; it++){
            int v = tid + it*256;
            int r = v >> 4, u = v & 15;
            const float* src = g_xbt + ((size_t)b*768 + ht*128 + r)*L_ + c*64 + u*4;
            float4 a = *(const float4*)src;
            const float* s4 = sc + (r >> 6)*64 + u*4;
            a.x *= s4[0]; a.y *= s4[1]; a.z *= s4[2]; a.w *= s4[3];
            __nv_bfloat16 h0,l0,h1,l1,h2,l2,h3,l3;
            bf16_split(a.x,h0,l0); bf16_split(a.y,h1,l1);
            bf16_split(a.z,h2,l2); bf16_split(a.w,h3,l3);
            __nv_bfloat162 hp2 = __halves2bfloat162(h0,h1), hq2 = __halves2bfloat162(h2,h3);
            __nv_bfloat162 lp2 = __halves2bfloat162(l0,l1), lq2 = __halves2bfloat162(l2,l3);
            uint32_t so = SWZ((uint32_t)(r*128 + u*8));
            *(uint2*)(smem + ST_AH + so) = make_uint2(*(uint32_t*)&hp2, *(uint32_t*)&hq2);
            *(uint2*)(smem + ST_AL + so) = make_uint2(*(uint32_t*)&lp2, *(uint32_t*)&lq2);
        }
        __syncthreads();
        asm volatile("fence.proxy.async.shared::cta;" ::: "memory");

        for (int nt = 0; nt < 2; nt++){
            if (wid == 0 && elect_one()){
                uint64_t ah = make_desc_sw128(sbase + ST_AH);
                uint64_t al = make_desc_sw128(sbase + ST_AL);
                uint64_t bh = make_desc_sw128(sbase + ST_BH + nt*16384);
                uint64_t bl = make_desc_sw128(sbase + ST_BL + nt*16384);
                bool first = true;
                #pragma unroll
                for (int s = 0; s < 4; s++){
                    mma_bf16_ss(tmem, ah + s*2, bh + s*2, IDESC_N128, !first);
                    first = false;
                    mma_bf16_ss(tmem, ah + s*2, bl + s*2, IDESC_N128, true);
                    mma_bf16_ss(tmem, al + s*2, bh + s*2, IDESC_N128, true);
                }
                TC_COMMIT(sbase + 8);
            }
            MBAR_WAIT(sbase + 8, phase);
            phase ^= 1;
            TC_FENCE_AFTER();
            if (wid < 4){
                int hp = ht*128 + wid*32 + lid;
                float* out = g_states + ((size_t)bc*512 + hp)*256 + nt*128;
                #pragma unroll
                for (int g = 0; g < 4; g++){
                    uint32_t r[32];
                    TC_LD_X32(r, tmem + g*32);
                    TC_WAIT_LD();
                    #pragma unroll
                    for (int j = 0; j < 32; j += 4){
                        float4 v4 = make_float4(__uint_as_float(r[j]),   __uint_as_float(r[j+1]),
                                                __uint_as_float(r[j+2]), __uint_as_float(r[j+3]));
                        *(float4*)(out + g*32 + j) = v4;
                    }
                }
                TC_FENCE_BEFORE();
            }
            __syncthreads();
        }
    }
    if (wid == 0){
        TC_RELINQ();
        TC_DEALLOC(tmem, 128);
    }
#else
    __shared__ float sc8[8][64];
    for (int v = tid; v < 512; v += 256){
        int h = v >> 6, l = v & 63;
        const float* ap = g_acs + ((size_t)(b*8+h)*32 + c)*64;
        sc8[h][l] = g_dt[(size_t)(t0+l)*NHD + h] * __expf(ap[63] - ap[l]);
    }
    __syncthreads();
    for (int h = 0; h < 8; h++)
        for (int idx = tid; idx < 16384; idx += 256){
            int p = idx >> 8, n = idx & 255;
            float s = 0.f;
            for (int l = 0; l < 64; l++)
                s += g_xbc[(size_t)(t0+l)*CONV_DIM + h*64 + p] * sc8[h][l]
                   * g_xbc[(size_t)(t0+l)*CONV_DIM + 512 + n];
            g_states[((size_t)bc*512 + h*64 + p)*256 + n] = s;
        }
#endif
}

// ---------------- yoff ----------------
__global__ void __launch_bounds__(256)
k_yoff_mma(const float* __restrict__ Dvec){
    extern __shared__ char smem[];
    int tid = threadIdx.x;
    int bc = blockIdx.x;
    int c = bc & 31, b = bc >> 5;
    int t0 = b*L_ + c*64;
#if HAS_TCGEN05
    uint32_t sbase = smem_u32(smem);
    int wid = tid >> 5, lid = tid & 31;
    float* ex = (float*)(smem + 128);
    if (wid == 0) TC_ALLOC(sbase, 64);
    if (tid == 0) MBAR_INIT(sbase + 8, 1);
    __syncthreads();
    uint32_t tmem;
    asm volatile("ld.shared.b32 %0, [%1];" : "=r"(tmem) : "r"(sbase));

    #pragma unroll
    for (int it = 0; it < 8; it++){
        int v = tid + it*256;
        int l = v >> 5, q = v & 31;
        const float* src = &g_xbc[(size_t)(t0+l)*CONV_DIM + 768 + q*8];
        float4 a = *(const float4*)src;
        float4 bq = *(const float4*)(src + 4);
        __nv_bfloat16 h0,l0,h1,l1,h2,l2,h3,l3,h4,l4,h5,l5,h6,l6,h7,l7;
        bf16_split(a.x,h0,l0);  bf16_split(a.y,h1,l1);
        bf16_split(a.z,h2,l2);  bf16_split(a.w,h3,l3);
        bf16_split(bq.x,h4,l4); bf16_split(bq.y,h5,l5);
        bf16_split(bq.z,h6,l6); bf16_split(bq.w,h7,l7);
        __nv_bfloat162 H0 = __halves2bfloat162(h0,h1), H1 = __halves2bfloat162(h2,h3);
        __nv_bfloat162 H2 = __halves2bfloat162(h4,h5), H3 = __halves2bfloat162(h6,h7);
        __nv_bfloat162 L0 = __halves2bfloat162(l0,l1), L1 = __halves2bfloat162(l2,l3);
        __nv_bfloat162 L2 = __halves2bfloat162(l4,l5), L3 = __halves2bfloat162(l6,l7);
        int kt = q >> 3;
        uint32_t so = kt*8192 + SWZ((uint32_t)(l*128 + (q & 7)*16));
        *(uint4*)(smem + YO_CH + so) = make_uint4(*(uint32_t*)&H0, *(uint32_t*)&H1,
                                                  *(uint32_t*)&H2, *(uint32_t*)&H3);
        *(uint4*)(smem + YO_CL + so) = make_uint4(*(uint32_t*)&L0, *(uint32_t*)&L1,
                                                  *(uint32_t*)&L2, *(uint32_t*)&L3);
    }

    int phase = 0;
    for (int ht = 0; ht < 4; ht++){
        __syncthreads();
        if (tid < 128){
            int hl = tid >> 6, l = tid & 63;
            int h = ht*2 + hl;
            ex[hl*64 + l] = __expf(g_acs[((size_t)(b*8+h)*32 + c)*64 + l]);
        }
        #pragma unroll
        for (int it = 0; it < 16; it++){
            int v = tid + it*256;
            int r = v >> 5, u = v & 31;
            size_t gi = ((size_t)bc*512 + ht*128 + r)*256 + u*8;
            int kt = u >> 3;
            uint32_t so = kt*16384 + SWZ((uint32_t)(r*128 + (u & 7)*16));
            *(uint4*)(smem + YO_AH + so) = *(const uint4*)&g_sph[gi];
            *(uint4*)(smem + YO_AL + so) = *(const uint4*)&g_spl[gi];
        }
        __syncthreads();
        asm volatile("fence.proxy.async.shared::cta;" ::: "memory");

        if (wid == 0 && elect_one()){
            bool first = true;
            #pragma unroll
            for (int kt = 0; kt < 4; kt++){
                uint64_t ah = make_desc_sw128(sbase + YO_AH + kt*16384);
                uint64_t al = make_desc_sw128(sbase + YO_AL + kt*16384);
                uint64_t bh = make_desc_sw128(sbase + YO_CH + kt*8192);
                uint64_t bl = make_desc_sw128(sbase + YO_CL + kt*8192);
                #pragma unroll
                for (int s = 0; s < 4; s++){
                    mma_bf16_ss(tmem, ah + s*2, bh + s*2, IDESC_N64, !first);
                    first = false;
                    mma_bf16_ss(tmem, ah + s*2, bl + s*2, IDESC_N64, true);
                    mma_bf16_ss(tmem, al + s*2, bh + s*2, IDESC_N64, true);
                }
            }
            TC_COMMIT(sbase + 8);
        }
        MBAR_WAIT(sbase + 8, phase);
        phase ^= 1;
        TC_FENCE_AFTER();
        float* eb = (float*)(smem + YO_AH);
        if (wid < 4){
            int hp = wid*32 + lid;
            #pragma unroll
            for (int g = 0; g < 2; g++){
                uint32_t r[32];
                TC_LD_X32(r, tmem + g*32);
                TC_WAIT_LD();
                #pragma unroll
                for (int j = 0; j < 32; j++)
                    eb[hp*65 + g*32 + j] = __uint_as_float(r[j]);
            }
            TC_FENCE_BEFORE();
        }
        __syncthreads();
        #pragma unroll
        for (int it = 0; it < 32; it++){
            int v = tid + it*256;
            int l = v >> 7, hp = v & 127;
            int h = ht*2 + (hp >> 6);
            float val = ex[(hp >> 6)*64 + l] * eb[hp*65 + l];
            float xh = g_xbc[(size_t)(t0+l)*CONV_DIM + ht*128 + hp];
            size_t oi = (size_t)(t0+l)*D_INNER + ht*128 + hp;
            g_y[oi] += val + xh*Dvec[h];
        }
    }
    __syncthreads();
    if (wid == 0){
        TC_RELINQ();
        TC_DEALLOC(tmem, 64);
    }
#else
    for (int idx = tid; idx < 64*512; idx += 256){
        int l = idx >> 9, hp = idx & 511;
        int h = hp >> 6;
        const __nv_bfloat16* sh = g_sph + ((size_t)bc*512 + hp)*256;
        const __nv_bfloat16* sl = g_spl + ((size_t)bc*512 + hp)*256;
        float acc = 0.f;
        for (int n = 0; n < 256; n++)
            acc += g_xbc[(size_t)(t0+l)*CONV_DIM + 768 + n]
                 * (__bfloat162float(sh[n]) + __bfloat162float(sl[n]));
        float e = __expf(g_acs[((size_t)(b*8+h)*32 + c)*64 + l]);
        float xh = g_xbc[(size_t)(t0+l)*CONV_DIM + hp];
        g_y[(size_t)(t0+l)*D_INNER + hp] += e*acc + xh*Dvec[h];
    }
#endif
}

// ---------------- transpose x,B channels ----------------
__global__ void k_transpose(){
    __shared__ float t[32][33];
    int ch0 = blockIdx.x*32, l0 = blockIdx.y*32, b = blockIdx.z;
    int tx = threadIdx.x, ty = threadIdx.y;
    #pragma unroll
    for (int r = ty; r < 32; r += 8)
        t[r][tx] = g_xbc[(size_t)(b*L_ + l0 + r)*CONV_DIM + ch0 + tx];
    __syncthreads();
    #pragma unroll
    for (int r = ty; r < 32; r += 8)
        g_xbt[((size_t)b*768 + ch0 + r)*L_ + l0 + tx] = t[tx][r];
}

// ---------------- W split + transpose ----------------
__global__ void k_wsplit_t(const float* __restrict__ W,
                           __nv_bfloat16* __restrict__ Wh, __nv_bfloat16* __restrict__ Wl,
                           int K, int N){
    __shared__ float tile[32][33];
    int n0 = blockIdx.x*32, k0 = blockIdx.y*32;
    int tx = threadIdx.x, ty = threadIdx.y;
    #pragma unroll
    for (int r = ty; r < 32; r += 8){
        int k = k0 + r, n = n0 + tx;
        tile[r][tx] = (k < K && n < N) ? W[(size_t)k*N + n] : 0.f;
    }
    __syncthreads();
    #pragma unroll
    for (int r = ty; r < 32; r += 8){
        int n = n0 + r, k = k0 + tx;
        if (n < N && k < K){
            __nv_bfloat16 hi, lo;
            bf16_split(tile[tx][r], hi, lo);
            Wh[(size_t)n*K + k] = hi;
            Wl[(size_t)n*K + k] = lo;
        }
    }
}

// ---------------- embed ----------------
__global__ void k_embed(const float* __restrict__ x, const float* __restrict__ emb){
    int t = blockIdx.x;
    int e = threadIdx.x;
    int v = (int)(255.0f * x[t]);
    v = min(max(v, 0), 255);
    g_h[(size_t)t*EMB + e] = emb[(size_t)v*EMB + e];
}

// ---------------- rmsnorm + bf16 split ----------------
template<int DIM>
__global__ void k_rmsnorm_split(const float* __restrict__ in, const float* __restrict__ w,
                                __nv_bfloat16* __restrict__ oh, __nv_bfloat16* __restrict__ ol){
    int t = blockIdx.x;
    const float* row = in + (size_t)t*DIM;
    __shared__ float red[8];
    float v[DIM/256];
    float ss = 0.f;
    #pragma unroll
    for (int i = 0; i < DIM/256; i++){
        v[i] = row[threadIdx.x + i*256];
        ss += v[i]*v[i];
    }
    #pragma unroll
    for (int o = 16; o; o >>= 1) ss += __shfl_xor_sync(0xffffffffu, ss, o);
    if ((threadIdx.x & 31) == 0) red[threadIdx.x >> 5] = ss;
    __syncthreads();
    if (threadIdx.x < 32){
        float s2 = (threadIdx.x < 8) ? red[threadIdx.x] : 0.f;
        #pragma unroll
        for (int o = 4; o; o >>= 1) s2 += __shfl_xor_sync(0xffffffffu, s2, o);
        if (threadIdx.x == 0) red[0] = s2;
    }
    __syncthreads();
    float scale = rsqrtf(red[0]/(float)DIM + 1e-5f);
    #pragma unroll
    for (int i = 0; i < DIM/256; i++){
        int d = threadIdx.x + i*256;
        float val = v[i]*scale*w[d];
        __nv_bfloat16 hi, lo;
        bf16_split(val, hi, lo);
        oh[(size_t)t*DIM + d] = hi;
        ol[(size_t)t*DIM + d] = lo;
    }
}

// ---------------- smem-tiled causal depthwise conv (k=4) + bias + silu ----------------
__global__ void __launch_bounds__(256)
k_conv2(const float* __restrict__ cw, const float* __restrict__ cb){
    extern __shared__ float s[];                 // [67][256]
    int t0  = blockIdx.x * 64;
    int ch0 = blockIdx.y * 256;
    int tid = threadIdx.x;
    int l0  = t0 & (L_-1);
    #pragma unroll
    for (int r = 0; r < 67; r++){
        float val = 0.f;
        if (l0 - 3 + r >= 0)
            val = g_zx[(size_t)(t0 - 3 + r)*D_PROJ + 512 + ch0 + tid];
        s[r*256 + tid] = val;
    }
    __syncthreads();
    int ch = ch0 + tid;
    float w0 = cw[ch*4+0], w1 = cw[ch*4+1], w2 = cw[ch*4+2], w3 = cw[ch*4+3];
    float bias = cb[ch];
    #pragma unroll 4
    for (int r = 0; r < 64; r++){
        float acc = bias;
        acc = fmaf(w0, s[(r+0)*256 + tid], acc);
        acc = fmaf(w1, s[(r+1)*256 + tid], acc);
        acc = fmaf(w2, s[(r+2)*256 + tid], acc);
        acc = fmaf(w3, s[(r+3)*256 + tid], acc);
        acc = acc / (1.f + __expf(-acc));
        g_xbc[(size_t)(t0+r)*CONV_DIM + ch] = acc;
    }
}

// ---------------- fused dt(softplus) + per-chunk cumsum ----------------
__global__ void k_cumsum(const float* __restrict__ A_log, const float* __restrict__ dt_bias){
    int bhc = blockIdx.x;
    int c = bhc & 31;
    int h = (bhc >> 5) & 7;
    int b = bhc >> 8;
    int l = threadIdx.x;
    int t = b*L_ + c*64 + l;
    float v = g_zx[(size_t)t*D_PROJ + 1536 + h] + dt_bias[h];
    float dt = (v > 20.f) ? v : log1pf(__expf(v));
    g_dt[t*NHD + h] = dt;
    float a = -__expf(A_log[h]) * dt;
    __shared__ float s[64];
    s[l] = a; __syncthreads();
    #pragma unroll
    for (int off = 1; off < 64; off <<= 1){
        float vv = s[l] + ((l >= off) ? s[l-off] : 0.f);
        __syncthreads();
        s[l] = vv;
        __syncthreads();
    }
    g_acs[bhc*64 + l] = s[l];
}

// ---------------- Y_diag per (b,c) (fp32 FMA) ----------------
__global__ void k_ydiag(){
    __shared__ float bufA[64][65];
    __shared__ float bufB[64][65];
    __shared__ float acsS[64];
    int bc = blockIdx.x;
    int c = bc & 31, b = bc >> 5;
    int t0 = b*L_ + c*64;
    int tid = threadIdx.x, tx = tid & 15, ty = tid >> 4;
    float G[4][4] = {};
    for (int nt = 0; nt < 4; nt++){
        for (int i = tid; i < 4096; i += 256){
            int r = i >> 6, nn = i & 63;
            bufA[r][nn] = g_xbc[(size_t)(t0+r)*CONV_DIM + 768 + nt*64 + nn];
            bufB[r][nn] = g_xbc[(size_t)(t0+r)*CONV_DIM + 512 + nt*64 + nn];
        }
        __syncthreads();
        #pragma unroll 8
        for (int nn = 0; nn < 64; nn++){
            float cv[4], bv[4];
            #pragma unroll
            for (int i = 0; i < 4; i++) cv[i] = bufA[ty*4+i][nn];
            #pragma unroll
            for (int j = 0; j < 4; j++) bv[j] = bufB[tx*4+j][nn];
            #pragma unroll
            for (int i = 0; i < 4; i++)
                #pragma unroll
                for (int j = 0; j < 4; j++)
                    G[i][j] = fmaf(cv[i], bv[j], G[i][j]);
        }
        __syncthreads();
    }

    for (int hh = 0; hh < NHD; hh++){
        __syncthreads();
        if (tid < 64) acsS[tid] = g_acs[((b*8+hh)*32 + c)*64 + tid];
        for (int i = tid; i < 4096; i += 256){
            int s = i >> 6, p = i & 63;
            int t = t0 + s;
            bufB[s][p] = g_xbc[(size_t)t*CONV_DIM + hh*64 + p] * g_dt[t*NHD + hh];
        }
        __syncthreads();
        #pragma unroll
        for (int i = 0; i < 4; i++){
            int l = ty*4 + i;
            #pragma unroll
            for (int j = 0; j < 4; j++){
                int s = tx*4 + j;
                bufA[l][s] = (s <= l) ? G[i][j]*__expf(acsS[l]-acsS[s]) : 0.f;
            }
        }
        __syncthreads();
        float y[4][4] = {};
        #pragma unroll 4
        for (int s = 0; s < 64; s++){
            float xv[4], wv[4];
            #pragma unroll
            for (int j = 0; j < 4; j++) xv[j] = bufB[s][tx*4+j];
            #pragma unroll
            for (int i = 0; i < 4; i++) wv[i] = bufA[ty*4+i][s];
            #pragma unroll
            for (int i = 0; i < 4; i++)
                #pragma unroll
                for (int j = 0; j < 4; j++)
                    y[i][j] = fmaf(wv[i], xv[j], y[i][j]);
        }
        #pragma unroll
        for (int i = 0; i < 4; i++)
            #pragma unroll
            for (int j = 0; j < 4; j++)
                g_y[(size_t)(t0 + ty*4 + i)*D_INNER + hh*64 + tx*4 + j] = y[i][j];
    }
}

// ---------------- inter-chunk scan: fp32 states -> bf16 hi/lo prev-states ----------------
// finer split: grid (B_*NHD, 16), 4 carried elements/thread
__global__ void k_scan(){
    int bh = blockIdx.x;
    int h = bh & 7, b = bh >> 3;
    int base = blockIdx.y*1024 + threadIdx.x;
    float S[4] = {};
    for (int c = 0; c < 32; c++){
        float dec = __expf(g_acs[((b*8+h)*32 + c)*64 + 63]);
        size_t off = ((size_t)(b*32 + c)*8 + h)*16384 + base;
        const float* ptr = g_states + off;
        __nv_bfloat16* ph = g_sph + off;
        __nv_bfloat16* pl = g_spl + off;
        #pragma unroll
        for (int e = 0; e < 4; e++){
            float tmp = ptr[e*256];
            __nv_bfloat16 hi, lo;
            bf16_split(S[e], hi, lo);
            ph[e*256] = hi;
            pl[e*256] = lo;
            S[e] = fmaf(S[e], dec, tmp);
        }
    }
}

// ---------------- gated rmsnorm + bf16 split ----------------
__global__ void k_gatenorm_split(const float* __restrict__ gw,
                                 __nv_bfloat16* __restrict__ oh, __nv_bfloat16* __restrict__ ol){
    int t = blockIdx.x;
    __shared__ float red[8];
    float v[2];
    float ss = 0.f;
    #pragma unroll
    for (int i = 0; i < 2; i++){
        int d = threadIdx.x + i*256;
        float z = g_zx[(size_t)t*D_PROJ + d];
        float val = g_y[(size_t)t*D_INNER + d] * (z / (1.f + __expf(-z)));
        v[i] = val;
        ss += val*val;
    }
    #pragma unroll
    for (int o = 16; o; o >>= 1) ss += __shfl_xor_sync(0xffffffffu, ss, o);
    if ((threadIdx.x & 31) == 0) red[threadIdx.x >> 5] = ss;
    __syncthreads();
    if (threadIdx.x < 32){
        float s2 = (threadIdx.x < 8) ? red[threadIdx.x] : 0.f;
        #pragma unroll
        for (int o = 4; o; o >>= 1) s2 += __shfl_xor_sync(0xffffffffu, s2, o);
        if (threadIdx.x == 0) red[0] = s2;
    }
    __syncthreads();
    float scale = rsqrtf(red[0]/512.f + 1e-5f);
    #pragma unroll
    for (int i = 0; i < 2; i++){
        int d = threadIdx.x + i*256;
        float val = v[i]*scale*gw[d];
        __nv_bfloat16 hi, lo;
        bf16_split(val, hi, lo);
        oh[(size_t)t*D_INNER + d] = hi;
        ol[(size_t)t*D_INNER + d] = lo;
    }
}

// ---------------- launch ----------------
extern "C" void kernel_launch(void* const* d_in, const int* in_sizes, int n_in,
                              void* d_out, int out_size){
    const float* x       = (const float*)d_in[0];
    const float* emb     = (const float*)d_in[1];
    const float* in_proj = (const float*)d_in[2];
    const float* conv_w  = (const float*)d_in[3];
    const float* conv_b  = (const float*)d_in[4];
    const float* dt_bias = (const float*)d_in[5];
    const float* A_log   = (const float*)d_in[6];
    const float* Dv      = (const float*)d_in[7];
    const float* gnorm   = (const float*)d_in[8];
    const float* outp_w  = (const float*)d_in[9];
    const float* norm_w  = (const float*)d_in[10];
    const float* normf   = (const float*)d_in[11];
    const float* head_w  = (const float*)d_in[12];

    void *p_h, *p_ah, *p_al, *p_wh, *p_wl, *p_zx;
    cudaGetSymbolAddress(&p_h,  g_h);
    cudaGetSymbolAddress(&p_ah, g_ah);
    cudaGetSymbolAddress(&p_al, g_al);
    cudaGetSymbolAddress(&p_wh, g_wth);
    cudaGetSymbolAddress(&p_wl, g_wtl);
    cudaGetSymbolAddress(&p_zx, g_zx);
    float* gh  = (float*)p_h;
    float* gzx = (float*)p_zx;
    __nv_bfloat16* ah = (__nv_bfloat16*)p_ah;
    __nv_bfloat16* al = (__nv_bfloat16*)p_al;
    __nv_bfloat16* wh = (__nv_bfloat16*)p_wh;
    __nv_bfloat16* wl = (__nv_bfloat16*)p_wl;

    cudaFuncSetAttribute(k_mma_gemm2,  cudaFuncAttributeMaxDynamicSharedMemorySize, SM2_BYTES);
    cudaFuncSetAttribute(k_mma_gemm,   cudaFuncAttributeMaxDynamicSharedMemorySize, SM1_BYTES);
    cudaFuncSetAttribute(k_states_mma, cudaFuncAttributeMaxDynamicSharedMemorySize, ST_BYTES);
    cudaFuncSetAttribute(k_yoff_mma,   cudaFuncAttributeMaxDynamicSharedMemorySize, YO_BYTES);
    cudaFuncSetAttribute(k_conv2,      cudaFuncAttributeMaxDynamicSharedMemorySize, CV_BYTES);

    k_embed<<<NTOK, 256>>>(x, emb);

    for (int i = 0; i < 2; i++){
        k_rmsnorm_split<256><<<NTOK, 256>>>(gh, norm_w + i*EMB, ah, al);
        k_wsplit_t<<<dim3((D_PROJ+31)/32, EMB/32), dim3(32,8)>>>(
            in_proj + (size_t)i*EMB*D_PROJ, wh, wl, EMB, D_PROJ);
        k_mma_gemm2<<<dim3((D_PROJ+255)/256, NTOK/128), 256, SM2_BYTES>>>(
            ah, al, wh, wl, gzx, NTOK, D_PROJ, EMB, nullptr);
        k_conv2<<<dim3(NTOK/64, CONV_DIM/256), 256, CV_BYTES>>>(
            conv_w + i*CONV_DIM*4, conv_b + i*CONV_DIM);
        k_cumsum<<<B_*NHD*NCHUNK, 64>>>(A_log + i*NHD, dt_bias + i*NHD);
        k_transpose<<<dim3(24, 64, 4), dim3(32,8)>>>();
        k_ydiag<<<B_*NCHUNK, 256>>>();
        k_states_mma<<<B_*NCHUNK, 256, ST_BYTES>>>();
        k_scan<<<dim3(B_*NHD, 16), 256>>>();
        k_yoff_mma<<<B_*NCHUNK, 256, YO_BYTES>>>(Dv + i*NHD);
        k_gatenorm_split<<<NTOK, 256>>>(gnorm + i*D_INNER, ah, al);
        k_wsplit_t<<<dim3(EMB/32, D_INNER/32), dim3(32,8)>>>(
            outp_w + (size_t)i*D_INNER*EMB, wh, wl, D_INNER, EMB);
        k_mma_gemm<<<dim3(EMB/128, NTOK/128), 256, SM1_BYTES>>>(
            ah, al, wh, wl, gh, NTOK, EMB, D_INNER, gh);
    }

    k_rmsnorm_split<256><<<NTOK, 256>>>(gh, normf, ah, al);
    k_wsplit_t<<<dim3(EMB/32, EMB/32), dim3(32,8)>>>(head_w, wh, wl, EMB, EMB);
    k_mma_gemm<<<dim3(EMB/128, NTOK/128), 256, SM1_BYTES>>>(
        ah, al, wh, wl, (float*)d_out, NTOK, EMB, EMB, nullptr);
}

// round 15
// speedup vs baseline: 1.0346x; 1.0141x over previous
#include <cuda_runtime.h>
#include <cuda_bf16.h>
#include <cstdint>
#include <math.h>

// ---------------- problem constants ----------------
#define B_      4
#define L_      2048
#define EMB     256
#define NHD     8
#define CHK     64
#define NCHUNK  (L_/CHK)          // 32
#define D_INNER 512
#define D_STATE 256
#define CONV_DIM 1024
#define D_PROJ  1544
#define NTOK    (B_*L_)           // 8192

#if defined(__CUDA_ARCH_FEAT_SM103_ALL) || defined(__CUDA_ARCH_FEAT_SM100_ALL) || \
    defined(__CUDA_ARCH_SPECIFIC__) || defined(__CUDA_ARCH_FAMILY_SPECIFIC__)
#define HAS_TCGEN05 1
#else
#define HAS_TCGEN05 0
#endif

// ---------------- scratch (device globals, no allocation) ----------------
__device__ float g_h  [NTOK*EMB];
__device__ float g_zx [NTOK*D_PROJ];
__device__ float g_xbc[NTOK*CONV_DIM];
__device__ float g_dt [NTOK*NHD];
__device__ float g_acs[B_*NHD*NCHUNK*CHK];
__device__ float g_states[(size_t)B_*NCHUNK*NHD*64*256];   // chunk states fp32
__device__ float g_y  [NTOK*D_INNER];
__device__ __nv_bfloat16 g_ah[NTOK*512];
__device__ __nv_bfloat16 g_al[NTOK*512];
__device__ __nv_bfloat16 g_wth[1544*256];
__device__ __nv_bfloat16 g_wtl[1544*256];
__device__ float g_xbt[(size_t)B_*768*L_];
__device__ __nv_bfloat16 g_sph[(size_t)B_*NCHUNK*512*256];
__device__ __nv_bfloat16 g_spl[(size_t)B_*NCHUNK*512*256];

__device__ __forceinline__ void bf16_split(float x, __nv_bfloat16& hi, __nv_bfloat16& lo){
    hi = __float2bfloat16_rn(x);
    lo = __float2bfloat16_rn(x - __bfloat162float(hi));
}

// GEMM v2 (in_proj) smem
#define GM_STAGE0  1024
#define GM_STAGE   98304
#define GM_AH      0
#define GM_AL      16384
#define GM_BH      32768
#define GM_BL      65536
#define SM2_BYTES  197632
// GEMM v1 (out_proj/head) smem: double-buffered, K-chunk 64
#define S1_STAGE0  1024
#define S1_STAGE   65536
#define S1_AH      0
#define S1_AL      16384
#define S1_BH      32768
#define S1_BL      49152
#define SM1_BYTES  132096
// states kernel smem
#define ST_BH      1024
#define ST_BL      33792
#define ST_AH      66560
#define ST_AL      82944
#define ST_BYTES   100352
// yoff kernel smem
#define YO_CH      1024
#define YO_CL      33792
#define YO_AH      66560
#define YO_AL      132096
#define YO_BYTES   197632
// conv smem: (64+3) x 256 fp32
#define CV_BYTES   (67*256*4)

#if HAS_TCGEN05
// ================= tcgen05 helpers =================
__device__ __forceinline__ uint32_t smem_u32(const void* p){
    uint32_t a;
    asm("{ .reg .u64 t; cvta.to.shared.u64 t, %1; cvt.u32.u64 %0, t; }" : "=r"(a) : "l"(p));
    return a;
}
__device__ __forceinline__ uint32_t elect_one(){
    uint32_t p;
    asm volatile("{ .reg .pred p; elect.sync _|p, 0xFFFFFFFF; selp.b32 %0, 1, 0, p; }" : "=r"(p));
    return p;
}
#define TC_ALLOC(sm, n)  asm volatile("tcgen05.alloc.cta_group::1.sync.aligned.shared::cta.b32 [%0], %1;" :: "r"(sm), "r"(n) : "memory")
#define TC_DEALLOC(t, n) asm volatile("tcgen05.dealloc.cta_group::1.sync.aligned.b32 %0, %1;" :: "r"(t), "r"(n))
#define TC_RELINQ()      asm volatile("tcgen05.relinquish_alloc_permit.cta_group::1.sync.aligned;")
#define TC_COMMIT(mb)    asm volatile("tcgen05.commit.cta_group::1.mbarrier::arrive::one.shared::cluster.b64 [%0];" :: "r"(mb) : "memory")
#define TC_FENCE_AFTER() asm volatile("tcgen05.fence::after_thread_sync;" ::: "memory")
#define TC_FENCE_BEFORE() asm volatile("tcgen05.fence::before_thread_sync;" ::: "memory")
#define TC_WAIT_LD()     asm volatile("tcgen05.wait::ld.sync.aligned;" ::: "memory")
#define MBAR_INIT(mb, c) asm volatile("mbarrier.init.shared.b64 [%0], %1;" :: "r"(mb), "r"(c) : "memory")
#define MBAR_WAIT(mb, ph) do { \
    uint32_t _m = (mb), _p = (ph), _d; \
    asm volatile("{ .reg .pred p; mbarrier.try_wait.parity.acquire.cta.shared::cta.b64 p, [%1], %2; selp.b32 %0, 1, 0, p; }" \
        : "=r"(_d) : "r"(_m), "r"(_p) : "memory"); \
    if (!_d) { \
        asm volatile("{ .reg .pred P1; WL_%=: mbarrier.try_wait.parity.acquire.cta.shared::cta.b64 P1, [%0], %1, 0x989680; @P1 bra.uni WD_%=; bra.uni WL_%=; WD_%=: }" \
            :: "r"(_m), "r"(_p) : "memory"); \
    } } while(0)
#define TC_LD_X32(r, ta) \
    asm volatile("tcgen05.ld.sync.aligned.32x32b.x32.b32 " \
        "{%0,%1,%2,%3,%4,%5,%6,%7,%8,%9,%10,%11,%12,%13,%14,%15," \
        "%16,%17,%18,%19,%20,%21,%22,%23,%24,%25,%26,%27,%28,%29,%30,%31}, [%32];" \
        : "=r"((r)[0]),"=r"((r)[1]),"=r"((r)[2]),"=r"((r)[3]),"=r"((r)[4]),"=r"((r)[5]),"=r"((r)[6]),"=r"((r)[7]), \
          "=r"((r)[8]),"=r"((r)[9]),"=r"((r)[10]),"=r"((r)[11]),"=r"((r)[12]),"=r"((r)[13]),"=r"((r)[14]),"=r"((r)[15]), \
          "=r"((r)[16]),"=r"((r)[17]),"=r"((r)[18]),"=r"((r)[19]),"=r"((r)[20]),"=r"((r)[21]),"=r"((r)[22]),"=r"((r)[23]), \
          "=r"((r)[24]),"=r"((r)[25]),"=r"((r)[26]),"=r"((r)[27]),"=r"((r)[28]),"=r"((r)[29]),"=r"((r)[30]),"=r"((r)[31]) \
        : "r"(ta))

static __device__ __forceinline__ uint64_t make_desc_sw128(uint32_t addr){
    const uint64_t base =
        (uint64_t(2)  << 61) | (uint64_t(1) << 46) | (uint64_t(64) << 32) | (uint64_t(1) << 16);
    return base | ((uint64_t)(addr >> 4) & 0x3FFF);
}
__device__ __forceinline__ void mma_bf16_ss(uint32_t d, uint64_t ad, uint64_t bd,
                                            uint32_t idesc, bool acc){
    uint32_t en = acc ? 1u : 0u;
    asm volatile(
        "{\n\t"
        ".reg .pred p;\n\t"
        "setp.ne.u32 p, %5, 0;\n\t"
        "tcgen05.mma.cta_group::1.kind::f16 [%0], %1, %2, %3, {%4, %4, %4, %4}, p;\n\t"
        "}"
        :: "r"(d), "l"(ad), "l"(bd), "r"(idesc), "r"(0u), "r"(en)
        : "memory");
}
#define SWZ(o) ((o) ^ (((o) >> 3) & 0x70))
#define IDESC_N128 ((1u<<4) | (1u<<7) | (1u<<10) | ((128u/8u)<<17) | ((128u/16u)<<24))
#define IDESC_N64  ((1u<<4) | (1u<<7) | (1u<<10) | (( 64u/8u)<<17) | ((128u/16u)<<24))
#endif // HAS_TCGEN05

// ---------------- GEMM v2 (in_proj): 128x256 tile, K chunks of 64, double-buffered ----------------
__global__ void __launch_bounds__(256)
k_mma_gemm2(const __nv_bfloat16* __restrict__ Ah, const __nv_bfloat16* __restrict__ Al,
            const __nv_bfloat16* __restrict__ Bh, const __nv_bfloat16* __restrict__ Bl,
            float* __restrict__ C, int M, int N, int K,
            const float* __restrict__ resid){
    extern __shared__ char smem[];
    int tid = threadIdx.x;
    int bm = blockIdx.y * 128, bn = blockIdx.x * 256;

#if HAS_TCGEN05
    uint32_t sbase = smem_u32(smem);
    int wid = tid >> 5, lid = tid & 31;
    if (wid == 0) TC_ALLOC(sbase, 256);
    if (tid == 0){ MBAR_INIT(sbase + 8, 1); MBAR_INIT(sbase + 16, 1); }
    __syncthreads();
    uint32_t tmem;
    asm volatile("ld.shared.b32 %0, [%1];" : "=r"(tmem) : "r"(sbase));

    int nc = K >> 6;
    int ph0 = 0, ph1 = 0;
    for (int c = 0; c < nc; c++){
        int buf = c & 1;
        uint32_t sb = sbase + GM_STAGE0 + buf*GM_STAGE;
        char* smb = smem + GM_STAGE0 + buf*GM_STAGE;
        int kc = c << 6;
        if (c >= 2){
            if (buf == 0){ MBAR_WAIT(sbase + 8,  ph0); ph0 ^= 1; }
            else         { MBAR_WAIT(sbase + 16, ph1); ph1 ^= 1; }
        }
        #pragma unroll
        for (int it = 0; it < 4; it++){
            int v = tid + it*256;
            int m = v >> 3, u = v & 7;
            uint32_t so = SWZ((uint32_t)(m*128 + u*16));
            size_t gi = (size_t)(bm+m)*K + kc + u*8;
            *(uint4*)(smb + GM_AH + so) = *(const uint4*)&Ah[gi];
            *(uint4*)(smb + GM_AL + so) = *(const uint4*)&Al[gi];
        }
        #pragma unroll
        for (int it = 0; it < 8; it++){
            int v = tid + it*256;
            int n = v >> 3, u = v & 7;
            uint32_t so = SWZ((uint32_t)(n*128 + u*16));
            uint4 vh = make_uint4(0,0,0,0), vl = make_uint4(0,0,0,0);
            if (bn + n < N){
                size_t gi = (size_t)(bn+n)*K + kc + u*8;
                vh = *(const uint4*)&Bh[gi];
                vl = *(const uint4*)&Bl[gi];
            }
            *(uint4*)(smb + GM_BH + so) = vh;
            *(uint4*)(smb + GM_BL + so) = vl;
        }
        __syncthreads();
        asm volatile("fence.proxy.async.shared::cta;" ::: "memory");

        if (wid == 0 && elect_one()){
            uint64_t ah = make_desc_sw128(sb + GM_AH);
            uint64_t al = make_desc_sw128(sb + GM_AL);
            #pragma unroll
            for (int half = 0; half < 2; half++){
                uint64_t bh = make_desc_sw128(sb + GM_BH + half*16384);
                uint64_t bl = make_desc_sw128(sb + GM_BL + half*16384);
                uint32_t dt_ = tmem + half*128;
                #pragma unroll
                for (int s = 0; s < 4; s++){
                    bool acc = !(c == 0 && s == 0);
                    mma_bf16_ss(dt_, ah + s*2, bh + s*2, IDESC_N128, acc);
                    mma_bf16_ss(dt_, ah + s*2, bl + s*2, IDESC_N128, true);
                    mma_bf16_ss(dt_, al + s*2, bh + s*2, IDESC_N128, true);
                }
            }
            TC_COMMIT(sbase + 8 + buf*8);
        }
        __syncthreads();
    }
    {
        int lb = (nc-1) & 1;
        if (lb == 0) MBAR_WAIT(sbase + 8,  ph0);
        else         MBAR_WAIT(sbase + 16, ph1);
    }

    TC_FENCE_AFTER();
    float* eb = (float*)(smem + GM_STAGE0);
    for (int g = 0; g < 8; g++){
        if (wid < 4){
            uint32_t r[32];
            TC_LD_X32(r, tmem + g*32);
            TC_WAIT_LD();
            int m = wid*32 + lid;
            #pragma unroll
            for (int j = 0; j < 32; j++)
                eb[m*33 + j] = __uint_as_float(r[j]);
        }
        __syncthreads();
        #pragma unroll
        for (int it = 0; it < 16; it++){
            int v = tid + it*256;
            int m = v >> 5, j = v & 31;
            int n = bn + g*32 + j;
            if (n < N){
                size_t idx = (size_t)(bm+m)*N + n;
                float val = eb[m*33 + j];
                if (resid) val += resid[idx];
                C[idx] = val;
            }
        }
        __syncthreads();
    }
    if (wid == 0){
        TC_RELINQ();
        TC_DEALLOC(tmem, 256);
    }
#else
    float (*As)[132] = (float(*)[132])(smem);
    float (*Ws)[132] = (float(*)[132])(smem + 16*132*4);
    int tx = tid & 15, ty = tid >> 4;
    for (int half = 0; half < 2; half++){
        int bn2 = bn + half*128;
        float acc[8][8] = {};
        for (int k0 = 0; k0 < K; k0 += 16){
            #pragma unroll
            for (int r = 0; r < 8; r++){
                int i = tid + r*256;
                int m = i >> 4, k = i & 15;
                size_t gi = (size_t)(bm+m)*K + k0 + k;
                As[k][m] = __bfloat162float(Ah[gi]) + __bfloat162float(Al[gi]);
            }
            #pragma unroll
            for (int r = 0; r < 8; r++){
                int i = tid + r*256;
                int k = i >> 7, n = i & 127;
                float w = 0.f;
                if (bn2+n < N){
                    size_t gi = (size_t)(bn2+n)*K + k0 + k;
                    w = __bfloat162float(Bh[gi]) + __bfloat162float(Bl[gi]);
                }
                Ws[k][n] = w;
            }
            __syncthreads();
            #pragma unroll
            for (int kk = 0; kk < 16; kk++){
                float a[8], b[8];
                #pragma unroll
                for (int i = 0; i < 8; i++) a[i] = As[kk][ty*8+i];
                #pragma unroll
                for (int j = 0; j < 8; j++) b[j] = Ws[kk][tx*8+j];
                #pragma unroll
                for (int i = 0; i < 8; i++)
                    #pragma unroll
                    for (int j = 0; j < 8; j++)
                        acc[i][j] = fmaf(a[i], b[j], acc[i][j]);
            }
            __syncthreads();
        }
        #pragma unroll
        for (int i = 0; i < 8; i++){
            int m = bm + ty*8 + i;
            #pragma unroll
            for (int j = 0; j < 8; j++){
                int n = bn2 + tx*8 + j;
                if (n < N){
                    size_t idx = (size_t)m*N + n;
                    float v = acc[i][j];
                    if (resid) v += resid[idx];
                    C[idx] = v;
                }
            }
        }
        __syncthreads();
    }
#endif
}

// ---------------- GEMM v1 (out_proj/head): 128x128 tile, K chunks of 64, double-buffered ----------------
__global__ void __launch_bounds__(256)
k_mma_gemm(const __nv_bfloat16* __restrict__ Ah, const __nv_bfloat16* __restrict__ Al,
           const __nv_bfloat16* __restrict__ Bh, const __nv_bfloat16* __restrict__ Bl,
           float* __restrict__ C, int M, int N, int K,
           const float* __restrict__ resid){
    extern __shared__ char smem[];
    int tid = threadIdx.x;
    int bm = blockIdx.y * 128, bn = blockIdx.x * 128;

#if HAS_TCGEN05
    uint32_t sbase = smem_u32(smem);
    int wid = tid >> 5, lid = tid & 31;
    if (wid == 0) TC_ALLOC(sbase, 128);
    if (tid == 0){ MBAR_INIT(sbase + 8, 1); MBAR_INIT(sbase + 16, 1); }
    __syncthreads();
    uint32_t tmem;
    asm volatile("ld.shared.b32 %0, [%1];" : "=r"(tmem) : "r"(sbase));

    int nc = K >> 6;
    int ph0 = 0, ph1 = 0;
    for (int c = 0; c < nc; c++){
        int buf = c & 1;
        uint32_t sb = sbase + S1_STAGE0 + buf*S1_STAGE;
        char* smb = smem + S1_STAGE0 + buf*S1_STAGE;
        int kc = c << 6;
        if (c >= 2){
            if (buf == 0){ MBAR_WAIT(sbase + 8,  ph0); ph0 ^= 1; }
            else         { MBAR_WAIT(sbase + 16, ph1); ph1 ^= 1; }
        }
        #pragma unroll
        for (int it = 0; it < 4; it++){
            int v = tid + it*256;
            int m = v >> 3, u = v & 7;
            uint32_t so = SWZ((uint32_t)(m*128 + u*16));
            size_t gi = (size_t)(bm+m)*K + kc + u*8;
            *(uint4*)(smb + S1_AH + so) = *(const uint4*)&Ah[gi];
            *(uint4*)(smb + S1_AL + so) = *(const uint4*)&Al[gi];
        }
        #pragma unroll
        for (int it = 0; it < 4; it++){
            int v = tid + it*256;
            int n = v >> 3, u = v & 7;
            uint32_t so = SWZ((uint32_t)(n*128 + u*16));
            uint4 vh = make_uint4(0,0,0,0), vl = make_uint4(0,0,0,0);
            if (bn + n < N){
                size_t gi = (size_t)(bn+n)*K + kc + u*8;
                vh = *(const uint4*)&Bh[gi];
                vl = *(const uint4*)&Bl[gi];
            }
            *(uint4*)(smb + S1_BH + so) = vh;
            *(uint4*)(smb + S1_BL + so) = vl;
        }
        __syncthreads();
        asm volatile("fence.proxy.async.shared::cta;" ::: "memory");

        if (wid == 0 && elect_one()){
            uint64_t ah = make_desc_sw128(sb + S1_AH);
            uint64_t al = make_desc_sw128(sb + S1_AL);
            uint64_t bh = make_desc_sw128(sb + S1_BH);
            uint64_t bl = make_desc_sw128(sb + S1_BL);
            #pragma unroll
            for (int s = 0; s < 4; s++){
                bool acc = !(c == 0 && s == 0);
                mma_bf16_ss(tmem, ah + s*2, bh + s*2, IDESC_N128, acc);
                mma_bf16_ss(tmem, ah + s*2, bl + s*2, IDESC_N128, true);
                mma_bf16_ss(tmem, al + s*2, bh + s*2, IDESC_N128, true);
            }
            TC_COMMIT(sbase + 8 + buf*8);
        }
        __syncthreads();
    }
    {
        int lb = (nc-1) & 1;
        if (lb == 0) MBAR_WAIT(sbase + 8,  ph0);
        else         MBAR_WAIT(sbase + 16, ph1);
    }

    TC_FENCE_AFTER();
    float* eb = (float*)(smem + S1_STAGE0);
    for (int g = 0; g < 4; g++){
        if (wid < 4){
            uint32_t r[32];
            TC_LD_X32(r, tmem + g*32);
            TC_WAIT_LD();
            int m = wid*32 + lid;
            #pragma unroll
            for (int j = 0; j < 32; j++)
                eb[m*33 + j] = __uint_as_float(r[j]);
        }
        __syncthreads();
        #pragma unroll
        for (int it = 0; it < 16; it++){
            int v = tid + it*256;
            int m = v >> 5, j = v & 31;
            int n = bn + g*32 + j;
            if (n < N){
                size_t idx = (size_t)(bm+m)*N + n;
                float val = eb[m*33 + j];
                if (resid) val += resid[idx];
                C[idx] = val;
            }
        }
        __syncthreads();
    }
    if (wid == 0){
        TC_RELINQ();
        TC_DEALLOC(tmem, 128);
    }
#else
    float (*As)[132] = (float(*)[132])(smem);
    float (*Ws)[132] = (float(*)[132])(smem + 16*132*4);
    int tx = tid & 15, ty = tid >> 4;
    float acc[8][8] = {};
    for (int k0 = 0; k0 < K; k0 += 16){
        #pragma unroll
        for (int r = 0; r < 8; r++){
            int i = tid + r*256;
            int m = i >> 4, k = i & 15;
            size_t gi = (size_t)(bm+m)*K + k0 + k;
            As[k][m] = __bfloat162float(Ah[gi]) + __bfloat162float(Al[gi]);
        }
        #pragma unroll
        for (int r = 0; r < 8; r++){
            int i = tid + r*256;
            int k = i >> 7, n = i & 127;
            float w = 0.f;
            if (bn+n < N){
                size_t gi = (size_t)(bn+n)*K + k0 + k;
                w = __bfloat162float(Bh[gi]) + __bfloat162float(Bl[gi]);
            }
            Ws[k][n] = w;
        }
        __syncthreads();
        #pragma unroll
        for (int kk = 0; kk < 16; kk++){
            float a[8], b[8];
            #pragma unroll
            for (int i = 0; i < 8; i++) a[i] = As[kk][ty*8+i];
            #pragma unroll
            for (int j = 0; j < 8; j++) b[j] = Ws[kk][tx*8+j];
            #pragma unroll
            for (int i = 0; i < 8; i++)
                #pragma unroll
                for (int j = 0; j < 8; j++)
                    acc[i][j] = fmaf(a[i], b[j], acc[i][j]);
        }
        __syncthreads();
    }
    #pragma unroll
    for (int i = 0; i < 8; i++){
        int m = bm + ty*8 + i;
        #pragma unroll
        for (int j = 0; j < 8; j++){
            int n = bn + tx*8 + j;
            if (n < N){
                size_t idx = (size_t)m*N + n;
                float v = acc[i][j];
                if (resid) v += resid[idx];
                C[idx] = v;
            }
        }
    }
#endif
}

// ---------------- states: S[hp,n] = sum_l xdts[l,hp]*B[l,n]  (tcgen05, fp32 out) ----------------
__global__ void __launch_bounds__(256)
k_states_mma(){
    extern __shared__ char smem[];
    int tid = threadIdx.x;
    int bc = blockIdx.x;
    int c = bc & 31, b = bc >> 5;
    int t0 = b*L_ + c*64;
#if HAS_TCGEN05
    uint32_t sbase = smem_u32(smem);
    int wid = tid >> 5, lid = tid & 31;
    float* sc = (float*)(smem + 128);
    if (wid == 0) TC_ALLOC(sbase, 128);
    if (tid == 0) MBAR_INIT(sbase + 8, 1);
    __syncthreads();
    uint32_t tmem;
    asm volatile("ld.shared.b32 %0, [%1];" : "=r"(tmem) : "r"(sbase));

    #pragma unroll
    for (int it = 0; it < 16; it++){
        int v = tid + it*256;
        int n = v >> 4, u = v & 15;
        const float* src = g_xbt + ((size_t)b*768 + 512 + n)*L_ + c*64 + u*4;
        float4 a = *(const float4*)src;
        __nv_bfloat16 h0,l0,h1,l1,h2,l2,h3,l3;
        bf16_split(a.x,h0,l0); bf16_split(a.y,h1,l1);
        bf16_split(a.z,h2,l2); bf16_split(a.w,h3,l3);
        __nv_bfloat162 hp2 = __halves2bfloat162(h0,h1), hq2 = __halves2bfloat162(h2,h3);
        __nv_bfloat162 lp2 = __halves2bfloat162(l0,l1), lq2 = __halves2bfloat162(l2,l3);
        int nt = n >> 7, r = n & 127;
        uint32_t so = nt*16384 + SWZ((uint32_t)(r*128 + u*8));
        *(uint2*)(smem + ST_BH + so) = make_uint2(*(uint32_t*)&hp2, *(uint32_t*)&hq2);
        *(uint2*)(smem + ST_BL + so) = make_uint2(*(uint32_t*)&lp2, *(uint32_t*)&lq2);
    }

    int phase = 0;
    for (int ht = 0; ht < 4; ht++){
        __syncthreads();
        if (tid < 128){
            int hl = tid >> 6, l = tid & 63;
            int h = ht*2 + hl;
            const float* ap = g_acs + ((size_t)(b*8+h)*32 + c)*64;
            sc[hl*64 + l] = g_dt[(size_t)(t0+l)*NHD + h] * __expf(ap[63] - ap[l]);
        }
        __syncthreads();
        #pragma unroll
        for (int it = 0; it < 8; it++){
            int v = tid + it*256;
            int r = v >> 4, u = v & 15;
            const float* src = g_xbt + ((size_t)b*768 + ht*128 + r)*L_ + c*64 + u*4;
            float4 a = *(const float4*)src;
            const float* s4 = sc + (r >> 6)*64 + u*4;
            a.x *= s4[0]; a.y *= s4[1]; a.z *= s4[2]; a.w *= s4[3];
            __nv_bfloat16 h0,l0,h1,l1,h2,l2,h3,l3;
            bf16_split(a.x,h0,l0); bf16_split(a.y,h1,l1);
            bf16_split(a.z,h2,l2); bf16_split(a.w,h3,l3);
            __nv_bfloat162 hp2 = __halves2bfloat162(h0,h1), hq2 = __halves2bfloat162(h2,h3);
            __nv_bfloat162 lp2 = __halves2bfloat162(l0,l1), lq2 = __halves2bfloat162(l2,l3);
            uint32_t so = SWZ((uint32_t)(r*128 + u*8));
            *(uint2*)(smem + ST_AH + so) = make_uint2(*(uint32_t*)&hp2, *(uint32_t*)&hq2);
            *(uint2*)(smem + ST_AL + so) = make_uint2(*(uint32_t*)&lp2, *(uint32_t*)&lq2);
        }
        __syncthreads();
        asm volatile("fence.proxy.async.shared::cta;" ::: "memory");

        for (int nt = 0; nt < 2; nt++){
            if (wid == 0 && elect_one()){
                uint64_t ah = make_desc_sw128(sbase + ST_AH);
                uint64_t al = make_desc_sw128(sbase + ST_AL);
                uint64_t bh = make_desc_sw128(sbase + ST_BH + nt*16384);
                uint64_t bl = make_desc_sw128(sbase + ST_BL + nt*16384);
                bool first = true;
                #pragma unroll
                for (int s = 0; s < 4; s++){
                    mma_bf16_ss(tmem, ah + s*2, bh + s*2, IDESC_N128, !first);
                    first = false;
                    mma_bf16_ss(tmem, ah + s*2, bl + s*2, IDESC_N128, true);
                    mma_bf16_ss(tmem, al + s*2, bh + s*2, IDESC_N128, true);
                }
                TC_COMMIT(sbase + 8);
            }
            MBAR_WAIT(sbase + 8, phase);
            phase ^= 1;
            TC_FENCE_AFTER();
            if (wid < 4){
                int hp = ht*128 + wid*32 + lid;
                float* out = g_states + ((size_t)bc*512 + hp)*256 + nt*128;
                #pragma unroll
                for (int g = 0; g < 4; g++){
                    uint32_t r[32];
                    TC_LD_X32(r, tmem + g*32);
                    TC_WAIT_LD();
                    #pragma unroll
                    for (int j = 0; j < 32; j += 4){
                        float4 v4 = make_float4(__uint_as_float(r[j]),   __uint_as_float(r[j+1]),
                                                __uint_as_float(r[j+2]), __uint_as_float(r[j+3]));
                        *(float4*)(out + g*32 + j) = v4;
                    }
                }
                TC_FENCE_BEFORE();
            }
            __syncthreads();
        }
    }
    if (wid == 0){
        TC_RELINQ();
        TC_DEALLOC(tmem, 128);
    }
#else
    __shared__ float sc8[8][64];
    for (int v = tid; v < 512; v += 256){
        int h = v >> 6, l = v & 63;
        const float* ap = g_acs + ((size_t)(b*8+h)*32 + c)*64;
        sc8[h][l] = g_dt[(size_t)(t0+l)*NHD + h] * __expf(ap[63] - ap[l]);
    }
    __syncthreads();
    for (int h = 0; h < 8; h++)
        for (int idx = tid; idx < 16384; idx += 256){
            int p = idx >> 8, n = idx & 255;
            float s = 0.f;
            for (int l = 0; l < 64; l++)
                s += g_xbc[(size_t)(t0+l)*CONV_DIM + h*64 + p] * sc8[h][l]
                   * g_xbc[(size_t)(t0+l)*CONV_DIM + 512 + n];
            g_states[((size_t)bc*512 + h*64 + p)*256 + n] = s;
        }
#endif
}

// ---------------- yoff ----------------
__global__ void __launch_bounds__(256)
k_yoff_mma(const float* __restrict__ Dvec){
    extern __shared__ char smem[];
    int tid = threadIdx.x;
    int bc = blockIdx.x;
    int c = bc & 31, b = bc >> 5;
    int t0 = b*L_ + c*64;
#if HAS_TCGEN05
    uint32_t sbase = smem_u32(smem);
    int wid = tid >> 5, lid = tid & 31;
    float* ex = (float*)(smem + 128);
    if (wid == 0) TC_ALLOC(sbase, 64);
    if (tid == 0) MBAR_INIT(sbase + 8, 1);
    __syncthreads();
    uint32_t tmem;
    asm volatile("ld.shared.b32 %0, [%1];" : "=r"(tmem) : "r"(sbase));

    #pragma unroll
    for (int it = 0; it < 8; it++){
        int v = tid + it*256;
        int l = v >> 5, q = v & 31;
        const float* src = &g_xbc[(size_t)(t0+l)*CONV_DIM + 768 + q*8];
        float4 a = *(const float4*)src;
        float4 bq = *(const float4*)(src + 4);
        __nv_bfloat16 h0,l0,h1,l1,h2,l2,h3,l3,h4,l4,h5,l5,h6,l6,h7,l7;
        bf16_split(a.x,h0,l0);  bf16_split(a.y,h1,l1);
        bf16_split(a.z,h2,l2);  bf16_split(a.w,h3,l3);
        bf16_split(bq.x,h4,l4); bf16_split(bq.y,h5,l5);
        bf16_split(bq.z,h6,l6); bf16_split(bq.w,h7,l7);
        __nv_bfloat162 H0 = __halves2bfloat162(h0,h1), H1 = __halves2bfloat162(h2,h3);
        __nv_bfloat162 H2 = __halves2bfloat162(h4,h5), H3 = __halves2bfloat162(h6,h7);
        __nv_bfloat162 L0 = __halves2bfloat162(l0,l1), L1 = __halves2bfloat162(l2,l3);
        __nv_bfloat162 L2 = __halves2bfloat162(l4,l5), L3 = __halves2bfloat162(l6,l7);
        int kt = q >> 3;
        uint32_t so = kt*8192 + SWZ((uint32_t)(l*128 + (q & 7)*16));
        *(uint4*)(smem + YO_CH + so) = make_uint4(*(uint32_t*)&H0, *(uint32_t*)&H1,
                                                  *(uint32_t*)&H2, *(uint32_t*)&H3);
        *(uint4*)(smem + YO_CL + so) = make_uint4(*(uint32_t*)&L0, *(uint32_t*)&L1,
                                                  *(uint32_t*)&L2, *(uint32_t*)&L3);
    }

    int phase = 0;
    for (int ht = 0; ht < 4; ht++){
        __syncthreads();
        if (tid < 128){
            int hl = tid >> 6, l = tid & 63;
            int h = ht*2 + hl;
            ex[hl*64 + l] = __expf(g_acs[((size_t)(b*8+h)*32 + c)*64 + l]);
        }
        #pragma unroll
        for (int it = 0; it < 16; it++){
            int v = tid + it*256;
            int r = v >> 5, u = v & 31;
            size_t gi = ((size_t)bc*512 + ht*128 + r)*256 + u*8;
            int kt = u >> 3;
            uint32_t so = kt*16384 + SWZ((uint32_t)(r*128 + (u & 7)*16));
            *(uint4*)(smem + YO_AH + so) = *(const uint4*)&g_sph[gi];
            *(uint4*)(smem + YO_AL + so) = *(const uint4*)&g_spl[gi];
        }
        __syncthreads();
        asm volatile("fence.proxy.async.shared::cta;" ::: "memory");

        if (wid == 0 && elect_one()){
            bool first = true;
            #pragma unroll
            for (int kt = 0; kt < 4; kt++){
                uint64_t ah = make_desc_sw128(sbase + YO_AH + kt*16384);
                uint64_t al = make_desc_sw128(sbase + YO_AL + kt*16384);
                uint64_t bh = make_desc_sw128(sbase + YO_CH + kt*8192);
                uint64_t bl = make_desc_sw128(sbase + YO_CL + kt*8192);
                #pragma unroll
                for (int s = 0; s < 4; s++){
                    mma_bf16_ss(tmem, ah + s*2, bh + s*2, IDESC_N64, !first);
                    first = false;
                    mma_bf16_ss(tmem, ah + s*2, bl + s*2, IDESC_N64, true);
                    mma_bf16_ss(tmem, al + s*2, bh + s*2, IDESC_N64, true);
                }
            }
            TC_COMMIT(sbase + 8);
        }
        MBAR_WAIT(sbase + 8, phase);
        phase ^= 1;
        TC_FENCE_AFTER();
        float* eb = (float*)(smem + YO_AH);
        if (wid < 4){
            int hp = wid*32 + lid;
            #pragma unroll
            for (int g = 0; g < 2; g++){
                uint32_t r[32];
                TC_LD_X32(r, tmem + g*32);
                TC_WAIT_LD();
                #pragma unroll
                for (int j = 0; j < 32; j++)
                    eb[hp*65 + g*32 + j] = __uint_as_float(r[j]);
            }
            TC_FENCE_BEFORE();
        }
        __syncthreads();
        #pragma unroll
        for (int it = 0; it < 32; it++){
            int v = tid + it*256;
            int l = v >> 7, hp = v & 127;
            int h = ht*2 + (hp >> 6);
            float val = ex[(hp >> 6)*64 + l] * eb[hp*65 + l];
            float xh = g_xbc[(size_t)(t0+l)*CONV_DIM + ht*128 + hp];
            size_t oi = (size_t)(t0+l)*D_INNER + ht*128 + hp;
            g_y[oi] += val + xh*Dvec[h];
        }
    }
    __syncthreads();
    if (wid == 0){
        TC_RELINQ();
        TC_DEALLOC(tmem, 64);
    }
#else
    for (int idx = tid; idx < 64*512; idx += 256){
        int l = idx >> 9, hp = idx & 511;
        int h = hp >> 6;
        const __nv_bfloat16* sh = g_sph + ((size_t)bc*512 + hp)*256;
        const __nv_bfloat16* sl = g_spl + ((size_t)bc*512 + hp)*256;
        float acc = 0.f;
        for (int n = 0; n < 256; n++)
            acc += g_xbc[(size_t)(t0+l)*CONV_DIM + 768 + n]
                 * (__bfloat162float(sh[n]) + __bfloat162float(sl[n]));
        float e = __expf(g_acs[((size_t)(b*8+h)*32 + c)*64 + l]);
        float xh = g_xbc[(size_t)(t0+l)*CONV_DIM + hp];
        g_y[(size_t)(t0+l)*D_INNER + hp] += e*acc + xh*Dvec[h];
    }
#endif
}

// ---------------- transpose x,B channels ----------------
__global__ void k_transpose(){
    __shared__ float t[32][33];
    int ch0 = blockIdx.x*32, l0 = blockIdx.y*32, b = blockIdx.z;
    int tx = threadIdx.x, ty = threadIdx.y;
    #pragma unroll
    for (int r = ty; r < 32; r += 8)
        t[r][tx] = g_xbc[(size_t)(b*L_ + l0 + r)*CONV_DIM + ch0 + tx];
    __syncthreads();
    #pragma unroll
    for (int r = ty; r < 32; r += 8)
        g_xbt[((size_t)b*768 + ch0 + r)*L_ + l0 + tx] = t[tx][r];
}

// ---------------- W split + transpose ----------------
__global__ void k_wsplit_t(const float* __restrict__ W,
                           __nv_bfloat16* __restrict__ Wh, __nv_bfloat16* __restrict__ Wl,
                           int K, int N){
    __shared__ float tile[32][33];
    int n0 = blockIdx.x*32, k0 = blockIdx.y*32;
    int tx = threadIdx.x, ty = threadIdx.y;
    #pragma unroll
    for (int r = ty; r < 32; r += 8){
        int k = k0 + r, n = n0 + tx;
        tile[r][tx] = (k < K && n < N) ? W[(size_t)k*N + n] : 0.f;
    }
    __syncthreads();
    #pragma unroll
    for (int r = ty; r < 32; r += 8){
        int n = n0 + r, k = k0 + tx;
        if (n < N && k < K){
            __nv_bfloat16 hi, lo;
            bf16_split(tile[tx][r], hi, lo);
            Wh[(size_t)n*K + k] = hi;
            Wl[(size_t)n*K + k] = lo;
        }
    }
}

// ---------------- fused embed + rmsnorm + bf16 split (layer 0) ----------------
__global__ void k_embed_norm(const float* __restrict__ x, const float* __restrict__ emb,
                             const float* __restrict__ w,
                             __nv_bfloat16* __restrict__ oh, __nv_bfloat16* __restrict__ ol){
    int t = blockIdx.x;
    int e = threadIdx.x;
    int vv = (int)(255.0f * x[t]);
    vv = min(max(vv, 0), 255);
    float val0 = emb[(size_t)vv*EMB + e];
    g_h[(size_t)t*EMB + e] = val0;
    __shared__ float red[8];
    float ss = val0*val0;
    #pragma unroll
    for (int o = 16; o; o >>= 1) ss += __shfl_xor_sync(0xffffffffu, ss, o);
    if ((threadIdx.x & 31) == 0) red[threadIdx.x >> 5] = ss;
    __syncthreads();
    if (threadIdx.x < 32){
        float s2 = (threadIdx.x < 8) ? red[threadIdx.x] : 0.f;
        #pragma unroll
        for (int o = 4; o; o >>= 1) s2 += __shfl_xor_sync(0xffffffffu, s2, o);
        if (threadIdx.x == 0) red[0] = s2;
    }
    __syncthreads();
    float scale = rsqrtf(red[0]/(float)EMB + 1e-5f);
    float val = val0*scale*w[e];
    __nv_bfloat16 hi, lo;
    bf16_split(val, hi, lo);
    oh[(size_t)t*EMB + e] = hi;
    ol[(size_t)t*EMB + e] = lo;
}

// ---------------- rmsnorm + bf16 split ----------------
template<int DIM>
__global__ void k_rmsnorm_split(const float* __restrict__ in, const float* __restrict__ w,
                                __nv_bfloat16* __restrict__ oh, __nv_bfloat16* __restrict__ ol){
    int t = blockIdx.x;
    const float* row = in + (size_t)t*DIM;
    __shared__ float red[8];
    float v[DIM/256];
    float ss = 0.f;
    #pragma unroll
    for (int i = 0; i < DIM/256; i++){
        v[i] = row[threadIdx.x + i*256];
        ss += v[i]*v[i];
    }
    #pragma unroll
    for (int o = 16; o; o >>= 1) ss += __shfl_xor_sync(0xffffffffu, ss, o);
    if ((threadIdx.x & 31) == 0) red[threadIdx.x >> 5] = ss;
    __syncthreads();
    if (threadIdx.x < 32){
        float s2 = (threadIdx.x < 8) ? red[threadIdx.x] : 0.f;
        #pragma unroll
        for (int o = 4; o; o >>= 1) s2 += __shfl_xor_sync(0xffffffffu, s2, o);
        if (threadIdx.x == 0) red[0] = s2;
    }
    __syncthreads();
    float scale = rsqrtf(red[0]/(float)DIM + 1e-5f);
    #pragma unroll
    for (int i = 0; i < DIM/256; i++){
        int d = threadIdx.x + i*256;
        float val = v[i]*scale*w[d];
        __nv_bfloat16 hi, lo;
        bf16_split(val, hi, lo);
        oh[(size_t)t*DIM + d] = hi;
        ol[(size_t)t*DIM + d] = lo;
    }
}

// ---------------- smem-tiled causal depthwise conv (k=4) + bias + silu ----------------
__global__ void __launch_bounds__(256)
k_conv2(const float* __restrict__ cw, const float* __restrict__ cb){
    extern __shared__ float s[];                 // [67][256]
    int t0  = blockIdx.x * 64;
    int ch0 = blockIdx.y * 256;
    int tid = threadIdx.x;
    int l0  = t0 & (L_-1);
    #pragma unroll
    for (int r = 0; r < 67; r++){
        float val = 0.f;
        if (l0 - 3 + r >= 0)
            val = g_zx[(size_t)(t0 - 3 + r)*D_PROJ + 512 + ch0 + tid];
        s[r*256 + tid] = val;
    }
    __syncthreads();
    int ch = ch0 + tid;
    float w0 = cw[ch*4+0], w1 = cw[ch*4+1], w2 = cw[ch*4+2], w3 = cw[ch*4+3];
    float bias = cb[ch];
    #pragma unroll 4
    for (int r = 0; r < 64; r++){
        float acc = bias;
        acc = fmaf(w0, s[(r+0)*256 + tid], acc);
        acc = fmaf(w1, s[(r+1)*256 + tid], acc);
        acc = fmaf(w2, s[(r+2)*256 + tid], acc);
        acc = fmaf(w3, s[(r+3)*256 + tid], acc);
        acc = acc / (1.f + __expf(-acc));
        g_xbc[(size_t)(t0+r)*CONV_DIM + ch] = acc;
    }
}

// ---------------- fused dt(softplus) + per-chunk cumsum ----------------
__global__ void k_cumsum(const float* __restrict__ A_log, const float* __restrict__ dt_bias){
    int bhc = blockIdx.x;
    int c = bhc & 31;
    int h = (bhc >> 5) & 7;
    int b = bhc >> 8;
    int l = threadIdx.x;
    int t = b*L_ + c*64 + l;
    float v = g_zx[(size_t)t*D_PROJ + 1536 + h] + dt_bias[h];
    float dt = (v > 20.f) ? v : log1pf(__expf(v));
    g_dt[t*NHD + h] = dt;
    float a = -__expf(A_log[h]) * dt;
    __shared__ float s[64];
    s[l] = a; __syncthreads();
    #pragma unroll
    for (int off = 1; off < 64; off <<= 1){
        float vv = s[l] + ((l >= off) ? s[l-off] : 0.f);
        __syncthreads();
        s[l] = vv;
        __syncthreads();
    }
    g_acs[bhc*64 + l] = s[l];
}

// ---------------- Y_diag per (b,c) (fp32 FMA) ----------------
__global__ void k_ydiag(){
    __shared__ float bufA[64][65];
    __shared__ float bufB[64][65];
    __shared__ float acsS[64];
    int bc = blockIdx.x;
    int c = bc & 31, b = bc >> 5;
    int t0 = b*L_ + c*64;
    int tid = threadIdx.x, tx = tid & 15, ty = tid >> 4;
    float G[4][4] = {};
    for (int nt = 0; nt < 4; nt++){
        for (int i = tid; i < 4096; i += 256){
            int r = i >> 6, nn = i & 63;
            bufA[r][nn] = g_xbc[(size_t)(t0+r)*CONV_DIM + 768 + nt*64 + nn];
            bufB[r][nn] = g_xbc[(size_t)(t0+r)*CONV_DIM + 512 + nt*64 + nn];
        }
        __syncthreads();
        #pragma unroll 8
        for (int nn = 0; nn < 64; nn++){
            float cv[4], bv[4];
            #pragma unroll
            for (int i = 0; i < 4; i++) cv[i] = bufA[ty*4+i][nn];
            #pragma unroll
            for (int j = 0; j < 4; j++) bv[j] = bufB[tx*4+j][nn];
            #pragma unroll
            for (int i = 0; i < 4; i++)
                #pragma unroll
                for (int j = 0; j < 4; j++)
                    G[i][j] = fmaf(cv[i], bv[j], G[i][j]);
        }
        __syncthreads();
    }

    for (int hh = 0; hh < NHD; hh++){
        __syncthreads();
        if (tid < 64) acsS[tid] = g_acs[((b*8+hh)*32 + c)*64 + tid];
        for (int i = tid; i < 4096; i += 256){
            int s = i >> 6, p = i & 63;
            int t = t0 + s;
            bufB[s][p] = g_xbc[(size_t)t*CONV_DIM + hh*64 + p] * g_dt[t*NHD + hh];
        }
        __syncthreads();
        #pragma unroll
        for (int i = 0; i < 4; i++){
            int l = ty*4 + i;
            #pragma unroll
            for (int j = 0; j < 4; j++){
                int s = tx*4 + j;
                bufA[l][s] = (s <= l) ? G[i][j]*__expf(acsS[l]-acsS[s]) : 0.f;
            }
        }
        __syncthreads();
        float y[4][4] = {};
        #pragma unroll 4
        for (int s = 0; s < 64; s++){
            float xv[4], wv[4];
            #pragma unroll
            for (int j = 0; j < 4; j++) xv[j] = bufB[s][tx*4+j];
            #pragma unroll
            for (int i = 0; i < 4; i++) wv[i] = bufA[ty*4+i][s];
            #pragma unroll
            for (int i = 0; i < 4; i++)
                #pragma unroll
                for (int j = 0; j < 4; j++)
                    y[i][j] = fmaf(wv[i], xv[j], y[i][j]);
        }
        #pragma unroll
        for (int i = 0; i < 4; i++)
            #pragma unroll
            for (int j = 0; j < 4; j++)
                g_y[(size_t)(t0 + ty*4 + i)*D_INNER + hh*64 + tx*4 + j] = y[i][j];
    }
}

// ---------------- inter-chunk scan: fp32 states -> bf16 hi/lo prev-states ----------------
// finer split: grid (B_*NHD, 32), 2 carried elements/thread
__global__ void k_scan(){
    int bh = blockIdx.x;
    int h = bh & 7, b = bh >> 3;
    int base = blockIdx.y*512 + threadIdx.x;
    float S[2] = {};
    for (int c = 0; c < 32; c++){
        float dec = __expf(g_acs[((b*8+h)*32 + c)*64 + 63]);
        size_t off = ((size_t)(b*32 + c)*8 + h)*16384 + base;
        const float* ptr = g_states + off;
        __nv_bfloat16* ph = g_sph + off;
        __nv_bfloat16* pl = g_spl + off;
        #pragma unroll
        for (int e = 0; e < 2; e++){
            float tmp = ptr[e*256];
            __nv_bfloat16 hi, lo;
            bf16_split(S[e], hi, lo);
            ph[e*256] = hi;
            pl[e*256] = lo;
            S[e] = fmaf(S[e], dec, tmp);
        }
    }
}

// ---------------- gated rmsnorm + bf16 split ----------------
__global__ void k_gatenorm_split(const float* __restrict__ gw,
                                 __nv_bfloat16* __restrict__ oh, __nv_bfloat16* __restrict__ ol){
    int t = blockIdx.x;
    __shared__ float red[8];
    float v[2];
    float ss = 0.f;
    #pragma unroll
    for (int i = 0; i < 2; i++){
        int d = threadIdx.x + i*256;
        float z = g_zx[(size_t)t*D_PROJ + d];
        float val = g_y[(size_t)t*D_INNER + d] * (z / (1.f + __expf(-z)));
        v[i] = val;
        ss += val*val;
    }
    #pragma unroll
    for (int o = 16; o; o >>= 1) ss += __shfl_xor_sync(0xffffffffu, ss, o);
    if ((threadIdx.x & 31) == 0) red[threadIdx.x >> 5] = ss;
    __syncthreads();
    if (threadIdx.x < 32){
        float s2 = (threadIdx.x < 8) ? red[threadIdx.x] : 0.f;
        #pragma unroll
        for (int o = 4; o; o >>= 1) s2 += __shfl_xor_sync(0xffffffffu, s2, o);
        if (threadIdx.x == 0) red[0] = s2;
    }
    __syncthreads();
    float scale = rsqrtf(red[0]/512.f + 1e-5f);
    #pragma unroll
    for (int i = 0; i < 2; i++){
        int d = threadIdx.x + i*256;
        float val = v[i]*scale*gw[d];
        __nv_bfloat16 hi, lo;
        bf16_split(val, hi, lo);
        oh[(size_t)t*D_INNER + d] = hi;
        ol[(size_t)t*D_INNER + d] = lo;
    }
}

// ---------------- launch ----------------
extern "C" void kernel_launch(void* const* d_in, const int* in_sizes, int n_in,
                              void* d_out, int out_size){
    const float* x       = (const float*)d_in[0];
    const float* emb     = (const float*)d_in[1];
    const float* in_proj = (const float*)d_in[2];
    const float* conv_w  = (const float*)d_in[3];
    const float* conv_b  = (const float*)d_in[4];
    const float* dt_bias = (const float*)d_in[5];
    const float* A_log   = (const float*)d_in[6];
    const float* Dv      = (const float*)d_in[7];
    const float* gnorm   = (const float*)d_in[8];
    const float* outp_w  = (const float*)d_in[9];
    const float* norm_w  = (const float*)d_in[10];
    const float* normf   = (const float*)d_in[11];
    const float* head_w  = (const float*)d_in[12];

    void *p_h, *p_ah, *p_al, *p_wh, *p_wl, *p_zx;
    cudaGetSymbolAddress(&p_h,  g_h);
    cudaGetSymbolAddress(&p_ah, g_ah);
    cudaGetSymbolAddress(&p_al, g_al);
    cudaGetSymbolAddress(&p_wh, g_wth);
    cudaGetSymbolAddress(&p_wl, g_wtl);
    cudaGetSymbolAddress(&p_zx, g_zx);
    float* gh  = (float*)p_h;
    float* gzx = (float*)p_zx;
    __nv_bfloat16* ah = (__nv_bfloat16*)p_ah;
    __nv_bfloat16* al = (__nv_bfloat16*)p_al;
    __nv_bfloat16* wh = (__nv_bfloat16*)p_wh;
    __nv_bfloat16* wl = (__nv_bfloat16*)p_wl;

    cudaFuncSetAttribute(k_mma_gemm2,  cudaFuncAttributeMaxDynamicSharedMemorySize, SM2_BYTES);
    cudaFuncSetAttribute(k_mma_gemm,   cudaFuncAttributeMaxDynamicSharedMemorySize, SM1_BYTES);
    cudaFuncSetAttribute(k_states_mma, cudaFuncAttributeMaxDynamicSharedMemorySize, ST_BYTES);
    cudaFuncSetAttribute(k_yoff_mma,   cudaFuncAttributeMaxDynamicSharedMemorySize, YO_BYTES);
    cudaFuncSetAttribute(k_conv2,      cudaFuncAttributeMaxDynamicSharedMemorySize, CV_BYTES);

    for (int i = 0; i < 2; i++){
        if (i == 0)
            k_embed_norm<<<NTOK, 256>>>(x, emb, norm_w, ah, al);
        else
            k_rmsnorm_split<256><<<NTOK, 256>>>(gh, norm_w + i*EMB, ah, al);
        k_wsplit_t<<<dim3((D_PROJ+31)/32, EMB/32), dim3(32,8)>>>(
            in_proj + (size_t)i*EMB*D_PROJ, wh, wl, EMB, D_PROJ);
        k_mma_gemm2<<<dim3((D_PROJ+255)/256, NTOK/128), 256, SM2_BYTES>>>(
            ah, al, wh, wl, gzx, NTOK, D_PROJ, EMB, nullptr);
        k_conv2<<<dim3(NTOK/64, CONV_DIM/256), 256, CV_BYTES>>>(
            conv_w + i*CONV_DIM*4, conv_b + i*CONV_DIM);
        k_cumsum<<<B_*NHD*NCHUNK, 64>>>(A_log + i*NHD, dt_bias + i*NHD);
        k_transpose<<<dim3(24, 64, 4), dim3(32,8)>>>();
        k_ydiag<<<B_*NCHUNK, 256>>>();
        k_states_mma<<<B_*NCHUNK, 256, ST_BYTES>>>();
        k_scan<<<dim3(B_*NHD, 32), 256>>>();
        k_yoff_mma<<<B_*NCHUNK, 256, YO_BYTES>>>(Dv + i*NHD);
        k_gatenorm_split<<<NTOK, 256>>>(gnorm + i*D_INNER, ah, al);
        k_wsplit_t<<<dim3(EMB/32, D_INNER/32), dim3(32,8)>>>(
            outp_w + (size_t)i*D_INNER*EMB, wh, wl, D_INNER, EMB);
        k_mma_gemm<<<dim3(EMB/128, NTOK/128), 256, SM1_BYTES>>>(
            ah, al, wh, wl, gh, NTOK, EMB, D_INNER, gh);
    }

    k_rmsnorm_split<256><<<NTOK, 256>>>(gh, normf, ah, al);
    k_wsplit_t<<<dim3(EMB/32, EMB/32), dim3(32,8)>>>(head_w, wh, wl, EMB, EMB);
    k_mma_gemm<<<dim3(EMB/128, NTOK/128), 256, SM1_BYTES>>>(
        ah, al, wh, wl, (float*)d_out, NTOK, EMB, EMB, nullptr);
}

// round 16
// speedup vs baseline: 1.0560x; 1.0207x over previous
#include <cuda_runtime.h>
#include <cuda_bf16.h>
#include <cstdint>
#include <math.h>

// ---------------- problem constants ----------------
#define B_      4
#define L_      2048
#define EMB     256
#define NHD     8
#define CHK     64
#define NCHUNK  (L_/CHK)          // 32
#define D_INNER 512
#define D_STATE 256
#define CONV_DIM 1024
#define D_PROJ  1544
#define NTOK    (B_*L_)           // 8192

#if defined(__CUDA_ARCH_FEAT_SM103_ALL) || defined(__CUDA_ARCH_FEAT_SM100_ALL) || \
    defined(__CUDA_ARCH_SPECIFIC__) || defined(__CUDA_ARCH_FAMILY_SPECIFIC__)
#define HAS_TCGEN05 1
#else
#define HAS_TCGEN05 0
#endif

// ---------------- scratch (device globals, no allocation) ----------------
__device__ float g_h  [NTOK*EMB];
__device__ float g_zx [NTOK*D_PROJ];
__device__ float g_xbc[NTOK*CONV_DIM];
__device__ float g_dt [NTOK*NHD];
__device__ float g_acs[B_*NHD*NCHUNK*CHK];
__device__ float g_states[(size_t)B_*NCHUNK*NHD*64*256];   // chunk states fp32
__device__ float g_y  [NTOK*D_INNER];
__device__ __nv_bfloat16 g_ah[NTOK*512];
__device__ __nv_bfloat16 g_al[NTOK*512];
__device__ __nv_bfloat16 g_wth[1544*256];
__device__ __nv_bfloat16 g_wtl[1544*256];
__device__ float g_xbt[(size_t)B_*768*L_];
__device__ __nv_bfloat16 g_sph[(size_t)B_*NCHUNK*512*256];
__device__ __nv_bfloat16 g_spl[(size_t)B_*NCHUNK*512*256];

__device__ __forceinline__ void bf16_split(float x, __nv_bfloat16& hi, __nv_bfloat16& lo){
    hi = __float2bfloat16_rn(x);
    lo = __float2bfloat16_rn(x - __bfloat162float(hi));
}

// GEMM v2 (in_proj) smem
#define GM_STAGE0  1024
#define GM_STAGE   98304
#define GM_AH      0
#define GM_AL      16384
#define GM_BH      32768
#define GM_BL      65536
#define SM2_BYTES  197632
// GEMM v1 (out_proj/head) smem: double-buffered, K-chunk 64
#define S1_STAGE0  1024
#define S1_STAGE   65536
#define S1_AH      0
#define S1_AL      16384
#define S1_BH      32768
#define S1_BL      49152
#define SM1_BYTES  132096
// states kernel smem
#define ST_BH      1024
#define ST_BL      33792
#define ST_AH      66560
#define ST_AL      82944
#define ST_BYTES   100352
// yoff kernel smem
#define YO_CH      1024
#define YO_CL      33792
#define YO_AH      66560
#define YO_AL      132096
#define YO_BYTES   197632
// conv smem: (32+3) x 256 fp32
#define CV_BYTES   (35*256*4)

#if HAS_TCGEN05
// ================= tcgen05 helpers =================
__device__ __forceinline__ uint32_t smem_u32(const void* p){
    uint32_t a;
    asm("{ .reg .u64 t; cvta.to.shared.u64 t, %1; cvt.u32.u64 %0, t; }" : "=r"(a) : "l"(p));
    return a;
}
__device__ __forceinline__ uint32_t elect_one(){
    uint32_t p;
    asm volatile("{ .reg .pred p; elect.sync _|p, 0xFFFFFFFF; selp.b32 %0, 1, 0, p; }" : "=r"(p));
    return p;
}
#define TC_ALLOC(sm, n)  asm volatile("tcgen05.alloc.cta_group::1.sync.aligned.shared::cta.b32 [%0], %1;" :: "r"(sm), "r"(n) : "memory")
#define TC_DEALLOC(t, n) asm volatile("tcgen05.dealloc.cta_group::1.sync.aligned.b32 %0, %1;" :: "r"(t), "r"(n))
#define TC_RELINQ()      asm volatile("tcgen05.relinquish_alloc_permit.cta_group::1.sync.aligned;")
#define TC_COMMIT(mb)    asm volatile("tcgen05.commit.cta_group::1.mbarrier::arrive::one.shared::cluster.b64 [%0];" :: "r"(mb) : "memory")
#define TC_FENCE_AFTER() asm volatile("tcgen05.fence::after_thread_sync;" ::: "memory")
#define TC_FENCE_BEFORE() asm volatile("tcgen05.fence::before_thread_sync;" ::: "memory")
#define TC_WAIT_LD()     asm volatile("tcgen05.wait::ld.sync.aligned;" ::: "memory")
#define MBAR_INIT(mb, c) asm volatile("mbarrier.init.shared.b64 [%0], %1;" :: "r"(mb), "r"(c) : "memory")
#define MBAR_WAIT(mb, ph) do { \
    uint32_t _m = (mb), _p = (ph), _d; \
    asm volatile("{ .reg .pred p; mbarrier.try_wait.parity.acquire.cta.shared::cta.b64 p, [%1], %2; selp.b32 %0, 1, 0, p; }" \
        : "=r"(_d) : "r"(_m), "r"(_p) : "memory"); \
    if (!_d) { \
        asm volatile("{ .reg .pred P1; WL_%=: mbarrier.try_wait.parity.acquire.cta.shared::cta.b64 P1, [%0], %1, 0x989680; @P1 bra.uni WD_%=; bra.uni WL_%=; WD_%=: }" \
            :: "r"(_m), "r"(_p) : "memory"); \
    } } while(0)
#define TC_LD_X32(r, ta) \
    asm volatile("tcgen05.ld.sync.aligned.32x32b.x32.b32 " \
        "{%0,%1,%2,%3,%4,%5,%6,%7,%8,%9,%10,%11,%12,%13,%14,%15," \
        "%16,%17,%18,%19,%20,%21,%22,%23,%24,%25,%26,%27,%28,%29,%30,%31}, [%32];" \
        : "=r"((r)[0]),"=r"((r)[1]),"=r"((r)[2]),"=r"((r)[3]),"=r"((r)[4]),"=r"((r)[5]),"=r"((r)[6]),"=r"((r)[7]), \
          "=r"((r)[8]),"=r"((r)[9]),"=r"((r)[10]),"=r"((r)[11]),"=r"((r)[12]),"=r"((r)[13]),"=r"((r)[14]),"=r"((r)[15]), \
          "=r"((r)[16]),"=r"((r)[17]),"=r"((r)[18]),"=r"((r)[19]),"=r"((r)[20]),"=r"((r)[21]),"=r"((r)[22]),"=r"((r)[23]), \
          "=r"((r)[24]),"=r"((r)[25]),"=r"((r)[26]),"=r"((r)[27]),"=r"((r)[28]),"=r"((r)[29]),"=r"((r)[30]),"=r"((r)[31]) \
        : "r"(ta))

static __device__ __forceinline__ uint64_t make_desc_sw128(uint32_t addr){
    const uint64_t base =
        (uint64_t(2)  << 61) | (uint64_t(1) << 46) | (uint64_t(64) << 32) | (uint64_t(1) << 16);
    return base | ((uint64_t)(addr >> 4) & 0x3FFF);
}
__device__ __forceinline__ void mma_bf16_ss(uint32_t d, uint64_t ad, uint64_t bd,
                                            uint32_t idesc, bool acc){
    uint32_t en = acc ? 1u : 0u;
    asm volatile(
        "{\n\t"
        ".reg .pred p;\n\t"
        "setp.ne.u32 p, %5, 0;\n\t"
        "tcgen05.mma.cta_group::1.kind::f16 [%0], %1, %2, %3, {%4, %4, %4, %4}, p;\n\t"
        "}"
        :: "r"(d), "l"(ad), "l"(bd), "r"(idesc), "r"(0u), "r"(en)
        : "memory");
}
#define SWZ(o) ((o) ^ (((o) >> 3) & 0x70))
#define IDESC_N128 ((1u<<4) | (1u<<7) | (1u<<10) | ((128u/8u)<<17) | ((128u/16u)<<24))
#define IDESC_N64  ((1u<<4) | (1u<<7) | (1u<<10) | (( 64u/8u)<<17) | ((128u/16u)<<24))
#endif // HAS_TCGEN05

// ---------------- GEMM v2 (in_proj): 128x256 tile, K chunks of 64, double-buffered ----------------
__global__ void __launch_bounds__(256)
k_mma_gemm2(const __nv_bfloat16* __restrict__ Ah, const __nv_bfloat16* __restrict__ Al,
            const __nv_bfloat16* __restrict__ Bh, const __nv_bfloat16* __restrict__ Bl,
            float* __restrict__ C, int M, int N, int K,
            const float* __restrict__ resid){
    extern __shared__ char smem[];
    int tid = threadIdx.x;
    int bm = blockIdx.y * 128, bn = blockIdx.x * 256;

#if HAS_TCGEN05
    uint32_t sbase = smem_u32(smem);
    int wid = tid >> 5, lid = tid & 31;
    if (wid == 0) TC_ALLOC(sbase, 256);
    if (tid == 0){ MBAR_INIT(sbase + 8, 1); MBAR_INIT(sbase + 16, 1); }
    __syncthreads();
    uint32_t tmem;
    asm volatile("ld.shared.b32 %0, [%1];" : "=r"(tmem) : "r"(sbase));

    int nc = K >> 6;
    int ph0 = 0, ph1 = 0;
    for (int c = 0; c < nc; c++){
        int buf = c & 1;
        uint32_t sb = sbase + GM_STAGE0 + buf*GM_STAGE;
        char* smb = smem + GM_STAGE0 + buf*GM_STAGE;
        int kc = c << 6;
        if (c >= 2){
            if (buf == 0){ MBAR_WAIT(sbase + 8,  ph0); ph0 ^= 1; }
            else         { MBAR_WAIT(sbase + 16, ph1); ph1 ^= 1; }
        }
        #pragma unroll
        for (int it = 0; it < 4; it++){
            int v = tid + it*256;
            int m = v >> 3, u = v & 7;
            uint32_t so = SWZ((uint32_t)(m*128 + u*16));
            size_t gi = (size_t)(bm+m)*K + kc + u*8;
            *(uint4*)(smb + GM_AH + so) = *(const uint4*)&Ah[gi];
            *(uint4*)(smb + GM_AL + so) = *(const uint4*)&Al[gi];
        }
        #pragma unroll
        for (int it = 0; it < 8; it++){
            int v = tid + it*256;
            int n = v >> 3, u = v & 7;
            uint32_t so = SWZ((uint32_t)(n*128 + u*16));
            uint4 vh = make_uint4(0,0,0,0), vl = make_uint4(0,0,0,0);
            if (bn + n < N){
                size_t gi = (size_t)(bn+n)*K + kc + u*8;
                vh = *(const uint4*)&Bh[gi];
                vl = *(const uint4*)&Bl[gi];
            }
            *(uint4*)(smb + GM_BH + so) = vh;
            *(uint4*)(smb + GM_BL + so) = vl;
        }
        __syncthreads();
        asm volatile("fence.proxy.async.shared::cta;" ::: "memory");

        if (wid == 0 && elect_one()){
            uint64_t ah = make_desc_sw128(sb + GM_AH);
            uint64_t al = make_desc_sw128(sb + GM_AL);
            #pragma unroll
            for (int half = 0; half < 2; half++){
                uint64_t bh = make_desc_sw128(sb + GM_BH + half*16384);
                uint64_t bl = make_desc_sw128(sb + GM_BL + half*16384);
                uint32_t dt_ = tmem + half*128;
                #pragma unroll
                for (int s = 0; s < 4; s++){
                    bool acc = !(c == 0 && s == 0);
                    mma_bf16_ss(dt_, ah + s*2, bh + s*2, IDESC_N128, acc);
                    mma_bf16_ss(dt_, ah + s*2, bl + s*2, IDESC_N128, true);
                    mma_bf16_ss(dt_, al + s*2, bh + s*2, IDESC_N128, true);
                }
            }
            TC_COMMIT(sbase + 8 + buf*8);
        }
        __syncthreads();
    }
    {
        int lb = (nc-1) & 1;
        if (lb == 0) MBAR_WAIT(sbase + 8,  ph0);
        else         MBAR_WAIT(sbase + 16, ph1);
    }

    TC_FENCE_AFTER();
    float* eb = (float*)(smem + GM_STAGE0);
    for (int g = 0; g < 8; g++){
        if (wid < 4){
            uint32_t r[32];
            TC_LD_X32(r, tmem + g*32);
            TC_WAIT_LD();
            int m = wid*32 + lid;
            #pragma unroll
            for (int j = 0; j < 32; j++)
                eb[m*33 + j] = __uint_as_float(r[j]);
        }
        __syncthreads();
        #pragma unroll
        for (int it = 0; it < 16; it++){
            int v = tid + it*256;
            int m = v >> 5, j = v & 31;
            int n = bn + g*32 + j;
            if (n < N){
                size_t idx = (size_t)(bm+m)*N + n;
                float val = eb[m*33 + j];
                if (resid) val += resid[idx];
                C[idx] = val;
            }
        }
        __syncthreads();
    }
    if (wid == 0){
        TC_RELINQ();
        TC_DEALLOC(tmem, 256);
    }
#else
    float (*As)[132] = (float(*)[132])(smem);
    float (*Ws)[132] = (float(*)[132])(smem + 16*132*4);
    int tx = tid & 15, ty = tid >> 4;
    for (int half = 0; half < 2; half++){
        int bn2 = bn + half*128;
        float acc[8][8] = {};
        for (int k0 = 0; k0 < K; k0 += 16){
            #pragma unroll
            for (int r = 0; r < 8; r++){
                int i = tid + r*256;
                int m = i >> 4, k = i & 15;
                size_t gi = (size_t)(bm+m)*K + k0 + k;
                As[k][m] = __bfloat162float(Ah[gi]) + __bfloat162float(Al[gi]);
            }
            #pragma unroll
            for (int r = 0; r < 8; r++){
                int i = tid + r*256;
                int k = i >> 7, n = i & 127;
                float w = 0.f;
                if (bn2+n < N){
                    size_t gi = (size_t)(bn2+n)*K + k0 + k;
                    w = __bfloat162float(Bh[gi]) + __bfloat162float(Bl[gi]);
                }
                Ws[k][n] = w;
            }
            __syncthreads();
            #pragma unroll
            for (int kk = 0; kk < 16; kk++){
                float a[8], b[8];
                #pragma unroll
                for (int i = 0; i < 8; i++) a[i] = As[kk][ty*8+i];
                #pragma unroll
                for (int j = 0; j < 8; j++) b[j] = Ws[kk][tx*8+j];
                #pragma unroll
                for (int i = 0; i < 8; i++)
                    #pragma unroll
                    for (int j = 0; j < 8; j++)
                        acc[i][j] = fmaf(a[i], b[j], acc[i][j]);
            }
            __syncthreads();
        }
        #pragma unroll
        for (int i = 0; i < 8; i++){
            int m = bm + ty*8 + i;
            #pragma unroll
            for (int j = 0; j < 8; j++){
                int n = bn2 + tx*8 + j;
                if (n < N){
                    size_t idx = (size_t)m*N + n;
                    float v = acc[i][j];
                    if (resid) v += resid[idx];
                    C[idx] = v;
                }
            }
        }
        __syncthreads();
    }
#endif
}

// ---------------- GEMM v1 (out_proj/head): 128x128 tile, K chunks of 64, double-buffered ----------------
__global__ void __launch_bounds__(256)
k_mma_gemm(const __nv_bfloat16* __restrict__ Ah, const __nv_bfloat16* __restrict__ Al,
           const __nv_bfloat16* __restrict__ Bh, const __nv_bfloat16* __restrict__ Bl,
           float* __restrict__ C, int M, int N, int K,
           const float* __restrict__ resid){
    extern __shared__ char smem[];
    int tid = threadIdx.x;
    int bm = blockIdx.y * 128, bn = blockIdx.x * 128;

#if HAS_TCGEN05
    uint32_t sbase = smem_u32(smem);
    int wid = tid >> 5, lid = tid & 31;
    if (wid == 0) TC_ALLOC(sbase, 128);
    if (tid == 0){ MBAR_INIT(sbase + 8, 1); MBAR_INIT(sbase + 16, 1); }
    __syncthreads();
    uint32_t tmem;
    asm volatile("ld.shared.b32 %0, [%1];" : "=r"(tmem) : "r"(sbase));

    int nc = K >> 6;
    int ph0 = 0, ph1 = 0;
    for (int c = 0; c < nc; c++){
        int buf = c & 1;
        uint32_t sb = sbase + S1_STAGE0 + buf*S1_STAGE;
        char* smb = smem + S1_STAGE0 + buf*S1_STAGE;
        int kc = c << 6;
        if (c >= 2){
            if (buf == 0){ MBAR_WAIT(sbase + 8,  ph0); ph0 ^= 1; }
            else         { MBAR_WAIT(sbase + 16, ph1); ph1 ^= 1; }
        }
        #pragma unroll
        for (int it = 0; it < 4; it++){
            int v = tid + it*256;
            int m = v >> 3, u = v & 7;
            uint32_t so = SWZ((uint32_t)(m*128 + u*16));
            size_t gi = (size_t)(bm+m)*K + kc + u*8;
            *(uint4*)(smb + S1_AH + so) = *(const uint4*)&Ah[gi];
            *(uint4*)(smb + S1_AL + so) = *(const uint4*)&Al[gi];
        }
        #pragma unroll
        for (int it = 0; it < 4; it++){
            int v = tid + it*256;
            int n = v >> 3, u = v & 7;
            uint32_t so = SWZ((uint32_t)(n*128 + u*16));
            uint4 vh = make_uint4(0,0,0,0), vl = make_uint4(0,0,0,0);
            if (bn + n < N){
                size_t gi = (size_t)(bn+n)*K + kc + u*8;
                vh = *(const uint4*)&Bh[gi];
                vl = *(const uint4*)&Bl[gi];
            }
            *(uint4*)(smb + S1_BH + so) = vh;
            *(uint4*)(smb + S1_BL + so) = vl;
        }
        __syncthreads();
        asm volatile("fence.proxy.async.shared::cta;" ::: "memory");

        if (wid == 0 && elect_one()){
            uint64_t ah = make_desc_sw128(sb + S1_AH);
            uint64_t al = make_desc_sw128(sb + S1_AL);
            uint64_t bh = make_desc_sw128(sb + S1_BH);
            uint64_t bl = make_desc_sw128(sb + S1_BL);
            #pragma unroll
            for (int s = 0; s < 4; s++){
                bool acc = !(c == 0 && s == 0);
                mma_bf16_ss(tmem, ah + s*2, bh + s*2, IDESC_N128, acc);
                mma_bf16_ss(tmem, ah + s*2, bl + s*2, IDESC_N128, true);
                mma_bf16_ss(tmem, al + s*2, bh + s*2, IDESC_N128, true);
            }
            TC_COMMIT(sbase + 8 + buf*8);
        }
        __syncthreads();
    }
    {
        int lb = (nc-1) & 1;
        if (lb == 0) MBAR_WAIT(sbase + 8,  ph0);
        else         MBAR_WAIT(sbase + 16, ph1);
    }

    TC_FENCE_AFTER();
    float* eb = (float*)(smem + S1_STAGE0);
    for (int g = 0; g < 4; g++){
        if (wid < 4){
            uint32_t r[32];
            TC_LD_X32(r, tmem + g*32);
            TC_WAIT_LD();
            int m = wid*32 + lid;
            #pragma unroll
            for (int j = 0; j < 32; j++)
                eb[m*33 + j] = __uint_as_float(r[j]);
        }
        __syncthreads();
        #pragma unroll
        for (int it = 0; it < 16; it++){
            int v = tid + it*256;
            int m = v >> 5, j = v & 31;
            int n = bn + g*32 + j;
            if (n < N){
                size_t idx = (size_t)(bm+m)*N + n;
                float val = eb[m*33 + j];
                if (resid) val += resid[idx];
                C[idx] = val;
            }
        }
        __syncthreads();
    }
    if (wid == 0){
        TC_RELINQ();
        TC_DEALLOC(tmem, 128);
    }
#else
    float (*As)[132] = (float(*)[132])(smem);
    float (*Ws)[132] = (float(*)[132])(smem + 16*132*4);
    int tx = tid & 15, ty = tid >> 4;
    float acc[8][8] = {};
    for (int k0 = 0; k0 < K; k0 += 16){
        #pragma unroll
        for (int r = 0; r < 8; r++){
            int i = tid + r*256;
            int m = i >> 4, k = i & 15;
            size_t gi = (size_t)(bm+m)*K + k0 + k;
            As[k][m] = __bfloat162float(Ah[gi]) + __bfloat162float(Al[gi]);
        }
        #pragma unroll
        for (int r = 0; r < 8; r++){
            int i = tid + r*256;
            int k = i >> 7, n = i & 127;
            float w = 0.f;
            if (bn+n < N){
                size_t gi = (size_t)(bn+n)*K + k0 + k;
                w = __bfloat162float(Bh[gi]) + __bfloat162float(Bl[gi]);
            }
            Ws[k][n] = w;
        }
        __syncthreads();
        #pragma unroll
        for (int kk = 0; kk < 16; kk++){
            float a[8], b[8];
            #pragma unroll
            for (int i = 0; i < 8; i++) a[i] = As[kk][ty*8+i];
            #pragma unroll
            for (int j = 0; j < 8; j++) b[j] = Ws[kk][tx*8+j];
            #pragma unroll
            for (int i = 0; i < 8; i++)
                #pragma unroll
                for (int j = 0; j < 8; j++)
                    acc[i][j] = fmaf(a[i], b[j], acc[i][j]);
        }
        __syncthreads();
    }
    #pragma unroll
    for (int i = 0; i < 8; i++){
        int m = bm + ty*8 + i;
        #pragma unroll
        for (int j = 0; j < 8; j++){
            int n = bn + tx*8 + j;
            if (n < N){
                size_t idx = (size_t)m*N + n;
                float v = acc[i][j];
                if (resid) v += resid[idx];
                C[idx] = v;
            }
        }
    }
#endif
}

// ---------------- states: S[hp,n] = sum_l xdts[l,hp]*B[l,n]  (tcgen05, fp32 out) ----------------
__global__ void __launch_bounds__(256)
k_states_mma(){
    extern __shared__ char smem[];
    int tid = threadIdx.x;
    int bc = blockIdx.x;
    int c = bc & 31, b = bc >> 5;
    int t0 = b*L_ + c*64;
#if HAS_TCGEN05
    uint32_t sbase = smem_u32(smem);
    int wid = tid >> 5, lid = tid & 31;
    float* sc = (float*)(smem + 128);
    if (wid == 0) TC_ALLOC(sbase, 128);
    if (tid == 0) MBAR_INIT(sbase + 8, 1);
    __syncthreads();
    uint32_t tmem;
    asm volatile("ld.shared.b32 %0, [%1];" : "=r"(tmem) : "r"(sbase));

    #pragma unroll
    for (int it = 0; it < 16; it++){
        int v = tid + it*256;
        int n = v >> 4, u = v & 15;
        const float* src = g_xbt + ((size_t)b*768 + 512 + n)*L_ + c*64 + u*4;
        float4 a = *(const float4*)src;
        __nv_bfloat16 h0,l0,h1,l1,h2,l2,h3,l3;
        bf16_split(a.x,h0,l0); bf16_split(a.y,h1,l1);
        bf16_split(a.z,h2,l2); bf16_split(a.w,h3,l3);
        __nv_bfloat162 hp2 = __halves2bfloat162(h0,h1), hq2 = __halves2bfloat162(h2,h3);
        __nv_bfloat162 lp2 = __halves2bfloat162(l0,l1), lq2 = __halves2bfloat162(l2,l3);
        int nt = n >> 7, r = n & 127;
        uint32_t so = nt*16384 + SWZ((uint32_t)(r*128 + u*8));
        *(uint2*)(smem + ST_BH + so) = make_uint2(*(uint32_t*)&hp2, *(uint32_t*)&hq2);
        *(uint2*)(smem + ST_BL + so) = make_uint2(*(uint32_t*)&lp2, *(uint32_t*)&lq2);
    }

    int phase = 0;
    for (int ht = 0; ht < 4; ht++){
        __syncthreads();
        if (tid < 128){
            int hl = tid >> 6, l = tid & 63;
            int h = ht*2 + hl;
            const float* ap = g_acs + ((size_t)(b*8+h)*32 + c)*64;
            sc[hl*64 + l] = g_dt[(size_t)(t0+l)*NHD + h] * __expf(ap[63] - ap[l]);
        }
        __syncthreads();
        #pragma unroll
        for (int it = 0; it < 8; it++){
            int v = tid + it*256;
            int r = v >> 4, u = v & 15;
            const float* src = g_xbt + ((size_t)b*768 + ht*128 + r)*L_ + c*64 + u*4;
            float4 a = *(const float4*)src;
            const float* s4 = sc + (r >> 6)*64 + u*4;
            a.x *= s4[0]; a.y *= s4[1]; a.z *= s4[2]; a.w *= s4[3];
            __nv_bfloat16 h0,l0,h1,l1,h2,l2,h3,l3;
            bf16_split(a.x,h0,l0); bf16_split(a.y,h1,l1);
            bf16_split(a.z,h2,l2); bf16_split(a.w,h3,l3);
            __nv_bfloat162 hp2 = __halves2bfloat162(h0,h1), hq2 = __halves2bfloat162(h2,h3);
            __nv_bfloat162 lp2 = __halves2bfloat162(l0,l1), lq2 = __halves2bfloat162(l2,l3);
            uint32_t so = SWZ((uint32_t)(r*128 + u*8));
            *(uint2*)(smem + ST_AH + so) = make_uint2(*(uint32_t*)&hp2, *(uint32_t*)&hq2);
            *(uint2*)(smem + ST_AL + so) = make_uint2(*(uint32_t*)&lp2, *(uint32_t*)&lq2);
        }
        __syncthreads();
        asm volatile("fence.proxy.async.shared::cta;" ::: "memory");

        for (int nt = 0; nt < 2; nt++){
            if (wid == 0 && elect_one()){
                uint64_t ah = make_desc_sw128(sbase + ST_AH);
                uint64_t al = make_desc_sw128(sbase + ST_AL);
                uint64_t bh = make_desc_sw128(sbase + ST_BH + nt*16384);
                uint64_t bl = make_desc_sw128(sbase + ST_BL + nt*16384);
                bool first = true;
                #pragma unroll
                for (int s = 0; s < 4; s++){
                    mma_bf16_ss(tmem, ah + s*2, bh + s*2, IDESC_N128, !first);
                    first = false;
                    mma_bf16_ss(tmem, ah + s*2, bl + s*2, IDESC_N128, true);
                    mma_bf16_ss(tmem, al + s*2, bh + s*2, IDESC_N128, true);
                }
                TC_COMMIT(sbase + 8);
            }
            MBAR_WAIT(sbase + 8, phase);
            phase ^= 1;
            TC_FENCE_AFTER();
            if (wid < 4){
                int hp = ht*128 + wid*32 + lid;
                float* out = g_states + ((size_t)bc*512 + hp)*256 + nt*128;
                #pragma unroll
                for (int g = 0; g < 4; g++){
                    uint32_t r[32];
                    TC_LD_X32(r, tmem + g*32);
                    TC_WAIT_LD();
                    #pragma unroll
                    for (int j = 0; j < 32; j += 4){
                        float4 v4 = make_float4(__uint_as_float(r[j]),   __uint_as_float(r[j+1]),
                                                __uint_as_float(r[j+2]), __uint_as_float(r[j+3]));
                        *(float4*)(out + g*32 + j) = v4;
                    }
                }
                TC_FENCE_BEFORE();
            }
            __syncthreads();
        }
    }
    if (wid == 0){
        TC_RELINQ();
        TC_DEALLOC(tmem, 128);
    }
#else
    __shared__ float sc8[8][64];
    for (int v = tid; v < 512; v += 256){
        int h = v >> 6, l = v & 63;
        const float* ap = g_acs + ((size_t)(b*8+h)*32 + c)*64;
        sc8[h][l] = g_dt[(size_t)(t0+l)*NHD + h] * __expf(ap[63] - ap[l]);
    }
    __syncthreads();
    for (int h = 0; h < 8; h++)
        for (int idx = tid; idx < 16384; idx += 256){
            int p = idx >> 8, n = idx & 255;
            float s = 0.f;
            for (int l = 0; l < 64; l++)
                s += g_xbc[(size_t)(t0+l)*CONV_DIM + h*64 + p] * sc8[h][l]
                   * g_xbc[(size_t)(t0+l)*CONV_DIM + 512 + n];
            g_states[((size_t)bc*512 + h*64 + p)*256 + n] = s;
        }
#endif
}

// ---------------- yoff ----------------
__global__ void __launch_bounds__(256)
k_yoff_mma(const float* __restrict__ Dvec){
    extern __shared__ char smem[];
    int tid = threadIdx.x;
    int bc = blockIdx.x;
    int c = bc & 31, b = bc >> 5;
    int t0 = b*L_ + c*64;
#if HAS_TCGEN05
    uint32_t sbase = smem_u32(smem);
    int wid = tid >> 5, lid = tid & 31;
    float* ex = (float*)(smem + 128);
    if (wid == 0) TC_ALLOC(sbase, 64);
    if (tid == 0) MBAR_INIT(sbase + 8, 1);
    __syncthreads();
    uint32_t tmem;
    asm volatile("ld.shared.b32 %0, [%1];" : "=r"(tmem) : "r"(sbase));

    #pragma unroll
    for (int it = 0; it < 8; it++){
        int v = tid + it*256;
        int l = v >> 5, q = v & 31;
        const float* src = &g_xbc[(size_t)(t0+l)*CONV_DIM + 768 + q*8];
        float4 a = *(const float4*)src;
        float4 bq = *(const float4*)(src + 4);
        __nv_bfloat16 h0,l0,h1,l1,h2,l2,h3,l3,h4,l4,h5,l5,h6,l6,h7,l7;
        bf16_split(a.x,h0,l0);  bf16_split(a.y,h1,l1);
        bf16_split(a.z,h2,l2);  bf16_split(a.w,h3,l3);
        bf16_split(bq.x,h4,l4); bf16_split(bq.y,h5,l5);
        bf16_split(bq.z,h6,l6); bf16_split(bq.w,h7,l7);
        __nv_bfloat162 H0 = __halves2bfloat162(h0,h1), H1 = __halves2bfloat162(h2,h3);
        __nv_bfloat162 H2 = __halves2bfloat162(h4,h5), H3 = __halves2bfloat162(h6,h7);
        __nv_bfloat162 L0 = __halves2bfloat162(l0,l1), L1 = __halves2bfloat162(l2,l3);
        __nv_bfloat162 L2 = __halves2bfloat162(l4,l5), L3 = __halves2bfloat162(l6,l7);
        int kt = q >> 3;
        uint32_t so = kt*8192 + SWZ((uint32_t)(l*128 + (q & 7)*16));
        *(uint4*)(smem + YO_CH + so) = make_uint4(*(uint32_t*)&H0, *(uint32_t*)&H1,
                                                  *(uint32_t*)&H2, *(uint32_t*)&H3);
        *(uint4*)(smem + YO_CL + so) = make_uint4(*(uint32_t*)&L0, *(uint32_t*)&L1,
                                                  *(uint32_t*)&L2, *(uint32_t*)&L3);
    }

    int phase = 0;
    for (int ht = 0; ht < 4; ht++){
        __syncthreads();
        if (tid < 128){
            int hl = tid >> 6, l = tid & 63;
            int h = ht*2 + hl;
            ex[hl*64 + l] = __expf(g_acs[((size_t)(b*8+h)*32 + c)*64 + l]);
        }
        #pragma unroll
        for (int it = 0; it < 16; it++){
            int v = tid + it*256;
            int r = v >> 5, u = v & 31;
            size_t gi = ((size_t)bc*512 + ht*128 + r)*256 + u*8;
            int kt = u >> 3;
            uint32_t so = kt*16384 + SWZ((uint32_t)(r*128 + (u & 7)*16));
            *(uint4*)(smem + YO_AH + so) = *(const uint4*)&g_sph[gi];
            *(uint4*)(smem + YO_AL + so) = *(const uint4*)&g_spl[gi];
        }
        __syncthreads();
        asm volatile("fence.proxy.async.shared::cta;" ::: "memory");

        if (wid == 0 && elect_one()){
            bool first = true;
            #pragma unroll
            for (int kt = 0; kt < 4; kt++){
                uint64_t ah = make_desc_sw128(sbase + YO_AH + kt*16384);
                uint64_t al = make_desc_sw128(sbase + YO_AL + kt*16384);
                uint64_t bh = make_desc_sw128(sbase + YO_CH + kt*8192);
                uint64_t bl = make_desc_sw128(sbase + YO_CL + kt*8192);
                #pragma unroll
                for (int s = 0; s < 4; s++){
                    mma_bf16_ss(tmem, ah + s*2, bh + s*2, IDESC_N64, !first);
                    first = false;
                    mma_bf16_ss(tmem, ah + s*2, bl + s*2, IDESC_N64, true);
                    mma_bf16_ss(tmem, al + s*2, bh + s*2, IDESC_N64, true);
                }
            }
            TC_COMMIT(sbase + 8);
        }
        MBAR_WAIT(sbase + 8, phase);
        phase ^= 1;
        TC_FENCE_AFTER();
        float* eb = (float*)(smem + YO_AH);
        if (wid < 4){
            int hp = wid*32 + lid;
            #pragma unroll
            for (int g = 0; g < 2; g++){
                uint32_t r[32];
                TC_LD_X32(r, tmem + g*32);
                TC_WAIT_LD();
                #pragma unroll
                for (int j = 0; j < 32; j++)
                    eb[hp*65 + g*32 + j] = __uint_as_float(r[j]);
            }
            TC_FENCE_BEFORE();
        }
        __syncthreads();
        #pragma unroll
        for (int it = 0; it < 32; it++){
            int v = tid + it*256;
            int l = v >> 7, hp = v & 127;
            int h = ht*2 + (hp >> 6);
            float val = ex[(hp >> 6)*64 + l] * eb[hp*65 + l];
            float xh = g_xbc[(size_t)(t0+l)*CONV_DIM + ht*128 + hp];
            size_t oi = (size_t)(t0+l)*D_INNER + ht*128 + hp;
            g_y[oi] += val + xh*Dvec[h];
        }
    }
    __syncthreads();
    if (wid == 0){
        TC_RELINQ();
        TC_DEALLOC(tmem, 64);
    }
#else
    for (int idx = tid; idx < 64*512; idx += 256){
        int l = idx >> 9, hp = idx & 511;
        int h = hp >> 6;
        const __nv_bfloat16* sh = g_sph + ((size_t)bc*512 + hp)*256;
        const __nv_bfloat16* sl = g_spl + ((size_t)bc*512 + hp)*256;
        float acc = 0.f;
        for (int n = 0; n < 256; n++)
            acc += g_xbc[(size_t)(t0+l)*CONV_DIM + 768 + n]
                 * (__bfloat162float(sh[n]) + __bfloat162float(sl[n]));
        float e = __expf(g_acs[((size_t)(b*8+h)*32 + c)*64 + l]);
        float xh = g_xbc[(size_t)(t0+l)*CONV_DIM + hp];
        g_y[(size_t)(t0+l)*D_INNER + hp] += e*acc + xh*Dvec[h];
    }
#endif
}

// ---------------- transpose x,B channels ----------------
__global__ void k_transpose(){
    __shared__ float t[32][33];
    int ch0 = blockIdx.x*32, l0 = blockIdx.y*32, b = blockIdx.z;
    int tx = threadIdx.x, ty = threadIdx.y;
    #pragma unroll
    for (int r = ty; r < 32; r += 8)
        t[r][tx] = g_xbc[(size_t)(b*L_ + l0 + r)*CONV_DIM + ch0 + tx];
    __syncthreads();
    #pragma unroll
    for (int r = ty; r < 32; r += 8)
        g_xbt[((size_t)b*768 + ch0 + r)*L_ + l0 + tx] = t[tx][r];
}

// ---------------- W split + transpose ----------------
__global__ void k_wsplit_t(const float* __restrict__ W,
                           __nv_bfloat16* __restrict__ Wh, __nv_bfloat16* __restrict__ Wl,
                           int K, int N){
    __shared__ float tile[32][33];
    int n0 = blockIdx.x*32, k0 = blockIdx.y*32;
    int tx = threadIdx.x, ty = threadIdx.y;
    #pragma unroll
    for (int r = ty; r < 32; r += 8){
        int k = k0 + r, n = n0 + tx;
        tile[r][tx] = (k < K && n < N) ? W[(size_t)k*N + n] : 0.f;
    }
    __syncthreads();
    #pragma unroll
    for (int r = ty; r < 32; r += 8){
        int n = n0 + r, k = k0 + tx;
        if (n < N && k < K){
            __nv_bfloat16 hi, lo;
            bf16_split(tile[tx][r], hi, lo);
            Wh[(size_t)n*K + k] = hi;
            Wl[(size_t)n*K + k] = lo;
        }
    }
}

// ---------------- fused embed + rmsnorm + bf16 split (layer 0) ----------------
__global__ void k_embed_norm(const float* __restrict__ x, const float* __restrict__ emb,
                             const float* __restrict__ w,
                             __nv_bfloat16* __restrict__ oh, __nv_bfloat16* __restrict__ ol){
    int t = blockIdx.x;
    int e = threadIdx.x;
    int vv = (int)(255.0f * x[t]);
    vv = min(max(vv, 0), 255);
    float val0 = emb[(size_t)vv*EMB + e];
    g_h[(size_t)t*EMB + e] = val0;
    __shared__ float red[8];
    float ss = val0*val0;
    #pragma unroll
    for (int o = 16; o; o >>= 1) ss += __shfl_xor_sync(0xffffffffu, ss, o);
    if ((threadIdx.x & 31) == 0) red[threadIdx.x >> 5] = ss;
    __syncthreads();
    if (threadIdx.x < 32){
        float s2 = (threadIdx.x < 8) ? red[threadIdx.x] : 0.f;
        #pragma unroll
        for (int o = 4; o; o >>= 1) s2 += __shfl_xor_sync(0xffffffffu, s2, o);
        if (threadIdx.x == 0) red[0] = s2;
    }
    __syncthreads();
    float scale = rsqrtf(red[0]/(float)EMB + 1e-5f);
    float val = val0*scale*w[e];
    __nv_bfloat16 hi, lo;
    bf16_split(val, hi, lo);
    oh[(size_t)t*EMB + e] = hi;
    ol[(size_t)t*EMB + e] = lo;
}

// ---------------- rmsnorm + bf16 split ----------------
template<int DIM>
__global__ void k_rmsnorm_split(const float* __restrict__ in, const float* __restrict__ w,
                                __nv_bfloat16* __restrict__ oh, __nv_bfloat16* __restrict__ ol){
    int t = blockIdx.x;
    const float* row = in + (size_t)t*DIM;
    __shared__ float red[8];
    float v[DIM/256];
    float ss = 0.f;
    #pragma unroll
    for (int i = 0; i < DIM/256; i++){
        v[i] = row[threadIdx.x + i*256];
        ss += v[i]*v[i];
    }
    #pragma unroll
    for (int o = 16; o; o >>= 1) ss += __shfl_xor_sync(0xffffffffu, ss, o);
    if ((threadIdx.x & 31) == 0) red[threadIdx.x >> 5] = ss;
    __syncthreads();
    if (threadIdx.x < 32){
        float s2 = (threadIdx.x < 8) ? red[threadIdx.x] : 0.f;
        #pragma unroll
        for (int o = 4; o; o >>= 1) s2 += __shfl_xor_sync(0xffffffffu, s2, o);
        if (threadIdx.x == 0) red[0] = s2;
    }
    __syncthreads();
    float scale = rsqrtf(red[0]/(float)DIM + 1e-5f);
    #pragma unroll
    for (int i = 0; i < DIM/256; i++){
        int d = threadIdx.x + i*256;
        float val = v[i]*scale*w[d];
        __nv_bfloat16 hi, lo;
        bf16_split(val, hi, lo);
        oh[(size_t)t*DIM + d] = hi;
        ol[(size_t)t*DIM + d] = lo;
    }
}

// ---------------- smem-tiled causal depthwise conv (k=4) + bias + silu ----------------
// tile: 32 tokens x 256 channels (35.8KB smem -> ~6 CTAs/SM)
__global__ void __launch_bounds__(256)
k_conv2(const float* __restrict__ cw, const float* __restrict__ cb){
    extern __shared__ float s[];                 // [35][256]
    int t0  = blockIdx.x * 32;
    int ch0 = blockIdx.y * 256;
    int tid = threadIdx.x;
    int l0  = t0 & (L_-1);
    #pragma unroll
    for (int r = 0; r < 35; r++){
        float val = 0.f;
        if (l0 - 3 + r >= 0)
            val = g_zx[(size_t)(t0 - 3 + r)*D_PROJ + 512 + ch0 + tid];
        s[r*256 + tid] = val;
    }
    __syncthreads();
    int ch = ch0 + tid;
    float w0 = cw[ch*4+0], w1 = cw[ch*4+1], w2 = cw[ch*4+2], w3 = cw[ch*4+3];
    float bias = cb[ch];
    #pragma unroll 4
    for (int r = 0; r < 32; r++){
        float acc = bias;
        acc = fmaf(w0, s[(r+0)*256 + tid], acc);
        acc = fmaf(w1, s[(r+1)*256 + tid], acc);
        acc = fmaf(w2, s[(r+2)*256 + tid], acc);
        acc = fmaf(w3, s[(r+3)*256 + tid], acc);
        acc = acc / (1.f + __expf(-acc));
        g_xbc[(size_t)(t0+r)*CONV_DIM + ch] = acc;
    }
}

// ---------------- fused dt(softplus) + per-chunk cumsum ----------------
__global__ void k_cumsum(const float* __restrict__ A_log, const float* __restrict__ dt_bias){
    int bhc = blockIdx.x;
    int c = bhc & 31;
    int h = (bhc >> 5) & 7;
    int b = bhc >> 8;
    int l = threadIdx.x;
    int t = b*L_ + c*64 + l;
    float v = g_zx[(size_t)t*D_PROJ + 1536 + h] + dt_bias[h];
    float dt = (v > 20.f) ? v : log1pf(__expf(v));
    g_dt[t*NHD + h] = dt;
    float a = -__expf(A_log[h]) * dt;
    __shared__ float s[64];
    s[l] = a; __syncthreads();
    #pragma unroll
    for (int off = 1; off < 64; off <<= 1){
        float vv = s[l] + ((l >= off) ? s[l-off] : 0.f);
        __syncthreads();
        s[l] = vv;
        __syncthreads();
    }
    g_acs[bhc*64 + l] = s[l];
}

// ---------------- Y_diag per (b,c) (fp32 FMA) ----------------
__global__ void k_ydiag(){
    __shared__ float bufA[64][65];
    __shared__ float bufB[64][65];
    __shared__ float acsS[64];
    int bc = blockIdx.x;
    int c = bc & 31, b = bc >> 5;
    int t0 = b*L_ + c*64;
    int tid = threadIdx.x, tx = tid & 15, ty = tid >> 4;
    float G[4][4] = {};
    for (int nt = 0; nt < 4; nt++){
        for (int i = tid; i < 4096; i += 256){
            int r = i >> 6, nn = i & 63;
            bufA[r][nn] = g_xbc[(size_t)(t0+r)*CONV_DIM + 768 + nt*64 + nn];
            bufB[r][nn] = g_xbc[(size_t)(t0+r)*CONV_DIM + 512 + nt*64 + nn];
        }
        __syncthreads();
        #pragma unroll 8
        for (int nn = 0; nn < 64; nn++){
            float cv[4], bv[4];
            #pragma unroll
            for (int i = 0; i < 4; i++) cv[i] = bufA[ty*4+i][nn];
            #pragma unroll
            for (int j = 0; j < 4; j++) bv[j] = bufB[tx*4+j][nn];
            #pragma unroll
            for (int i = 0; i < 4; i++)
                #pragma unroll
                for (int j = 0; j < 4; j++)
                    G[i][j] = fmaf(cv[i], bv[j], G[i][j]);
        }
        __syncthreads();
    }

    for (int hh = 0; hh < NHD; hh++){
        __syncthreads();
        if (tid < 64) acsS[tid] = g_acs[((b*8+hh)*32 + c)*64 + tid];
        for (int i = tid; i < 4096; i += 256){
            int s = i >> 6, p = i & 63;
            int t = t0 + s;
            bufB[s][p] = g_xbc[(size_t)t*CONV_DIM + hh*64 + p] * g_dt[t*NHD + hh];
        }
        __syncthreads();
        #pragma unroll
        for (int i = 0; i < 4; i++){
            int l = ty*4 + i;
            #pragma unroll
            for (int j = 0; j < 4; j++){
                int s = tx*4 + j;
                bufA[l][s] = (s <= l) ? G[i][j]*__expf(acsS[l]-acsS[s]) : 0.f;
            }
        }
        __syncthreads();
        float y[4][4] = {};
        #pragma unroll 4
        for (int s = 0; s < 64; s++){
            float xv[4], wv[4];
            #pragma unroll
            for (int j = 0; j < 4; j++) xv[j] = bufB[s][tx*4+j];
            #pragma unroll
            for (int i = 0; i < 4; i++) wv[i] = bufA[ty*4+i][s];
            #pragma unroll
            for (int i = 0; i < 4; i++)
                #pragma unroll
                for (int j = 0; j < 4; j++)
                    y[i][j] = fmaf(wv[i], xv[j], y[i][j]);
        }
        #pragma unroll
        for (int i = 0; i < 4; i++)
            #pragma unroll
            for (int j = 0; j < 4; j++)
                g_y[(size_t)(t0 + ty*4 + i)*D_INNER + hh*64 + tx*4 + j] = y[i][j];
    }
}

// ---------------- inter-chunk scan: fp32 states -> bf16 hi/lo prev-states ----------------
// finer split: grid (B_*NHD, 32), 2 carried elements/thread
__global__ void k_scan(){
    int bh = blockIdx.x;
    int h = bh & 7, b = bh >> 3;
    int base = blockIdx.y*512 + threadIdx.x;
    float S[2] = {};
    for (int c = 0; c < 32; c++){
        float dec = __expf(g_acs[((b*8+h)*32 + c)*64 + 63]);
        size_t off = ((size_t)(b*32 + c)*8 + h)*16384 + base;
        const float* ptr = g_states + off;
        __nv_bfloat16* ph = g_sph + off;
        __nv_bfloat16* pl = g_spl + off;
        #pragma unroll
        for (int e = 0; e < 2; e++){
            float tmp = ptr[e*256];
            __nv_bfloat16 hi, lo;
            bf16_split(S[e], hi, lo);
            ph[e*256] = hi;
            pl[e*256] = lo;
            S[e] = fmaf(S[e], dec, tmp);
        }
    }
}

// ---------------- gated rmsnorm + bf16 split ----------------
__global__ void k_gatenorm_split(const float* __restrict__ gw,
                                 __nv_bfloat16* __restrict__ oh, __nv_bfloat16* __restrict__ ol){
    int t = blockIdx.x;
    __shared__ float red[8];
    float v[2];
    float ss = 0.f;
    #pragma unroll
    for (int i = 0; i < 2; i++){
        int d = threadIdx.x + i*256;
        float z = g_zx[(size_t)t*D_PROJ + d];
        float val = g_y[(size_t)t*D_INNER + d] * (z / (1.f + __expf(-z)));
        v[i] = val;
        ss += val*val;
    }
    #pragma unroll
    for (int o = 16; o; o >>= 1) ss += __shfl_xor_sync(0xffffffffu, ss, o);
    if ((threadIdx.x & 31) == 0) red[threadIdx.x >> 5] = ss;
    __syncthreads();
    if (threadIdx.x < 32){
        float s2 = (threadIdx.x < 8) ? red[threadIdx.x] : 0.f;
        #pragma unroll
        for (int o = 4; o; o >>= 1) s2 += __shfl_xor_sync(0xffffffffu, s2, o);
        if (threadIdx.x == 0) red[0] = s2;
    }
    __syncthreads();
    float scale = rsqrtf(red[0]/512.f + 1e-5f);
    #pragma unroll
    for (int i = 0; i < 2; i++){
        int d = threadIdx.x + i*256;
        float val = v[i]*scale*gw[d];
        __nv_bfloat16 hi, lo;
        bf16_split(val, hi, lo);
        oh[(size_t)t*D_INNER + d] = hi;
        ol[(size_t)t*D_INNER + d] = lo;
    }
}

// ---------------- launch ----------------
extern "C" void kernel_launch(void* const* d_in, const int* in_sizes, int n_in,
                              void* d_out, int out_size){
    const float* x       = (const float*)d_in[0];
    const float* emb     = (const float*)d_in[1];
    const float* in_proj = (const float*)d_in[2];
    const float* conv_w  = (const float*)d_in[3];
    const float* conv_b  = (const float*)d_in[4];
    const float* dt_bias = (const float*)d_in[5];
    const float* A_log   = (const float*)d_in[6];
    const float* Dv      = (const float*)d_in[7];
    const float* gnorm   = (const float*)d_in[8];
    const float* outp_w  = (const float*)d_in[9];
    const float* norm_w  = (const float*)d_in[10];
    const float* normf   = (const float*)d_in[11];
    const float* head_w  = (const float*)d_in[12];

    void *p_h, *p_ah, *p_al, *p_wh, *p_wl, *p_zx;
    cudaGetSymbolAddress(&p_h,  g_h);
    cudaGetSymbolAddress(&p_ah, g_ah);
    cudaGetSymbolAddress(&p_al, g_al);
    cudaGetSymbolAddress(&p_wh, g_wth);
    cudaGetSymbolAddress(&p_wl, g_wtl);
    cudaGetSymbolAddress(&p_zx, g_zx);
    float* gh  = (float*)p_h;
    float* gzx = (float*)p_zx;
    __nv_bfloat16* ah = (__nv_bfloat16*)p_ah;
    __nv_bfloat16* al = (__nv_bfloat16*)p_al;
    __nv_bfloat16* wh = (__nv_bfloat16*)p_wh;
    __nv_bfloat16* wl = (__nv_bfloat16*)p_wl;

    cudaFuncSetAttribute(k_mma_gemm2,  cudaFuncAttributeMaxDynamicSharedMemorySize, SM2_BYTES);
    cudaFuncSetAttribute(k_mma_gemm,   cudaFuncAttributeMaxDynamicSharedMemorySize, SM1_BYTES);
    cudaFuncSetAttribute(k_states_mma, cudaFuncAttributeMaxDynamicSharedMemorySize, ST_BYTES);
    cudaFuncSetAttribute(k_yoff_mma,   cudaFuncAttributeMaxDynamicSharedMemorySize, YO_BYTES);
    cudaFuncSetAttribute(k_conv2,      cudaFuncAttributeMaxDynamicSharedMemorySize, CV_BYTES);

    for (int i = 0; i < 2; i++){
        if (i == 0)
            k_embed_norm<<<NTOK, 256>>>(x, emb, norm_w, ah, al);
        else
            k_rmsnorm_split<256><<<NTOK, 256>>>(gh, norm_w + i*EMB, ah, al);
        k_wsplit_t<<<dim3((D_PROJ+31)/32, EMB/32), dim3(32,8)>>>(
            in_proj + (size_t)i*EMB*D_PROJ, wh, wl, EMB, D_PROJ);
        k_mma_gemm2<<<dim3((D_PROJ+255)/256, NTOK/128), 256, SM2_BYTES>>>(
            ah, al, wh, wl, gzx, NTOK, D_PROJ, EMB, nullptr);
        k_conv2<<<dim3(NTOK/32, CONV_DIM/256), 256, CV_BYTES>>>(
            conv_w + i*CONV_DIM*4, conv_b + i*CONV_DIM);
        k_cumsum<<<B_*NHD*NCHUNK, 64>>>(A_log + i*NHD, dt_bias + i*NHD);
        k_transpose<<<dim3(24, 64, 4), dim3(32,8)>>>();
        k_ydiag<<<B_*NCHUNK, 256>>>();
        k_states_mma<<<B_*NCHUNK, 256, ST_BYTES>>>();
        k_scan<<<dim3(B_*NHD, 32), 256>>>();
        k_yoff_mma<<<B_*NCHUNK, 256, YO_BYTES>>>(Dv + i*NHD);
        k_gatenorm_split<<<NTOK, 256>>>(gnorm + i*D_INNER, ah, al);
        k_wsplit_t<<<dim3(EMB/32, D_INNER/32), dim3(32,8)>>>(
            outp_w + (size_t)i*D_INNER*EMB, wh, wl, D_INNER, EMB);
        k_mma_gemm<<<dim3(EMB/128, NTOK/128), 256, SM1_BYTES>>>(
            ah, al, wh, wl, gh, NTOK, EMB, D_INNER, gh);
    }

    k_rmsnorm_split<256><<<NTOK, 256>>>(gh, normf, ah, al);
    k_wsplit_t<<<dim3(EMB/32, EMB/32), dim3(32,8)>>>(head_w, wh, wl, EMB, EMB);
    k_mma_gemm<<<dim3(EMB/128, NTOK/128), 256, SM1_BYTES>>>(
        ah, al, wh, wl, (float*)d_out, NTOK, EMB, EMB, nullptr);
}